// round 6
// baseline (speedup 1.0000x reference)
#include <cuda_runtime.h>
#include <math.h>
#include <stdint.h>
#include <stddef.h>

// fixed problem shapes
#define BDIM 8
#define HDIM 8
#define DM 512
#define DA 256
#define DP 128
#define MDIM 32
#define DK 64
#define DAH 32
#define DPH 16
#define SDIM 6144

// ---------------- device scratch ----------------
__device__ float d_WqM[HDIM*DK*DM];
__device__ float d_WkM[HDIM*DK*DM];
__device__ float d_WvM[HDIM*DK*DM];
__device__ float d_WOM[DM*DM];
__device__ float d_Kn[(size_t)BDIM*HDIM*SDIM*DK];   // ~100 MB
__device__ float d_Qv[BDIM*HDIM*MDIM*DK];
__device__ float d_QA[BDIM*HDIM*DAH];
__device__ float d_QP[BDIM*HDIM*DPH];
__device__ float d_tn[BDIM*HDIM*SDIM];
__device__ float d_dot2[BDIM*HDIM*SDIM];
__device__ float d_dot3[BDIM*HDIM*SDIM];
__device__ float d_attn[BDIM*HDIM*SDIM];
__device__ float d_alast[BDIM*HDIM];
__device__ float d_xbar[BDIM*HDIM*DM];
__device__ float d_gi[BDIM*31*192];
__device__ float d_res[BDIM*DK];
__device__ float d_deta[BDIM*DM];

__device__ __forceinline__ void mma_tf32(float* c, const uint32_t* a, uint32_t b0, uint32_t b1) {
    asm volatile("mma.sync.aligned.m16n8k8.row.col.f32.tf32.tf32.f32 "
        "{%0,%1,%2,%3}, {%4,%5,%6,%7}, {%8,%9}, {%0,%1,%2,%3};\n"
        : "+f"(c[0]), "+f"(c[1]), "+f"(c[2]), "+f"(c[3])
        : "r"(a[0]), "r"(a[1]), "r"(a[2]), "r"(a[3]), "r"(b0), "r"(b1));
}

__device__ __forceinline__ void cpa16(uint32_t saddr, const void* g) {
    asm volatile("cp.async.cg.shared.global [%0], [%1], 16;" :: "r"(saddr), "l"(g));
}
__device__ __forceinline__ void cpa_commit() { asm volatile("cp.async.commit_group;"); }
__device__ __forceinline__ void cpa_wait0() { asm volatile("cp.async.wait_group 0;" ::: "memory"); }
__device__ __forceinline__ void cpa_wait1() { asm volatile("cp.async.wait_group 1;" ::: "memory"); }

// ---------------- masked weights + zero xbar ----------------
__global__ void mask_kernel(const float* __restrict__ Wq, const float* __restrict__ Wk,
                            const float* __restrict__ Wv, const float* __restrict__ WO,
                            const int* __restrict__ G) {
    int i = blockIdx.x*256 + threadIdx.x;
    const int NW = HDIM*DK*DM;
    if (i < NW) {
        int d = i & 511;
        int c = (i >> 9) & 63;
        float g = (float)G[c*64 + (d & 63)];
        d_WqM[i] = Wq[i]*g;
        d_WkM[i] = Wk[i]*g;
        d_WvM[i] = Wv[i]*g;
    }
    if (i < DM*DM) {
        int j = i & 511, r = i >> 9;
        d_WOM[i] = WO[i]*(float)G[(r & 63)*64 + (j & 63)];
    }
    if (i < BDIM*HDIM*DM) d_xbar[i] = 0.f;
}

// ---------------- Qv: last M rows, masked proj + l2norm (fp32, tiny) ----------------
__global__ void qv_kernel(const float* __restrict__ memory, const float* __restrict__ x_pre,
                          const float* __restrict__ bq, int S) {
    int m = blockIdx.x & 31, h = (blockIdx.x >> 5) & 7, b = blockIdx.x >> 8;
    __shared__ float xs[DM];
    __shared__ float wp[2];
    int s = S - MDIM + m;
    const float* row = (s < S-1) ? memory + ((size_t)b*(S-1) + s)*DM : x_pre + (size_t)b*DM;
    for (int i = threadIdx.x; i < DM; i += 64) xs[i] = row[i];
    __syncthreads();
    int c = threadIdx.x;
    const float* wr = d_WqM + ((size_t)h*DK + c)*DM;
    float acc = bq[h*DK + c];
    #pragma unroll 8
    for (int d = 0; d < DM; d++) acc += xs[d]*wr[d];
    float v = acc*acc;
    for (int o = 16; o; o >>= 1) v += __shfl_xor_sync(0xffffffffu, v, o);
    if ((c & 31) == 0) wp[c >> 5] = v;
    __syncthreads();
    float inv = 1.f / fmaxf(sqrtf(wp[0] + wp[1]), 1e-12f);
    d_Qv[(((size_t)b*HDIM + h)*MDIM + m)*DK + c] = acc*inv;
}

// ---------------- tensor-core projection (tf32 mma, cp.async DOUBLE-buffered) ----------------
// MODE 0: kproj (x = [memory; x_pre]; W = d_WkM; normalized rows -> d_Kn)
// MODE 1: aux   (epilogue: dot with d_QA -> d_dot2)
// MODE 2: pos   (epilogue: dot with d_QP -> d_dot3)
template<int DIN, int DOUT, int MODE, int NW_N>
__global__ void __launch_bounds__(256)
proj_mma_kernel(const float* __restrict__ src0, const float* __restrict__ x_pre,
                const float* __restrict__ W, const float* __restrict__ bias,
                int S, int Wn) {
    constexpr int NW_M = 8/NW_N;
    constexpr int TM   = NW_M*32;
    constexpr int WT_N = DOUT/NW_N;
    constexpr int NFN  = WT_N/8;
    constexpr int NCH  = DIN/32;

    extern __shared__ uint32_t dynsm[];
    uint32_t* Xs  = dynsm;               // 2 * TM * 36
    uint32_t* Wss = dynsm + 2*TM*36;     // 2 * DOUT * 36
    __shared__ float bs_s[DOUT];
    __shared__ float qs_s[DOUT];
    __shared__ float red_s[TM*2];

    int tid = threadIdx.x;
    int lane = tid & 31, wid = tid >> 5;
    int g = lane >> 2, tig = lane & 3;
    int warp_n = wid % NW_N, warp_m = wid / NW_N;
    int rb = warp_m*32, cb = warp_n*WT_N;
    int s0 = blockIdx.x*TM, h = blockIdx.y, b = blockIdx.z;
    int bh = b*HDIM + h;

    uint32_t xB = (uint32_t)__cvta_generic_to_shared(Xs);
    uint32_t wB = (uint32_t)__cvta_generic_to_shared(Wss);

    for (int i = tid; i < DOUT; i += 256) {
        bs_s[i] = bias[h*DOUT + i];
        if (MODE == 1) qs_s[i] = d_QA[(size_t)bh*DAH + i];
        if (MODE == 2) qs_s[i] = d_QP[(size_t)bh*DPH + i];
    }

    auto load_chunk = [&](int ch, int buf) {
        int d0 = ch*32;
        #pragma unroll
        for (int it = 0; it < TM*8/256; it++) {
            int e = it*256 + tid;
            int row = e >> 3, c4 = (e & 7)*4;
            int s = s0 + row;
            const float* rp;
            if (MODE == 0)
                rp = (s < S-1) ? src0 + ((size_t)b*(S-1) + s)*DIN : x_pre + (size_t)b*DIN;
            else
                rp = src0 + ((size_t)b*S + s)*DIN;
            cpa16(xB + (buf*TM*36 + row*36 + c4)*4, rp + d0 + c4);
        }
        for (int e = tid; e < DOUT*8; e += 256) {
            int rr = e >> 3, c4 = (e & 7)*4;
            const float* wp;
            if (MODE == 0) wp = d_WkM + ((size_t)(h*DOUT + rr))*DIN + d0 + c4;
            else           wp = W + ((size_t)(h*DOUT + rr))*DIN + d0 + c4;
            cpa16(wB + (buf*DOUT*36 + rr*36 + c4)*4, wp);
        }
    };

    float acc[2][NFN][4];
    #pragma unroll
    for (int mi = 0; mi < 2; mi++)
        #pragma unroll
        for (int ni = 0; ni < NFN; ni++)
            #pragma unroll
            for (int q = 0; q < 4; q++) acc[mi][ni][q] = 0.f;

    load_chunk(0, 0);
    cpa_commit();

    for (int ch = 0; ch < NCH; ch++) {
        if (ch + 1 < NCH) {
            load_chunk(ch + 1, (ch + 1) & 1);
            cpa_commit();
            cpa_wait1();
        } else {
            cpa_wait0();
        }
        __syncthreads();
        const uint32_t* Xb = Xs + (ch & 1)*TM*36;
        const uint32_t* Wb = Wss + (ch & 1)*DOUT*36;
        #pragma unroll
        for (int ks = 0; ks < 4; ks++) {
            int k0 = ks*8;
            uint32_t a[2][4];
            #pragma unroll
            for (int mi = 0; mi < 2; mi++) {
                int r = rb + mi*16 + g;
                a[mi][0] = Xb[r*36 + k0 + tig];
                a[mi][1] = Xb[(r+8)*36 + k0 + tig];
                a[mi][2] = Xb[r*36 + k0 + tig + 4];
                a[mi][3] = Xb[(r+8)*36 + k0 + tig + 4];
            }
            #pragma unroll
            for (int ni = 0; ni < NFN; ni++) {
                int cn = cb + ni*8 + g;
                uint32_t b0 = Wb[cn*36 + k0 + tig];
                uint32_t b1 = Wb[cn*36 + k0 + tig + 4];
                #pragma unroll
                for (int mi = 0; mi < 2; mi++) mma_tf32(acc[mi][ni], a[mi], b0, b1);
            }
        }
        __syncthreads();   // protect buffer (ch&1) before it is re-filled at ch+2
    }

    // ---- epilogue: bias + per-row l2 norm ----
    float sl[2] = {0.f, 0.f}, sh[2] = {0.f, 0.f};
    #pragma unroll
    for (int mi = 0; mi < 2; mi++)
        #pragma unroll
        for (int ni = 0; ni < NFN; ni++) {
            int c0 = cb + ni*8 + 2*tig, c1 = c0 + 1;
            acc[mi][ni][0] += bs_s[c0];
            acc[mi][ni][1] += bs_s[c1];
            acc[mi][ni][2] += bs_s[c0];
            acc[mi][ni][3] += bs_s[c1];
            sl[mi] += acc[mi][ni][0]*acc[mi][ni][0] + acc[mi][ni][1]*acc[mi][ni][1];
            sh[mi] += acc[mi][ni][2]*acc[mi][ni][2] + acc[mi][ni][3]*acc[mi][ni][3];
        }
    #pragma unroll
    for (int mi = 0; mi < 2; mi++) {
        sl[mi] += __shfl_xor_sync(0xffffffffu, sl[mi], 1);
        sl[mi] += __shfl_xor_sync(0xffffffffu, sl[mi], 2);
        sh[mi] += __shfl_xor_sync(0xffffffffu, sh[mi], 1);
        sh[mi] += __shfl_xor_sync(0xffffffffu, sh[mi], 2);
    }
    if (NW_N == 2) {
        if (tig == 0) {
            #pragma unroll
            for (int mi = 0; mi < 2; mi++) {
                int rl = rb + mi*16 + g;
                red_s[rl*2 + warp_n] = sl[mi];
                red_s[(rl+8)*2 + warp_n] = sh[mi];
            }
        }
        __syncthreads();
        #pragma unroll
        for (int mi = 0; mi < 2; mi++) {
            int rl = rb + mi*16 + g;
            sl[mi] = red_s[rl*2] + red_s[rl*2+1];
            sh[mi] = red_s[(rl+8)*2] + red_s[(rl+8)*2+1];
        }
    }
    float il[2], ih[2];
    #pragma unroll
    for (int mi = 0; mi < 2; mi++) {
        il[mi] = 1.f / fmaxf(sqrtf(sl[mi]), 1e-12f);
        ih[mi] = 1.f / fmaxf(sqrtf(sh[mi]), 1e-12f);
    }

    if (MODE == 0) {
        #pragma unroll
        for (int mi = 0; mi < 2; mi++) {
            int rl = rb + mi*16 + g;
            size_t base_l = ((size_t)bh*S + s0 + rl)*DK;
            size_t base_h = ((size_t)bh*S + s0 + rl + 8)*DK;
            #pragma unroll
            for (int ni = 0; ni < NFN; ni++) {
                int c0 = cb + ni*8 + 2*tig;
                float2 v0 = make_float2(acc[mi][ni][0]*il[mi], acc[mi][ni][1]*il[mi]);
                float2 v1 = make_float2(acc[mi][ni][2]*ih[mi], acc[mi][ni][3]*ih[mi]);
                *(float2*)&d_Kn[base_l + c0] = v0;
                *(float2*)&d_Kn[base_h + c0] = v1;
            }
        }
    } else {
        float* dst = (MODE == 1) ? d_dot2 : d_dot3;
        float dl[2], dh[2];
        #pragma unroll
        for (int mi = 0; mi < 2; mi++) {
            dl[mi] = 0.f; dh[mi] = 0.f;
            #pragma unroll
            for (int ni = 0; ni < NFN; ni++) {
                int c0 = cb + ni*8 + 2*tig, c1 = c0 + 1;
                dl[mi] += acc[mi][ni][0]*qs_s[c0] + acc[mi][ni][1]*qs_s[c1];
                dh[mi] += acc[mi][ni][2]*qs_s[c0] + acc[mi][ni][3]*qs_s[c1];
            }
            dl[mi] += __shfl_xor_sync(0xffffffffu, dl[mi], 1);
            dl[mi] += __shfl_xor_sync(0xffffffffu, dl[mi], 2);
            dh[mi] += __shfl_xor_sync(0xffffffffu, dh[mi], 1);
            dh[mi] += __shfl_xor_sync(0xffffffffu, dh[mi], 2);
        }
        if (NW_N == 2) {
            __syncthreads();
            if (tig == 0) {
                #pragma unroll
                for (int mi = 0; mi < 2; mi++) {
                    int rl = rb + mi*16 + g;
                    red_s[rl*2 + warp_n] = dl[mi];
                    red_s[(rl+8)*2 + warp_n] = dh[mi];
                }
            }
            __syncthreads();
            if (warp_n == 0 && tig == 0) {
                #pragma unroll
                for (int mi = 0; mi < 2; mi++) {
                    int rl = rb + mi*16 + g;
                    float DL = red_s[rl*2] + red_s[rl*2+1];
                    float DH = red_s[(rl+8)*2] + red_s[(rl+8)*2+1];
                    int wl = s0 + rl - 31, wh = wl + 8;
                    if (wl >= 0 && wl < Wn) dst[(size_t)bh*S + wl] = DL*il[mi];
                    if (wh >= 0 && wh < Wn) dst[(size_t)bh*S + wh] = DH*ih[mi];
                }
            }
        } else {
            if (tig == 0) {
                #pragma unroll
                for (int mi = 0; mi < 2; mi++) {
                    int rl = rb + mi*16 + g;
                    int wl = s0 + rl - 31, wh = wl + 8;
                    if (wl >= 0 && wl < Wn) dst[(size_t)bh*S + wl] = dl[mi]*il[mi];
                    if (wh >= 0 && wh < Wn) dst[(size_t)bh*S + wh] = dh[mi]*ih[mi];
                }
            }
        }
    }
}

// ---------------- banded Qv . Kn -> tn  (tf32 mma version) ----------------
__global__ void __launch_bounds__(128) band_mma_kernel(int S, int Wn) {
    __shared__ uint32_t Qs[32*68];
    __shared__ uint32_t Ks[96*68];
    __shared__ float Ps[32*100];
    int tid = threadIdx.x;
    int lane = tid & 31, wid = tid >> 5;
    int g = lane >> 2, tig = lane & 3;
    int w0 = blockIdx.x*64, h = blockIdx.y, b = blockIdx.z;
    int bh = b*HDIM + h;

    uint32_t qB = (uint32_t)__cvta_generic_to_shared(Qs);
    uint32_t kB = (uint32_t)__cvta_generic_to_shared(Ks);

    for (int e = tid; e < 96*16; e += 128) {
        int r = e >> 4, c4 = (e & 15)*4;
        int s = w0 + r;
        uint32_t sa = kB + (r*68 + c4)*4;
        if (s < S) cpa16(sa, d_Kn + ((size_t)bh*S + s)*DK + c4);
        else {
            *(float4*)((char*)Ks + (size_t)(r*68 + c4)*4) = make_float4(0.f,0.f,0.f,0.f);
        }
    }
    for (int e = tid; e < 32*16; e += 128) {
        int r = e >> 4, c4 = (e & 15)*4;
        cpa16(qB + (r*68 + c4)*4, d_Qv + ((size_t)bh*MDIM + r)*DK + c4);
    }
    cpa_commit();
    cpa_wait0();
    __syncthreads();

    float acc[2][3][4];
    #pragma unroll
    for (int mi = 0; mi < 2; mi++)
        #pragma unroll
        for (int ni = 0; ni < 3; ni++)
            #pragma unroll
            for (int q = 0; q < 4; q++) acc[mi][ni][q] = 0.f;
    int nb = wid*24;
    #pragma unroll
    for (int ks = 0; ks < 8; ks++) {
        int k0 = ks*8;
        uint32_t a[2][4];
        #pragma unroll
        for (int mi = 0; mi < 2; mi++) {
            int r = mi*16 + g;
            a[mi][0] = Qs[r*68 + k0 + tig];
            a[mi][1] = Qs[(r+8)*68 + k0 + tig];
            a[mi][2] = Qs[r*68 + k0 + tig + 4];
            a[mi][3] = Qs[(r+8)*68 + k0 + tig + 4];
        }
        #pragma unroll
        for (int ni = 0; ni < 3; ni++) {
            int cn = nb + ni*8 + g;
            uint32_t b0 = Ks[cn*68 + k0 + tig];
            uint32_t b1 = Ks[cn*68 + k0 + tig + 4];
            #pragma unroll
            for (int mi = 0; mi < 2; mi++) mma_tf32(acc[mi][ni], a[mi], b0, b1);
        }
    }
    #pragma unroll
    for (int mi = 0; mi < 2; mi++)
        #pragma unroll
        for (int ni = 0; ni < 3; ni++) {
            int c0 = nb + ni*8 + 2*tig;
            int r = mi*16 + g;
            Ps[r*100 + c0]     = acc[mi][ni][0];
            Ps[r*100 + c0 + 1] = acc[mi][ni][1];
            Ps[(r+8)*100 + c0]     = acc[mi][ni][2];
            Ps[(r+8)*100 + c0 + 1] = acc[mi][ni][3];
        }
    __syncthreads();
    if (tid < 64) {
        int w = w0 + tid;
        if (w < Wn) {
            float s = 0.f;
            #pragma unroll
            for (int m = 0; m < 32; m++) s += Ps[m*100 + tid + m];
            d_tn[(size_t)bh*S + w] = s*(1.f/32.f);
        }
    }
}

// ---------------- QA / QP (last-row queries, fp32) ----------------
__global__ void qa_kernel(const float* __restrict__ aux, const float* __restrict__ Wqa,
                          const float* __restrict__ bqa, int S) {
    int h = blockIdx.x & 7, b = blockIdx.x >> 3;
    int c = threadIdx.x;  // 32
    const float* ar = aux + ((size_t)b*S + (S-1))*DA;
    const float* wr = Wqa + ((size_t)h*DAH + c)*DA;
    float acc = bqa[h*DAH + c];
    #pragma unroll 4
    for (int d = 0; d < DA; d++) acc += ar[d]*wr[d];
    float v = acc*acc;
    for (int o = 16; o; o >>= 1) v += __shfl_xor_sync(0xffffffffu, v, o);
    float inv = 1.f / fmaxf(sqrtf(v), 1e-12f);
    d_QA[((size_t)b*HDIM + h)*DAH + c] = acc*inv;
}

__global__ void qp_kernel(const float* __restrict__ pos, const float* __restrict__ Wqp,
                          const float* __restrict__ bqp, int S) {
    int h = blockIdx.x & 7, b = blockIdx.x >> 3;
    int lane = threadIdx.x;   // 32
    int c = lane & 15;
    const float* pr = pos + ((size_t)b*S + (S-1))*DP;
    const float* wr = Wqp + ((size_t)h*DPH + c)*DP;
    float acc = bqp[h*DPH + c];
    #pragma unroll 4
    for (int d = 0; d < DP; d++) acc += pr[d]*wr[d];
    float v = acc*acc;
    for (int o = 8; o; o >>= 1) v += __shfl_xor_sync(0xffffffffu, v, o);
    float inv = 1.f / fmaxf(sqrtf(v), 1e-12f);
    if (lane < 16) d_QP[((size_t)b*HDIM + h)*DPH + c] = acc*inv;
}

// ---------------- softmax over Wn ----------------
__global__ void softmax_kernel(const float* __restrict__ w1, const float* __restrict__ w2,
                               const float* __restrict__ w3, int S, int Wn) {
    int bh = blockIdx.x, t = threadIdx.x;   // 256
    __shared__ float red[8];
    __shared__ float sval;
    float c1 = w1[0], c2 = w2[0], c3 = w3[0];
    size_t base = (size_t)bh*S;
    float mx = -1e30f;
    for (int i = t; i < Wn; i += 256) {
        float l = c1*d_tn[base+i] + c2*d_dot2[base+i] + c3*d_dot3[base+i];
        d_attn[base+i] = l;
        mx = fmaxf(mx, l);
    }
    for (int o = 16; o; o >>= 1) mx = fmaxf(mx, __shfl_xor_sync(0xffffffffu, mx, o));
    if ((t & 31) == 0) red[t >> 5] = mx;
    __syncthreads();
    if (t == 0) { float m = red[0]; for (int i = 1; i < 8; i++) m = fmaxf(m, red[i]); sval = m; }
    __syncthreads();
    float MX = sval, sum = 0.f;
    for (int i = t; i < Wn; i += 256) {
        float e = __expf(d_attn[base+i] - MX);
        d_attn[base+i] = e;
        sum += e;
    }
    for (int o = 16; o; o >>= 1) sum += __shfl_xor_sync(0xffffffffu, sum, o);
    __syncthreads();
    if ((t & 31) == 0) red[t >> 5] = sum;
    __syncthreads();
    if (t == 0) { float m = 0.f; for (int i = 0; i < 8; i++) m += red[i]; sval = m; }
    __syncthreads();
    float inv = 1.f / sval;
    for (int i = t; i < Wn; i += 256) {
        float a = d_attn[base+i]*inv;
        d_attn[base+i] = a;
        if (i == Wn-1) d_alast[bh] = a;
    }
}

// ---------------- xbar: attn-weighted row sums of x ----------------
__global__ void xbar_kernel(const float* __restrict__ memory, int S, int Wn) {
    __shared__ float a_s[8][64];
    int t = threadIdx.x;                 // 256
    int w0 = blockIdx.x*64, b = blockIdx.y;
    for (int i = t; i < 512; i += 256) {
        int hh = i >> 6, j = i & 63;
        int w = w0 + j;
        a_s[hh][j] = (w < Wn-1) ? d_attn[((size_t)b*HDIM + hh)*S + w] : 0.f;
    }
    __syncthreads();
    float acc[8][2];
    #pragma unroll
    for (int h = 0; h < 8; h++) { acc[h][0] = 0.f; acc[h][1] = 0.f; }
    int nrow = Wn - 1 - w0; if (nrow > 64) nrow = 64;
    for (int j = 0; j < nrow; j++) {
        size_t sr = (size_t)b*(S-1) + (31 + w0 + j);
        float x0 = memory[sr*DM + t];
        float x1 = memory[sr*DM + 256 + t];
        #pragma unroll
        for (int h = 0; h < 8; h++) {
            float a = a_s[h][j];
            acc[h][0] += a*x0;
            acc[h][1] += a*x1;
        }
    }
    #pragma unroll
    for (int h = 0; h < 8; h++) {
        atomicAdd(&d_xbar[((size_t)b*HDIM + h)*DM + t], acc[h][0]);
        atomicAdd(&d_xbar[((size_t)b*HDIM + h)*DM + 256 + t], acc[h][1]);
    }
}

// ---------------- GRU ----------------
__global__ void gi_kernel(const float* __restrict__ memory, const float* __restrict__ W_ih,
                          const float* __restrict__ b_ih, int S) {
    int tt = blockIdx.x, b = blockIdx.y;
    __shared__ float xs[DM];
    int s = S - MDIM + tt;               // always memory row (tt <= 30)
    const float* row = memory + ((size_t)b*(S-1) + s)*DM;
    for (int i = threadIdx.x; i < DM; i += 192) xs[i] = row[i];
    __syncthreads();
    int j = threadIdx.x;
    const float* wr = W_ih + (size_t)j*DM;
    float acc = b_ih[j];
    #pragma unroll 8
    for (int d = 0; d < DM; d++) acc += xs[d]*wr[d];
    d_gi[((size_t)b*31 + tt)*192 + j] = acc;
}

__global__ void gru_kernel(const float* __restrict__ W_hh, const float* __restrict__ b_hh) {
    int b = blockIdx.x, j = threadIdx.x;  // 192
    __shared__ float hs[DK];
    __shared__ float gh_s[192];
    if (j < DK) hs[j] = 0.f;
    __syncthreads();
    float bh = b_hh[j];
    const float* wr = W_hh + (size_t)j*DK;
    for (int t = 0; t < 31; t++) {
        float gh = bh;
        #pragma unroll 8
        for (int k2 = 0; k2 < DK; k2++) gh += hs[k2]*wr[k2];
        gh_s[j] = gh;
        __syncthreads();
        float hn = 0.f;
        if (j < DK) {
            const float* gi = d_gi + ((size_t)b*31 + t)*192;
            float r = 1.f/(1.f + __expf(-(gi[j] + gh_s[j])));
            float z = 1.f/(1.f + __expf(-(gi[64 + j] + gh_s[64 + j])));
            float n = tanhf(gi[128 + j] + r*gh_s[128 + j]);
            hn = (1.f - z)*n + z*hs[j];
        }
        __syncthreads();
        if (j < DK) hs[j] = hn;
        __syncthreads();
    }
    if (j < DK) d_res[b*DK + j] = hs[j];
}

// ---------------- deta = xbar @ WvM^T + bv*(1-alast) + alast*res ----------------
__global__ void deta_kernel(const float* __restrict__ bv) {
    int bh = blockIdx.x;
    int b = bh >> 3, h = bh & 7;
    int c = threadIdx.x;                 // 64
    __shared__ float xb[DM];
    for (int i = c; i < DM; i += 64) xb[i] = d_xbar[(size_t)bh*DM + i];
    __syncthreads();
    const float* wv = d_WvM + ((size_t)h*DK + c)*DM;
    float acc = 0.f;
    #pragma unroll 8
    for (int d = 0; d < DM; d++) acc += xb[d]*wv[d];
    float al = d_alast[bh];
    d_deta[(size_t)b*DM + h*DK + c] = acc + bv[h*DK + c]*(1.f - al) + al*d_res[b*DK + c];
}

// ---------------- out = x_pre + deta @ WOM^T + bO ----------------
__global__ void out_kernel(const float* __restrict__ x_pre, const float* __restrict__ bO,
                           float* __restrict__ out) {
    int b = blockIdx.x, j = threadIdx.x;  // 512
    __shared__ float dd[DM];
    dd[j] = d_deta[(size_t)b*DM + j];
    __syncthreads();
    const float* wo = d_WOM + (size_t)j*DM;
    float acc = bO[j];
    #pragma unroll 8
    for (int i = 0; i < DM; i++) acc += dd[i]*wo[i];
    out[(size_t)b*DM + j] = x_pre[(size_t)b*DM + j] + acc;
}

extern "C" void kernel_launch(void* const* d_in, const int* in_sizes, int n_in,
                              void* d_out, int out_size) {
    const float* memory = (const float*)d_in[0];
    const float* x_pre  = (const float*)d_in[1];
    const float* aux    = (const float*)d_in[2];
    const float* pos    = (const float*)d_in[3];
    const float* Wq  = (const float*)d_in[4];
    const float* bq  = (const float*)d_in[5];
    const float* Wk  = (const float*)d_in[6];
    const float* bk  = (const float*)d_in[7];
    const float* Wv  = (const float*)d_in[8];
    const float* bv  = (const float*)d_in[9];
    const float* Wqa = (const float*)d_in[10];
    const float* bqa = (const float*)d_in[11];
    const float* Wka = (const float*)d_in[12];
    const float* bka = (const float*)d_in[13];
    const float* Wqp = (const float*)d_in[14];
    const float* bqp = (const float*)d_in[15];
    const float* Wkp = (const float*)d_in[16];
    const float* bkp = (const float*)d_in[17];
    const float* W_ih = (const float*)d_in[18];
    const float* W_hh = (const float*)d_in[19];
    const float* b_ih = (const float*)d_in[20];
    const float* b_hh = (const float*)d_in[21];
    const float* WO = (const float*)d_in[22];
    const float* bO = (const float*)d_in[23];
    const float* w   = (const float*)d_in[24];
    const float* w_a = (const float*)d_in[25];
    const float* w_p = (const float*)d_in[26];
    const int* G = (const int*)d_in[27];
    float* out = (float*)d_out;

    int S  = in_sizes[2] / (BDIM*DA);   // 6144
    int Wn = S - MDIM + 1;              // 6113

    const int smem_k = (2*128*36 + 2*64*36)*4;   // 55296
    const int smem_a = (2*128*36 + 2*32*36)*4;   // 46080
    const int smem_p = (2*128*36 + 2*16*36)*4;   // 41472
    cudaFuncSetAttribute(proj_mma_kernel<DM, DK, 0, 2>,
                         cudaFuncAttributeMaxDynamicSharedMemorySize, smem_k);
    cudaFuncSetAttribute(proj_mma_kernel<DA, DAH, 1, 2>,
                         cudaFuncAttributeMaxDynamicSharedMemorySize, smem_a);
    cudaFuncSetAttribute(proj_mma_kernel<DP, DPH, 2, 2>,
                         cudaFuncAttributeMaxDynamicSharedMemorySize, smem_p);

    mask_kernel<<<1024, 256>>>(Wq, Wk, Wv, WO, G);
    qv_kernel<<<BDIM*HDIM*MDIM, 64>>>(memory, x_pre, bq, S);
    proj_mma_kernel<DM, DK, 0, 2><<<dim3(S/128, HDIM, BDIM), 256, smem_k>>>(memory, x_pre, nullptr, bk, S, Wn);
    band_mma_kernel<<<dim3((Wn + 63)/64, HDIM, BDIM), 128>>>(S, Wn);
    qa_kernel<<<BDIM*HDIM, 32>>>(aux, Wqa, bqa, S);
    proj_mma_kernel<DA, DAH, 1, 2><<<dim3(S/128, HDIM, BDIM), 256, smem_a>>>(aux, nullptr, Wka, bka, S, Wn);
    qp_kernel<<<BDIM*HDIM, 32>>>(pos, Wqp, bqp, S);
    proj_mma_kernel<DP, DPH, 2, 2><<<dim3(S/128, HDIM, BDIM), 256, smem_p>>>(pos, nullptr, Wkp, bkp, S, Wn);
    softmax_kernel<<<BDIM*HDIM, 256>>>(w, w_a, w_p, S, Wn);
    xbar_kernel<<<dim3((Wn - 1 + 63)/64, BDIM), 256>>>(memory, S, Wn);
    gi_kernel<<<dim3(31, BDIM), 192>>>(memory, W_ih, b_ih, S);
    gru_kernel<<<BDIM, 192>>>(W_hh, b_hh);
    deta_kernel<<<BDIM*HDIM, 64>>>(bv);
    out_kernel<<<BDIM, 512>>>(x_pre, bO, out);
}

// round 7
// speedup vs baseline: 1.8385x; 1.8385x over previous
#include <cuda_runtime.h>
#include <math.h>
#include <stdint.h>
#include <stddef.h>

// fixed problem shapes
#define BDIM 8
#define HDIM 8
#define DM 512
#define DA 256
#define DP 128
#define MDIM 32
#define DK 64
#define DAH 32
#define DPH 16
#define SDIM 6144

// ---------------- device scratch ----------------
__device__ float d_WkM[HDIM*DK*DM];
__device__ float d_WqMT[HDIM*DM*DK];   // [h][d][c]
__device__ float d_WvMT[HDIM*DM*DK];   // [h][d][c]
__device__ float d_WOMT[DM*DM];        // [i][j] = WOM[j][i]
__device__ float d_WihT[DM*192];       // [d][j]
__device__ float d_WhhT[DK*192];       // [k][j]
__device__ float d_Kn[(size_t)BDIM*HDIM*SDIM*DK];   // ~100 MB
__device__ float d_Qv[BDIM*HDIM*MDIM*DK];
__device__ float d_QA[BDIM*HDIM*DAH];
__device__ float d_QP[BDIM*HDIM*DPH];
__device__ float d_tn[BDIM*HDIM*SDIM];
__device__ float d_dot2[BDIM*HDIM*SDIM];
__device__ float d_dot3[BDIM*HDIM*SDIM];
__device__ float d_attn[BDIM*HDIM*SDIM];
__device__ float d_alast[BDIM*HDIM];
__device__ float d_xbar[BDIM*HDIM*DM];
__device__ float d_gi[BDIM*31*192];
__device__ float d_res[BDIM*DK];
__device__ float d_deta[BDIM*DM];

__device__ __forceinline__ void mma_tf32(float* c, const uint32_t* a, uint32_t b0, uint32_t b1) {
    asm volatile("mma.sync.aligned.m16n8k8.row.col.f32.tf32.tf32.f32 "
        "{%0,%1,%2,%3}, {%4,%5,%6,%7}, {%8,%9}, {%0,%1,%2,%3};\n"
        : "+f"(c[0]), "+f"(c[1]), "+f"(c[2]), "+f"(c[3])
        : "r"(a[0]), "r"(a[1]), "r"(a[2]), "r"(a[3]), "r"(b0), "r"(b1));
}

__device__ __forceinline__ void cpa16(uint32_t saddr, const void* g) {
    asm volatile("cp.async.cg.shared.global [%0], [%1], 16;" :: "r"(saddr), "l"(g));
}
__device__ __forceinline__ void cpa_commit() { asm volatile("cp.async.commit_group;"); }
__device__ __forceinline__ void cpa_wait0() { asm volatile("cp.async.wait_group 0;" ::: "memory"); }
__device__ __forceinline__ void cpa_wait1() { asm volatile("cp.async.wait_group 1;" ::: "memory"); }

// ---------------- masked weights (+ transposes) + zero xbar ----------------
__global__ void mask_kernel(const float* __restrict__ Wq, const float* __restrict__ Wk,
                            const float* __restrict__ Wv, const float* __restrict__ WO,
                            const float* __restrict__ W_ih, const float* __restrict__ W_hh,
                            const int* __restrict__ G) {
    int i = blockIdx.x*256 + threadIdx.x;
    const int NW = HDIM*DK*DM;
    if (i < NW) {
        int h = i >> 15;
        int c = (i >> 9) & 63;
        int d = i & 511;
        float g = (float)G[c*64 + (d & 63)];
        d_WkM[i] = Wk[i]*g;
        d_WqMT[((size_t)h*DM + d)*DK + c] = Wq[i]*g;
        d_WvMT[((size_t)h*DM + d)*DK + c] = Wv[i]*g;
    }
    if (i < DM*DM) {
        int j = i & 511, r = i >> 9;
        d_WOMT[(size_t)j*DM + r] = WO[i]*(float)G[(r & 63)*64 + (j & 63)];
    }
    if (i < 192*DM) {
        int j = i >> 9, d = i & 511;
        d_WihT[d*192 + j] = W_ih[i];
    }
    if (i < 192*DK) {
        int j = i >> 6, k = i & 63;
        d_WhhT[k*192 + j] = W_hh[i];
    }
    if (i < BDIM*HDIM*DM) d_xbar[i] = 0.f;
}

// ---------------- Qv: last M rows, masked proj + l2norm (coalesced WqMT) ----------------
__global__ void qv_kernel(const float* __restrict__ memory, const float* __restrict__ x_pre,
                          const float* __restrict__ bq, int S) {
    int m = blockIdx.x & 31, h = (blockIdx.x >> 5) & 7, b = blockIdx.x >> 8;
    __shared__ float xs[DM];
    __shared__ float wp[2];
    int s = S - MDIM + m;
    const float* row = (s < S-1) ? memory + ((size_t)b*(S-1) + s)*DM : x_pre + (size_t)b*DM;
    for (int i = threadIdx.x; i < DM; i += 64) xs[i] = row[i];
    __syncthreads();
    int c = threadIdx.x;
    const float* wt = d_WqMT + (size_t)h*DM*DK;
    float acc = bq[h*DK + c];
    #pragma unroll 8
    for (int d = 0; d < DM; d++) acc += xs[d]*wt[d*DK + c];
    float v = acc*acc;
    for (int o = 16; o; o >>= 1) v += __shfl_xor_sync(0xffffffffu, v, o);
    if ((c & 31) == 0) wp[c >> 5] = v;
    __syncthreads();
    float inv = 1.f / fmaxf(sqrtf(wp[0] + wp[1]), 1e-12f);
    d_Qv[(((size_t)b*HDIM + h)*MDIM + m)*DK + c] = acc*inv;
}

// ---------------- tensor-core projection (tf32 mma, cp.async double-buffered) ----------------
template<int DIN, int DOUT, int MODE, int NW_N>
__global__ void __launch_bounds__(256)
proj_mma_kernel(const float* __restrict__ src0, const float* __restrict__ x_pre,
                const float* __restrict__ W, const float* __restrict__ bias,
                int S, int Wn) {
    constexpr int NW_M = 8/NW_N;
    constexpr int TM   = NW_M*32;
    constexpr int WT_N = DOUT/NW_N;
    constexpr int NFN  = WT_N/8;
    constexpr int NCH  = DIN/32;

    extern __shared__ uint32_t dynsm[];
    uint32_t* Xs  = dynsm;               // 2 * TM * 36
    uint32_t* Wss = dynsm + 2*TM*36;     // 2 * DOUT * 36
    __shared__ float bs_s[DOUT];
    __shared__ float qs_s[DOUT];
    __shared__ float red_s[TM*2];

    int tid = threadIdx.x;
    int lane = tid & 31, wid = tid >> 5;
    int g = lane >> 2, tig = lane & 3;
    int warp_n = wid % NW_N, warp_m = wid / NW_N;
    int rb = warp_m*32, cb = warp_n*WT_N;
    int s0 = blockIdx.x*TM, h = blockIdx.y, b = blockIdx.z;
    int bh = b*HDIM + h;

    uint32_t xB = (uint32_t)__cvta_generic_to_shared(Xs);
    uint32_t wB = (uint32_t)__cvta_generic_to_shared(Wss);

    for (int i = tid; i < DOUT; i += 256) {
        bs_s[i] = bias[h*DOUT + i];
        if (MODE == 1) qs_s[i] = d_QA[(size_t)bh*DAH + i];
        if (MODE == 2) qs_s[i] = d_QP[(size_t)bh*DPH + i];
    }

    auto load_chunk = [&](int ch, int buf) {
        int d0 = ch*32;
        #pragma unroll
        for (int it = 0; it < TM*8/256; it++) {
            int e = it*256 + tid;
            int row = e >> 3, c4 = (e & 7)*4;
            int s = s0 + row;
            const float* rp;
            if (MODE == 0)
                rp = (s < S-1) ? src0 + ((size_t)b*(S-1) + s)*DIN : x_pre + (size_t)b*DIN;
            else
                rp = src0 + ((size_t)b*S + s)*DIN;
            cpa16(xB + (buf*TM*36 + row*36 + c4)*4, rp + d0 + c4);
        }
        for (int e = tid; e < DOUT*8; e += 256) {
            int rr = e >> 3, c4 = (e & 7)*4;
            const float* wp;
            if (MODE == 0) wp = d_WkM + ((size_t)(h*DOUT + rr))*DIN + d0 + c4;
            else           wp = W + ((size_t)(h*DOUT + rr))*DIN + d0 + c4;
            cpa16(wB + (buf*DOUT*36 + rr*36 + c4)*4, wp);
        }
    };

    float acc[2][NFN][4];
    #pragma unroll
    for (int mi = 0; mi < 2; mi++)
        #pragma unroll
        for (int ni = 0; ni < NFN; ni++)
            #pragma unroll
            for (int q = 0; q < 4; q++) acc[mi][ni][q] = 0.f;

    load_chunk(0, 0);
    cpa_commit();

    for (int ch = 0; ch < NCH; ch++) {
        if (ch + 1 < NCH) {
            load_chunk(ch + 1, (ch + 1) & 1);
            cpa_commit();
            cpa_wait1();
        } else {
            cpa_wait0();
        }
        __syncthreads();
        const uint32_t* Xb = Xs + (ch & 1)*TM*36;
        const uint32_t* Wb = Wss + (ch & 1)*DOUT*36;
        #pragma unroll
        for (int ks = 0; ks < 4; ks++) {
            int k0 = ks*8;
            uint32_t a[2][4];
            #pragma unroll
            for (int mi = 0; mi < 2; mi++) {
                int r = rb + mi*16 + g;
                a[mi][0] = Xb[r*36 + k0 + tig];
                a[mi][1] = Xb[(r+8)*36 + k0 + tig];
                a[mi][2] = Xb[r*36 + k0 + tig + 4];
                a[mi][3] = Xb[(r+8)*36 + k0 + tig + 4];
            }
            #pragma unroll
            for (int ni = 0; ni < NFN; ni++) {
                int cn = cb + ni*8 + g;
                uint32_t b0 = Wb[cn*36 + k0 + tig];
                uint32_t b1 = Wb[cn*36 + k0 + tig + 4];
                #pragma unroll
                for (int mi = 0; mi < 2; mi++) mma_tf32(acc[mi][ni], a[mi], b0, b1);
            }
        }
        __syncthreads();
    }

    // ---- epilogue: bias + per-row l2 norm ----
    float sl[2] = {0.f, 0.f}, sh[2] = {0.f, 0.f};
    #pragma unroll
    for (int mi = 0; mi < 2; mi++)
        #pragma unroll
        for (int ni = 0; ni < NFN; ni++) {
            int c0 = cb + ni*8 + 2*tig, c1 = c0 + 1;
            acc[mi][ni][0] += bs_s[c0];
            acc[mi][ni][1] += bs_s[c1];
            acc[mi][ni][2] += bs_s[c0];
            acc[mi][ni][3] += bs_s[c1];
            sl[mi] += acc[mi][ni][0]*acc[mi][ni][0] + acc[mi][ni][1]*acc[mi][ni][1];
            sh[mi] += acc[mi][ni][2]*acc[mi][ni][2] + acc[mi][ni][3]*acc[mi][ni][3];
        }
    #pragma unroll
    for (int mi = 0; mi < 2; mi++) {
        sl[mi] += __shfl_xor_sync(0xffffffffu, sl[mi], 1);
        sl[mi] += __shfl_xor_sync(0xffffffffu, sl[mi], 2);
        sh[mi] += __shfl_xor_sync(0xffffffffu, sh[mi], 1);
        sh[mi] += __shfl_xor_sync(0xffffffffu, sh[mi], 2);
    }
    if (NW_N == 2) {
        if (tig == 0) {
            #pragma unroll
            for (int mi = 0; mi < 2; mi++) {
                int rl = rb + mi*16 + g;
                red_s[rl*2 + warp_n] = sl[mi];
                red_s[(rl+8)*2 + warp_n] = sh[mi];
            }
        }
        __syncthreads();
        #pragma unroll
        for (int mi = 0; mi < 2; mi++) {
            int rl = rb + mi*16 + g;
            sl[mi] = red_s[rl*2] + red_s[rl*2+1];
            sh[mi] = red_s[(rl+8)*2] + red_s[(rl+8)*2+1];
        }
    }
    float il[2], ih[2];
    #pragma unroll
    for (int mi = 0; mi < 2; mi++) {
        il[mi] = 1.f / fmaxf(sqrtf(sl[mi]), 1e-12f);
        ih[mi] = 1.f / fmaxf(sqrtf(sh[mi]), 1e-12f);
    }

    if (MODE == 0) {
        #pragma unroll
        for (int mi = 0; mi < 2; mi++) {
            int rl = rb + mi*16 + g;
            size_t base_l = ((size_t)bh*S + s0 + rl)*DK;
            size_t base_h = ((size_t)bh*S + s0 + rl + 8)*DK;
            #pragma unroll
            for (int ni = 0; ni < NFN; ni++) {
                int c0 = cb + ni*8 + 2*tig;
                float2 v0 = make_float2(acc[mi][ni][0]*il[mi], acc[mi][ni][1]*il[mi]);
                float2 v1 = make_float2(acc[mi][ni][2]*ih[mi], acc[mi][ni][3]*ih[mi]);
                *(float2*)&d_Kn[base_l + c0] = v0;
                *(float2*)&d_Kn[base_h + c0] = v1;
            }
        }
    } else {
        float* dst = (MODE == 1) ? d_dot2 : d_dot3;
        float dl[2], dh[2];
        #pragma unroll
        for (int mi = 0; mi < 2; mi++) {
            dl[mi] = 0.f; dh[mi] = 0.f;
            #pragma unroll
            for (int ni = 0; ni < NFN; ni++) {
                int c0 = cb + ni*8 + 2*tig, c1 = c0 + 1;
                dl[mi] += acc[mi][ni][0]*qs_s[c0] + acc[mi][ni][1]*qs_s[c1];
                dh[mi] += acc[mi][ni][2]*qs_s[c0] + acc[mi][ni][3]*qs_s[c1];
            }
            dl[mi] += __shfl_xor_sync(0xffffffffu, dl[mi], 1);
            dl[mi] += __shfl_xor_sync(0xffffffffu, dl[mi], 2);
            dh[mi] += __shfl_xor_sync(0xffffffffu, dh[mi], 1);
            dh[mi] += __shfl_xor_sync(0xffffffffu, dh[mi], 2);
        }
        if (NW_N == 2) {
            __syncthreads();
            if (tig == 0) {
                #pragma unroll
                for (int mi = 0; mi < 2; mi++) {
                    int rl = rb + mi*16 + g;
                    red_s[rl*2 + warp_n] = dl[mi];
                    red_s[(rl+8)*2 + warp_n] = dh[mi];
                }
            }
            __syncthreads();
            if (warp_n == 0 && tig == 0) {
                #pragma unroll
                for (int mi = 0; mi < 2; mi++) {
                    int rl = rb + mi*16 + g;
                    float DL = red_s[rl*2] + red_s[rl*2+1];
                    float DH = red_s[(rl+8)*2] + red_s[(rl+8)*2+1];
                    int wl = s0 + rl - 31, wh = wl + 8;
                    if (wl >= 0 && wl < Wn) dst[(size_t)bh*S + wl] = DL*il[mi];
                    if (wh >= 0 && wh < Wn) dst[(size_t)bh*S + wh] = DH*ih[mi];
                }
            }
        } else {
            if (tig == 0) {
                #pragma unroll
                for (int mi = 0; mi < 2; mi++) {
                    int rl = rb + mi*16 + g;
                    int wl = s0 + rl - 31, wh = wl + 8;
                    if (wl >= 0 && wl < Wn) dst[(size_t)bh*S + wl] = dl[mi]*il[mi];
                    if (wh >= 0 && wh < Wn) dst[(size_t)bh*S + wh] = dh[mi]*ih[mi];
                }
            }
        }
    }
}

// ---------------- banded Qv . Kn -> tn  (tf32 mma) ----------------
__global__ void __launch_bounds__(128) band_mma_kernel(int S, int Wn) {
    __shared__ uint32_t Qs[32*68];
    __shared__ uint32_t Ks[96*68];
    __shared__ float Ps[32*100];
    int tid = threadIdx.x;
    int lane = tid & 31, wid = tid >> 5;
    int g = lane >> 2, tig = lane & 3;
    int w0 = blockIdx.x*64, h = blockIdx.y, b = blockIdx.z;
    int bh = b*HDIM + h;

    uint32_t qB = (uint32_t)__cvta_generic_to_shared(Qs);
    uint32_t kB = (uint32_t)__cvta_generic_to_shared(Ks);

    for (int e = tid; e < 96*16; e += 128) {
        int r = e >> 4, c4 = (e & 15)*4;
        int s = w0 + r;
        uint32_t sa = kB + (r*68 + c4)*4;
        if (s < S) cpa16(sa, d_Kn + ((size_t)bh*S + s)*DK + c4);
        else {
            *(float4*)((char*)Ks + (size_t)(r*68 + c4)*4) = make_float4(0.f,0.f,0.f,0.f);
        }
    }
    for (int e = tid; e < 32*16; e += 128) {
        int r = e >> 4, c4 = (e & 15)*4;
        cpa16(qB + (r*68 + c4)*4, d_Qv + ((size_t)bh*MDIM + r)*DK + c4);
    }
    cpa_commit();
    cpa_wait0();
    __syncthreads();

    float acc[2][3][4];
    #pragma unroll
    for (int mi = 0; mi < 2; mi++)
        #pragma unroll
        for (int ni = 0; ni < 3; ni++)
            #pragma unroll
            for (int q = 0; q < 4; q++) acc[mi][ni][q] = 0.f;
    int nb = wid*24;
    #pragma unroll
    for (int ks = 0; ks < 8; ks++) {
        int k0 = ks*8;
        uint32_t a[2][4];
        #pragma unroll
        for (int mi = 0; mi < 2; mi++) {
            int r = mi*16 + g;
            a[mi][0] = Qs[r*68 + k0 + tig];
            a[mi][1] = Qs[(r+8)*68 + k0 + tig];
            a[mi][2] = Qs[r*68 + k0 + tig + 4];
            a[mi][3] = Qs[(r+8)*68 + k0 + tig + 4];
        }
        #pragma unroll
        for (int ni = 0; ni < 3; ni++) {
            int cn = nb + ni*8 + g;
            uint32_t b0 = Ks[cn*68 + k0 + tig];
            uint32_t b1 = Ks[cn*68 + k0 + tig + 4];
            #pragma unroll
            for (int mi = 0; mi < 2; mi++) mma_tf32(acc[mi][ni], a[mi], b0, b1);
        }
    }
    #pragma unroll
    for (int mi = 0; mi < 2; mi++)
        #pragma unroll
        for (int ni = 0; ni < 3; ni++) {
            int c0 = nb + ni*8 + 2*tig;
            int r = mi*16 + g;
            Ps[r*100 + c0]     = acc[mi][ni][0];
            Ps[r*100 + c0 + 1] = acc[mi][ni][1];
            Ps[(r+8)*100 + c0]     = acc[mi][ni][2];
            Ps[(r+8)*100 + c0 + 1] = acc[mi][ni][3];
        }
    __syncthreads();
    if (tid < 64) {
        int w = w0 + tid;
        if (w < Wn) {
            float s = 0.f;
            #pragma unroll
            for (int m = 0; m < 32; m++) s += Ps[m*100 + tid + m];
            d_tn[(size_t)bh*S + w] = s*(1.f/32.f);
        }
    }
}

// ---------------- QA / QP (last-row queries, fp32) ----------------
__global__ void qa_kernel(const float* __restrict__ aux, const float* __restrict__ Wqa,
                          const float* __restrict__ bqa, int S) {
    int h = blockIdx.x & 7, b = blockIdx.x >> 3;
    int c = threadIdx.x;  // 32
    const float* ar = aux + ((size_t)b*S + (S-1))*DA;
    const float* wr = Wqa + ((size_t)h*DAH + c)*DA;
    float acc = bqa[h*DAH + c];
    #pragma unroll 4
    for (int d = 0; d < DA; d++) acc += ar[d]*wr[d];
    float v = acc*acc;
    for (int o = 16; o; o >>= 1) v += __shfl_xor_sync(0xffffffffu, v, o);
    float inv = 1.f / fmaxf(sqrtf(v), 1e-12f);
    d_QA[((size_t)b*HDIM + h)*DAH + c] = acc*inv;
}

__global__ void qp_kernel(const float* __restrict__ pos, const float* __restrict__ Wqp,
                          const float* __restrict__ bqp, int S) {
    int h = blockIdx.x & 7, b = blockIdx.x >> 3;
    int lane = threadIdx.x;   // 32
    int c = lane & 15;
    const float* pr = pos + ((size_t)b*S + (S-1))*DP;
    const float* wr = Wqp + ((size_t)h*DPH + c)*DP;
    float acc = bqp[h*DPH + c];
    #pragma unroll 4
    for (int d = 0; d < DP; d++) acc += pr[d]*wr[d];
    float v = acc*acc;
    for (int o = 8; o; o >>= 1) v += __shfl_xor_sync(0xffffffffu, v, o);
    float inv = 1.f / fmaxf(sqrtf(v), 1e-12f);
    if (lane < 16) d_QP[((size_t)b*HDIM + h)*DPH + c] = acc*inv;
}

// ---------------- softmax over Wn ----------------
__global__ void softmax_kernel(const float* __restrict__ w1, const float* __restrict__ w2,
                               const float* __restrict__ w3, int S, int Wn) {
    int bh = blockIdx.x, t = threadIdx.x;   // 256
    __shared__ float red[8];
    __shared__ float sval;
    float c1 = w1[0], c2 = w2[0], c3 = w3[0];
    size_t base = (size_t)bh*S;
    float mx = -1e30f;
    for (int i = t; i < Wn; i += 256) {
        float l = c1*d_tn[base+i] + c2*d_dot2[base+i] + c3*d_dot3[base+i];
        d_attn[base+i] = l;
        mx = fmaxf(mx, l);
    }
    for (int o = 16; o; o >>= 1) mx = fmaxf(mx, __shfl_xor_sync(0xffffffffu, mx, o));
    if ((t & 31) == 0) red[t >> 5] = mx;
    __syncthreads();
    if (t == 0) { float m = red[0]; for (int i = 1; i < 8; i++) m = fmaxf(m, red[i]); sval = m; }
    __syncthreads();
    float MX = sval, sum = 0.f;
    for (int i = t; i < Wn; i += 256) {
        float e = __expf(d_attn[base+i] - MX);
        d_attn[base+i] = e;
        sum += e;
    }
    for (int o = 16; o; o >>= 1) sum += __shfl_xor_sync(0xffffffffu, sum, o);
    __syncthreads();
    if ((t & 31) == 0) red[t >> 5] = sum;
    __syncthreads();
    if (t == 0) { float m = 0.f; for (int i = 0; i < 8; i++) m += red[i]; sval = m; }
    __syncthreads();
    float inv = 1.f / sval;
    for (int i = t; i < Wn; i += 256) {
        float a = d_attn[base+i]*inv;
        d_attn[base+i] = a;
        if (i == Wn-1) d_alast[bh] = a;
    }
}

// ---------------- xbar: attn-weighted row sums of x ----------------
__global__ void xbar_kernel(const float* __restrict__ memory, int S, int Wn) {
    __shared__ float a_s[8][64];
    int t = threadIdx.x;                 // 256
    int w0 = blockIdx.x*64, b = blockIdx.y;
    for (int i = t; i < 512; i += 256) {
        int hh = i >> 6, j = i & 63;
        int w = w0 + j;
        a_s[hh][j] = (w < Wn-1) ? d_attn[((size_t)b*HDIM + hh)*S + w] : 0.f;
    }
    __syncthreads();
    float acc[8][2];
    #pragma unroll
    for (int h = 0; h < 8; h++) { acc[h][0] = 0.f; acc[h][1] = 0.f; }
    int nrow = Wn - 1 - w0; if (nrow > 64) nrow = 64;
    for (int j = 0; j < nrow; j++) {
        size_t sr = (size_t)b*(S-1) + (31 + w0 + j);
        float x0 = memory[sr*DM + t];
        float x1 = memory[sr*DM + 256 + t];
        #pragma unroll
        for (int h = 0; h < 8; h++) {
            float a = a_s[h][j];
            acc[h][0] += a*x0;
            acc[h][1] += a*x1;
        }
    }
    #pragma unroll
    for (int h = 0; h < 8; h++) {
        atomicAdd(&d_xbar[((size_t)b*HDIM + h)*DM + t], acc[h][0]);
        atomicAdd(&d_xbar[((size_t)b*HDIM + h)*DM + 256 + t], acc[h][1]);
    }
}

// ---------------- GRU ----------------
__global__ void gi_kernel(const float* __restrict__ memory, const float* __restrict__ b_ih,
                          int S) {
    int tt = blockIdx.x, b = blockIdx.y;
    __shared__ float xs[DM];
    int s = S - MDIM + tt;
    const float* row = memory + ((size_t)b*(S-1) + s)*DM;
    for (int i = threadIdx.x; i < DM; i += 192) xs[i] = row[i];
    __syncthreads();
    int j = threadIdx.x;
    float acc = b_ih[j];
    #pragma unroll 8
    for (int d = 0; d < DM; d++) acc += xs[d]*d_WihT[d*192 + j];
    d_gi[((size_t)b*31 + tt)*192 + j] = acc;
}

__global__ void gru_kernel(const float* __restrict__ b_hh) {
    int b = blockIdx.x, j = threadIdx.x;  // 192
    __shared__ float hs[DK];
    __shared__ float gh_s[192];
    if (j < DK) hs[j] = 0.f;
    __syncthreads();
    float bh = b_hh[j];
    for (int t = 0; t < 31; t++) {
        float gh = bh;
        #pragma unroll 8
        for (int k2 = 0; k2 < DK; k2++) gh += hs[k2]*d_WhhT[k2*192 + j];
        gh_s[j] = gh;
        __syncthreads();
        float hn = 0.f;
        if (j < DK) {
            const float* gi = d_gi + ((size_t)b*31 + t)*192;
            float r = 1.f/(1.f + __expf(-(gi[j] + gh_s[j])));
            float z = 1.f/(1.f + __expf(-(gi[64 + j] + gh_s[64 + j])));
            float n = tanhf(gi[128 + j] + r*gh_s[128 + j]);
            hn = (1.f - z)*n + z*hs[j];
        }
        __syncthreads();
        if (j < DK) hs[j] = hn;
        __syncthreads();
    }
    if (j < DK) d_res[b*DK + j] = hs[j];
}

// ---------------- deta = xbar @ WvM^T + bv*(1-alast) + alast*res ----------------
__global__ void deta_kernel(const float* __restrict__ bv) {
    int bh = blockIdx.x;
    int b = bh >> 3, h = bh & 7;
    int c = threadIdx.x;                 // 64
    __shared__ float xb[DM];
    for (int i = c; i < DM; i += 64) xb[i] = d_xbar[(size_t)bh*DM + i];
    __syncthreads();
    const float* wt = d_WvMT + (size_t)h*DM*DK;
    float acc = 0.f;
    #pragma unroll 8
    for (int d = 0; d < DM; d++) acc += xb[d]*wt[d*DK + c];
    float al = d_alast[bh];
    d_deta[(size_t)b*DM + h*DK + c] = acc + bv[h*DK + c]*(1.f - al) + al*d_res[b*DK + c];
}

// ---------------- out = x_pre + deta @ WOM^T + bO ----------------
__global__ void out_kernel(const float* __restrict__ x_pre, const float* __restrict__ bO,
                           float* __restrict__ out) {
    int b = blockIdx.x, j = threadIdx.x;  // 512
    __shared__ float dd[DM];
    dd[j] = d_deta[(size_t)b*DM + j];
    __syncthreads();
    float acc = bO[j];
    #pragma unroll 8
    for (int i = 0; i < DM; i++) acc += dd[i]*d_WOMT[(size_t)i*DM + j];
    out[(size_t)b*DM + j] = x_pre[(size_t)b*DM + j] + acc;
}

extern "C" void kernel_launch(void* const* d_in, const int* in_sizes, int n_in,
                              void* d_out, int out_size) {
    const float* memory = (const float*)d_in[0];
    const float* x_pre  = (const float*)d_in[1];
    const float* aux    = (const float*)d_in[2];
    const float* pos    = (const float*)d_in[3];
    const float* Wq  = (const float*)d_in[4];
    const float* bq  = (const float*)d_in[5];
    const float* Wk  = (const float*)d_in[6];
    const float* bk  = (const float*)d_in[7];
    const float* Wv  = (const float*)d_in[8];
    const float* bv  = (const float*)d_in[9];
    const float* Wqa = (const float*)d_in[10];
    const float* bqa = (const float*)d_in[11];
    const float* Wka = (const float*)d_in[12];
    const float* bka = (const float*)d_in[13];
    const float* Wqp = (const float*)d_in[14];
    const float* bqp = (const float*)d_in[15];
    const float* Wkp = (const float*)d_in[16];
    const float* bkp = (const float*)d_in[17];
    const float* W_ih = (const float*)d_in[18];
    const float* W_hh = (const float*)d_in[19];
    const float* b_ih = (const float*)d_in[20];
    const float* b_hh = (const float*)d_in[21];
    const float* WO = (const float*)d_in[22];
    const float* bO = (const float*)d_in[23];
    const float* w   = (const float*)d_in[24];
    const float* w_a = (const float*)d_in[25];
    const float* w_p = (const float*)d_in[26];
    const int* G = (const int*)d_in[27];
    float* out = (float*)d_out;

    int S  = in_sizes[2] / (BDIM*DA);   // 6144
    int Wn = S - MDIM + 1;              // 6113

    const int smem_k = (2*128*36 + 2*64*36)*4;   // 55296
    const int smem_a = (2*128*36 + 2*32*36)*4;   // 46080
    const int smem_p = (2*128*36 + 2*16*36)*4;   // 41472
    cudaFuncSetAttribute(proj_mma_kernel<DM, DK, 0, 2>,
                         cudaFuncAttributeMaxDynamicSharedMemorySize, smem_k);
    cudaFuncSetAttribute(proj_mma_kernel<DA, DAH, 1, 2>,
                         cudaFuncAttributeMaxDynamicSharedMemorySize, smem_a);
    cudaFuncSetAttribute(proj_mma_kernel<DP, DPH, 2, 2>,
                         cudaFuncAttributeMaxDynamicSharedMemorySize, smem_p);

    mask_kernel<<<1024, 256>>>(Wq, Wk, Wv, WO, W_ih, W_hh, G);
    qv_kernel<<<BDIM*HDIM*MDIM, 64>>>(memory, x_pre, bq, S);
    proj_mma_kernel<DM, DK, 0, 2><<<dim3(S/128, HDIM, BDIM), 256, smem_k>>>(memory, x_pre, nullptr, bk, S, Wn);
    band_mma_kernel<<<dim3((Wn + 63)/64, HDIM, BDIM), 128>>>(S, Wn);
    qa_kernel<<<BDIM*HDIM, 32>>>(aux, Wqa, bqa, S);
    proj_mma_kernel<DA, DAH, 1, 2><<<dim3(S/128, HDIM, BDIM), 256, smem_a>>>(aux, nullptr, Wka, bka, S, Wn);
    qp_kernel<<<BDIM*HDIM, 32>>>(pos, Wqp, bqp, S);
    proj_mma_kernel<DP, DPH, 2, 2><<<dim3(S/128, HDIM, BDIM), 256, smem_p>>>(pos, nullptr, Wkp, bkp, S, Wn);
    softmax_kernel<<<BDIM*HDIM, 256>>>(w, w_a, w_p, S, Wn);
    xbar_kernel<<<dim3((Wn - 1 + 63)/64, BDIM), 256>>>(memory, S, Wn);
    gi_kernel<<<dim3(31, BDIM), 192>>>(memory, b_ih, S);
    gru_kernel<<<BDIM, 192>>>(b_hh);
    deta_kernel<<<BDIM*HDIM, 64>>>(bv);
    out_kernel<<<BDIM, 512>>>(x_pre, bO, out);
}

// round 9
// speedup vs baseline: 2.1122x; 1.1489x over previous
#include <cuda_runtime.h>
#include <cuda_bf16.h>
#include <math.h>
#include <stdint.h>
#include <stddef.h>

// fixed problem shapes
#define BDIM 8
#define HDIM 8
#define DM 512
#define DA 256
#define DP 128
#define MDIM 32
#define DK 64
#define DAH 32
#define DPH 16
#define SDIM 6144

// ---------------- device scratch ----------------
__device__ __nv_bfloat16 d_Xbf[(size_t)BDIM*SDIM*DM];
__device__ __nv_bfloat16 d_Abf[(size_t)BDIM*SDIM*DA];
__device__ __nv_bfloat16 d_Pbf[(size_t)BDIM*SDIM*DP];
__device__ __nv_bfloat16 d_WkMbf[HDIM*DK*DM];
__device__ __nv_bfloat16 d_Wkabf[HDIM*DAH*DA];
__device__ __nv_bfloat16 d_Wkpbf[HDIM*DPH*DP];
__device__ float d_WqMT[HDIM*DM*DK];   // [h][d][c]
__device__ float d_WvMT[HDIM*DM*DK];   // [h][d][c]
__device__ float d_WOMT[DM*DM];        // [i][j] = WOM[j][i]
__device__ float d_WihT[DM*192];       // [d][j]
__device__ float d_WhhT[DK*192];       // [k][j]
__device__ __nv_bfloat16 d_Knbf[(size_t)BDIM*HDIM*SDIM*DK];  // ~50 MB
__device__ __nv_bfloat16 d_Qvbf[BDIM*HDIM*MDIM*DK];
__device__ float d_QA[BDIM*HDIM*DAH];
__device__ float d_QP[BDIM*HDIM*DPH];
__device__ float d_tn[BDIM*HDIM*SDIM];
__device__ float d_dot2[BDIM*HDIM*SDIM];
__device__ float d_dot3[BDIM*HDIM*SDIM];
__device__ float d_attn[BDIM*HDIM*SDIM];
__device__ float d_alast[BDIM*HDIM];
__device__ float d_xbar[BDIM*HDIM*DM];
__device__ float d_gi[BDIM*31*192];
__device__ float d_res[BDIM*DK];
__device__ float d_deta[BDIM*DM];

__device__ __forceinline__ void mma_bf16(float* c, const uint32_t* a, uint32_t b0, uint32_t b1) {
    asm volatile("mma.sync.aligned.m16n8k16.row.col.f32.bf16.bf16.f32 "
        "{%0,%1,%2,%3}, {%4,%5,%6,%7}, {%8,%9}, {%0,%1,%2,%3};\n"
        : "+f"(c[0]), "+f"(c[1]), "+f"(c[2]), "+f"(c[3])
        : "r"(a[0]), "r"(a[1]), "r"(a[2]), "r"(a[3]), "r"(b0), "r"(b1));
}

__device__ __forceinline__ void cpa16(uint32_t saddr, const void* g) {
    asm volatile("cp.async.cg.shared.global [%0], [%1], 16;" :: "r"(saddr), "l"(g));
}
__device__ __forceinline__ void cpa_commit() { asm volatile("cp.async.commit_group;"); }
__device__ __forceinline__ void cpa_wait0() { asm volatile("cp.async.wait_group 0;" ::: "memory"); }
__device__ __forceinline__ void cpa_wait1() { asm volatile("cp.async.wait_group 1;" ::: "memory"); }

__device__ __forceinline__ uint32_t packbf(float a, float b) {
    __nv_bfloat162 t = __floats2bfloat162_rn(a, b);
    return *(uint32_t*)&t;
}

// ---------------- fp32 -> bf16 conversion of activations ----------------
__global__ void convert_kernel(const float* __restrict__ memory, const float* __restrict__ x_pre,
                               const float* __restrict__ aux, const float* __restrict__ pos,
                               int S) {
    int stride = gridDim.x*256;
    int nX = BDIM*S*(DM/4);
    for (int j = blockIdx.x*256 + threadIdx.x; j < nX; j += stride) {
        int b = j / (S*(DM/4));
        int r = j % (S*(DM/4));
        int s = r / (DM/4);
        int d4 = (r % (DM/4))*4;
        const float* src = (s < S-1) ? memory + ((size_t)b*(S-1) + s)*DM + d4
                                     : x_pre + (size_t)b*DM + d4;
        float4 v = *(const float4*)src;
        uint2 o; o.x = packbf(v.x, v.y); o.y = packbf(v.z, v.w);
        *(uint2*)&d_Xbf[((size_t)b*S + s)*DM + d4] = o;
    }
    int nA = BDIM*S*(DA/4);
    for (int j = blockIdx.x*256 + threadIdx.x; j < nA; j += stride) {
        float4 v = *(const float4*)(aux + (size_t)j*4);
        uint2 o; o.x = packbf(v.x, v.y); o.y = packbf(v.z, v.w);
        *(uint2*)&d_Abf[(size_t)j*4] = o;
    }
    int nP = BDIM*S*(DP/4);
    for (int j = blockIdx.x*256 + threadIdx.x; j < nP; j += stride) {
        float4 v = *(const float4*)(pos + (size_t)j*4);
        uint2 o; o.x = packbf(v.x, v.y); o.y = packbf(v.z, v.w);
        *(uint2*)&d_Pbf[(size_t)j*4] = o;
    }
}

// ---------------- masked weights (+ transposes, bf16 copies) + zero xbar ----------------
__global__ void mask_kernel(const float* __restrict__ Wq, const float* __restrict__ Wk,
                            const float* __restrict__ Wv, const float* __restrict__ WO,
                            const float* __restrict__ W_ih, const float* __restrict__ W_hh,
                            const float* __restrict__ Wka, const float* __restrict__ Wkp,
                            const int* __restrict__ G) {
    int i = blockIdx.x*256 + threadIdx.x;
    const int NW = HDIM*DK*DM;
    if (i < NW) {
        int h = i >> 15;
        int c = (i >> 9) & 63;
        int d = i & 511;
        float g = (float)G[c*64 + (d & 63)];
        d_WkMbf[i] = __float2bfloat16(Wk[i]*g);
        d_WqMT[((size_t)h*DM + d)*DK + c] = Wq[i]*g;
        d_WvMT[((size_t)h*DM + d)*DK + c] = Wv[i]*g;
    }
    if (i < HDIM*DAH*DA) d_Wkabf[i] = __float2bfloat16(Wka[i]);
    if (i < HDIM*DPH*DP) d_Wkpbf[i] = __float2bfloat16(Wkp[i]);
    if (i < DM*DM) {
        int j = i & 511, r = i >> 9;
        d_WOMT[(size_t)j*DM + r] = WO[i]*(float)G[(r & 63)*64 + (j & 63)];
    }
    if (i < 192*DM) {
        int j = i >> 9, d = i & 511;
        d_WihT[d*192 + j] = W_ih[i];
    }
    if (i < 192*DK) {
        int j = i >> 6, k = i & 63;
        d_WhhT[k*192 + j] = W_hh[i];
    }
    if (i < BDIM*HDIM*DM) d_xbar[i] = 0.f;
}

// ---------------- Qv: last M rows, masked proj + l2norm (fp32 math, bf16 out) ----------------
__global__ void qv_kernel(const float* __restrict__ memory, const float* __restrict__ x_pre,
                          const float* __restrict__ bq, int S) {
    int m = blockIdx.x & 31, h = (blockIdx.x >> 5) & 7, b = blockIdx.x >> 8;
    __shared__ float xs[DM];
    __shared__ float wp[2];
    int s = S - MDIM + m;
    const float* row = (s < S-1) ? memory + ((size_t)b*(S-1) + s)*DM : x_pre + (size_t)b*DM;
    for (int i = threadIdx.x; i < DM; i += 64) xs[i] = row[i];
    __syncthreads();
    int c = threadIdx.x;
    const float* wt = d_WqMT + (size_t)h*DM*DK;
    float acc = bq[h*DK + c];
    #pragma unroll 8
    for (int d = 0; d < DM; d++) acc += xs[d]*wt[d*DK + c];
    float v = acc*acc;
    for (int o = 16; o; o >>= 1) v += __shfl_xor_sync(0xffffffffu, v, o);
    if ((c & 31) == 0) wp[c >> 5] = v;
    __syncthreads();
    float inv = 1.f / fmaxf(sqrtf(wp[0] + wp[1]), 1e-12f);
    d_Qvbf[(((size_t)b*HDIM + h)*MDIM + m)*DK + c] = __float2bfloat16(acc*inv);
}

// ---------------- tensor-core projection (bf16 mma m16n8k16, cp.async double-buffered) ----------------
template<int DIN, int DOUT, int MODE>
__global__ void __launch_bounds__(256)
proj_mma_kernel(const __nv_bfloat16* __restrict__ src, const __nv_bfloat16* __restrict__ W,
                const float* __restrict__ bias, int S, int Wn) {
    constexpr int NW_N = 2;
    constexpr int TM   = 128;            // 4 m-warps * 32
    constexpr int WT_N = DOUT/NW_N;
    constexpr int NFN  = WT_N/8;
    constexpr int NCH  = DIN/32;
    constexpr int RS   = 20;             // 16 pairs + 4 pad (80B row = 5*16B, cp.async-aligned)

    __shared__ uint32_t Xs[2*TM*RS];
    __shared__ uint32_t Wss[2*DOUT*RS];
    __shared__ float bs_s[DOUT];
    __shared__ float qs_s[DOUT];
    __shared__ float red_s[TM*2];

    int tid = threadIdx.x;
    int lane = tid & 31, wid = tid >> 5;
    int g = lane >> 2, tig = lane & 3;
    int warp_n = wid % NW_N, warp_m = wid / NW_N;
    int rb = warp_m*32, cb = warp_n*WT_N;
    int s0 = blockIdx.x*TM, h = blockIdx.y, b = blockIdx.z;
    int bh = b*HDIM + h;

    uint32_t xB = (uint32_t)__cvta_generic_to_shared(Xs);
    uint32_t wB = (uint32_t)__cvta_generic_to_shared(Wss);

    for (int i = tid; i < DOUT; i += 256) {
        bs_s[i] = bias[h*DOUT + i];
        if (MODE == 1) qs_s[i] = d_QA[(size_t)bh*DAH + i];
        if (MODE == 2) qs_s[i] = d_QP[(size_t)bh*DPH + i];
    }

    auto load_chunk = [&](int ch, int buf) {
        int d0 = ch*32;
        #pragma unroll
        for (int e = tid; e < TM*4; e += 256) {
            int row = e >> 2, seg = e & 3;
            cpa16(xB + (buf*TM*RS + row*RS + seg*4)*4,
                  src + ((size_t)b*S + s0 + row)*DIN + d0 + seg*8);
        }
        for (int e = tid; e < DOUT*4; e += 256) {
            int rr = e >> 2, seg = e & 3;
            cpa16(wB + (buf*DOUT*RS + rr*RS + seg*4)*4,
                  W + ((size_t)(h*DOUT + rr))*DIN + d0 + seg*8);
        }
    };

    float acc[2][NFN][4];
    #pragma unroll
    for (int mi = 0; mi < 2; mi++)
        #pragma unroll
        for (int ni = 0; ni < NFN; ni++)
            #pragma unroll
            for (int q = 0; q < 4; q++) acc[mi][ni][q] = 0.f;

    load_chunk(0, 0);
    cpa_commit();

    for (int ch = 0; ch < NCH; ch++) {
        if (ch + 1 < NCH) {
            load_chunk(ch + 1, (ch + 1) & 1);
            cpa_commit();
            cpa_wait1();
        } else {
            cpa_wait0();
        }
        __syncthreads();
        const uint32_t* Xb = Xs + (ch & 1)*TM*RS;
        const uint32_t* Wb = Wss + (ch & 1)*DOUT*RS;
        #pragma unroll
        for (int ps = 0; ps < 2; ps++) {
            int p0 = ps*8;
            uint32_t a[2][4];
            #pragma unroll
            for (int mi = 0; mi < 2; mi++) {
                int r = rb + mi*16 + g;
                a[mi][0] = Xb[r*RS + p0 + tig];
                a[mi][1] = Xb[(r+8)*RS + p0 + tig];
                a[mi][2] = Xb[r*RS + p0 + tig + 4];
                a[mi][3] = Xb[(r+8)*RS + p0 + tig + 4];
            }
            #pragma unroll
            for (int ni = 0; ni < NFN; ni++) {
                int cn = cb + ni*8 + g;
                uint32_t b0 = Wb[cn*RS + p0 + tig];
                uint32_t b1 = Wb[cn*RS + p0 + tig + 4];
                #pragma unroll
                for (int mi = 0; mi < 2; mi++) mma_bf16(acc[mi][ni], a[mi], b0, b1);
            }
        }
        __syncthreads();
    }

    // ---- epilogue: bias + per-row l2 norm ----
    float sl[2] = {0.f, 0.f}, sh[2] = {0.f, 0.f};
    #pragma unroll
    for (int mi = 0; mi < 2; mi++)
        #pragma unroll
        for (int ni = 0; ni < NFN; ni++) {
            int c0 = cb + ni*8 + 2*tig, c1 = c0 + 1;
            acc[mi][ni][0] += bs_s[c0];
            acc[mi][ni][1] += bs_s[c1];
            acc[mi][ni][2] += bs_s[c0];
            acc[mi][ni][3] += bs_s[c1];
            sl[mi] += acc[mi][ni][0]*acc[mi][ni][0] + acc[mi][ni][1]*acc[mi][ni][1];
            sh[mi] += acc[mi][ni][2]*acc[mi][ni][2] + acc[mi][ni][3]*acc[mi][ni][3];
        }
    #pragma unroll
    for (int mi = 0; mi < 2; mi++) {
        sl[mi] += __shfl_xor_sync(0xffffffffu, sl[mi], 1);
        sl[mi] += __shfl_xor_sync(0xffffffffu, sl[mi], 2);
        sh[mi] += __shfl_xor_sync(0xffffffffu, sh[mi], 1);
        sh[mi] += __shfl_xor_sync(0xffffffffu, sh[mi], 2);
    }
    if (tig == 0) {
        #pragma unroll
        for (int mi = 0; mi < 2; mi++) {
            int rl = rb + mi*16 + g;
            red_s[rl*2 + warp_n] = sl[mi];
            red_s[(rl+8)*2 + warp_n] = sh[mi];
        }
    }
    __syncthreads();
    #pragma unroll
    for (int mi = 0; mi < 2; mi++) {
        int rl = rb + mi*16 + g;
        sl[mi] = red_s[rl*2] + red_s[rl*2+1];
        sh[mi] = red_s[(rl+8)*2] + red_s[(rl+8)*2+1];
    }
    float il[2], ih[2];
    #pragma unroll
    for (int mi = 0; mi < 2; mi++) {
        il[mi] = 1.f / fmaxf(sqrtf(sl[mi]), 1e-12f);
        ih[mi] = 1.f / fmaxf(sqrtf(sh[mi]), 1e-12f);
    }

    if (MODE == 0) {
        #pragma unroll
        for (int mi = 0; mi < 2; mi++) {
            int rl = rb + mi*16 + g;
            size_t base_l = ((size_t)bh*S + s0 + rl)*DK;
            size_t base_h = ((size_t)bh*S + s0 + rl + 8)*DK;
            #pragma unroll
            for (int ni = 0; ni < NFN; ni++) {
                int c0 = cb + ni*8 + 2*tig;
                *(uint32_t*)&d_Knbf[base_l + c0] = packbf(acc[mi][ni][0]*il[mi], acc[mi][ni][1]*il[mi]);
                *(uint32_t*)&d_Knbf[base_h + c0] = packbf(acc[mi][ni][2]*ih[mi], acc[mi][ni][3]*ih[mi]);
            }
        }
    } else {
        float* dst = (MODE == 1) ? d_dot2 : d_dot3;
        float dl[2], dh[2];
        #pragma unroll
        for (int mi = 0; mi < 2; mi++) {
            dl[mi] = 0.f; dh[mi] = 0.f;
            #pragma unroll
            for (int ni = 0; ni < NFN; ni++) {
                int c0 = cb + ni*8 + 2*tig, c1 = c0 + 1;
                dl[mi] += acc[mi][ni][0]*qs_s[c0] + acc[mi][ni][1]*qs_s[c1];
                dh[mi] += acc[mi][ni][2]*qs_s[c0] + acc[mi][ni][3]*qs_s[c1];
            }
            dl[mi] += __shfl_xor_sync(0xffffffffu, dl[mi], 1);
            dl[mi] += __shfl_xor_sync(0xffffffffu, dl[mi], 2);
            dh[mi] += __shfl_xor_sync(0xffffffffu, dh[mi], 1);
            dh[mi] += __shfl_xor_sync(0xffffffffu, dh[mi], 2);
        }
        __syncthreads();
        if (tig == 0) {
            #pragma unroll
            for (int mi = 0; mi < 2; mi++) {
                int rl = rb + mi*16 + g;
                red_s[rl*2 + warp_n] = dl[mi];
                red_s[(rl+8)*2 + warp_n] = dh[mi];
            }
        }
        __syncthreads();
        if (warp_n == 0 && tig == 0) {
            #pragma unroll
            for (int mi = 0; mi < 2; mi++) {
                int rl = rb + mi*16 + g;
                float DL = red_s[rl*2] + red_s[rl*2+1];
                float DH = red_s[(rl+8)*2] + red_s[(rl+8)*2+1];
                int wl = s0 + rl - 31, wh = wl + 8;
                if (wl >= 0 && wl < Wn) dst[(size_t)bh*S + wl] = DL*il[mi];
                if (wh >= 0 && wh < Wn) dst[(size_t)bh*S + wh] = DH*ih[mi];
            }
        }
    }
}

// ---------------- banded Qv . Kn -> tn  (bf16 mma) ----------------
__global__ void __launch_bounds__(128) band_mma_kernel(int S, int Wn) {
    constexpr int RS = 36;                 // 32 pairs + 4 pad (144B = 9*16B)
    __shared__ uint32_t Qs[32*RS];
    __shared__ uint32_t Ks[96*RS];
    __shared__ float Ps[32*100];
    int tid = threadIdx.x;
    int lane = tid & 31, wid = tid >> 5;
    int g = lane >> 2, tig = lane & 3;
    int w0 = blockIdx.x*64, h = blockIdx.y, b = blockIdx.z;
    int bh = b*HDIM + h;

    uint32_t qB = (uint32_t)__cvta_generic_to_shared(Qs);
    uint32_t kB = (uint32_t)__cvta_generic_to_shared(Ks);

    for (int e = tid; e < 96*8; e += 128) {
        int r = e >> 3, seg = e & 7;
        int s = w0 + r;
        if (s < S) cpa16(kB + (r*RS + seg*4)*4, d_Knbf + ((size_t)bh*S + s)*DK + seg*8);
        else {
            uint32_t* p = &Ks[r*RS + seg*4];
            p[0] = 0; p[1] = 0; p[2] = 0; p[3] = 0;
        }
    }
    for (int e = tid; e < 32*8; e += 128) {
        int r = e >> 3, seg = e & 7;
        cpa16(qB + (r*RS + seg*4)*4, d_Qvbf + ((size_t)bh*MDIM + r)*DK + seg*8);
    }
    cpa_commit();
    cpa_wait0();
    __syncthreads();

    float acc[2][3][4];
    #pragma unroll
    for (int mi = 0; mi < 2; mi++)
        #pragma unroll
        for (int ni = 0; ni < 3; ni++)
            #pragma unroll
            for (int q = 0; q < 4; q++) acc[mi][ni][q] = 0.f;
    int nb = wid*24;
    #pragma unroll
    for (int ks = 0; ks < 4; ks++) {
        int p0 = ks*8;
        uint32_t a[2][4];
        #pragma unroll
        for (int mi = 0; mi < 2; mi++) {
            int r = mi*16 + g;
            a[mi][0] = Qs[r*RS + p0 + tig];
            a[mi][1] = Qs[(r+8)*RS + p0 + tig];
            a[mi][2] = Qs[r*RS + p0 + tig + 4];
            a[mi][3] = Qs[(r+8)*RS + p0 + tig + 4];
        }
        #pragma unroll
        for (int ni = 0; ni < 3; ni++) {
            int cn = nb + ni*8 + g;
            uint32_t b0 = Ks[cn*RS + p0 + tig];
            uint32_t b1 = Ks[cn*RS + p0 + tig + 4];
            #pragma unroll
            for (int mi = 0; mi < 2; mi++) mma_bf16(acc[mi][ni], a[mi], b0, b1);
        }
    }
    #pragma unroll
    for (int mi = 0; mi < 2; mi++)
        #pragma unroll
        for (int ni = 0; ni < 3; ni++) {
            int c0 = nb + ni*8 + 2*tig;
            int r = mi*16 + g;
            Ps[r*100 + c0]     = acc[mi][ni][0];
            Ps[r*100 + c0 + 1] = acc[mi][ni][1];
            Ps[(r+8)*100 + c0]     = acc[mi][ni][2];
            Ps[(r+8)*100 + c0 + 1] = acc[mi][ni][3];
        }
    __syncthreads();
    if (tid < 64) {
        int w = w0 + tid;
        if (w < Wn) {
            float s = 0.f;
            #pragma unroll
            for (int m = 0; m < 32; m++) s += Ps[m*100 + tid + m];
            d_tn[(size_t)bh*S + w] = s*(1.f/32.f);
        }
    }
}

// ---------------- QA / QP (last-row queries, fp32) ----------------
__global__ void qa_kernel(const float* __restrict__ aux, const float* __restrict__ Wqa,
                          const float* __restrict__ bqa, int S) {
    int h = blockIdx.x & 7, b = blockIdx.x >> 3;
    int c = threadIdx.x;  // 32
    const float* ar = aux + ((size_t)b*S + (S-1))*DA;
    const float* wr = Wqa + ((size_t)h*DAH + c)*DA;
    float acc = bqa[h*DAH + c];
    #pragma unroll 4
    for (int d = 0; d < DA; d++) acc += ar[d]*wr[d];
    float v = acc*acc;
    for (int o = 16; o; o >>= 1) v += __shfl_xor_sync(0xffffffffu, v, o);
    float inv = 1.f / fmaxf(sqrtf(v), 1e-12f);
    d_QA[((size_t)b*HDIM + h)*DAH + c] = acc*inv;
}

__global__ void qp_kernel(const float* __restrict__ pos, const float* __restrict__ Wqp,
                          const float* __restrict__ bqp, int S) {
    int h = blockIdx.x & 7, b = blockIdx.x >> 3;
    int lane = threadIdx.x;   // 32
    int c = lane & 15;
    const float* pr = pos + ((size_t)b*S + (S-1))*DP;
    const float* wr = Wqp + ((size_t)h*DPH + c)*DP;
    float acc = bqp[h*DPH + c];
    #pragma unroll 4
    for (int d = 0; d < DP; d++) acc += pr[d]*wr[d];
    float v = acc*acc;
    for (int o = 8; o; o >>= 1) v += __shfl_xor_sync(0xffffffffu, v, o);
    float inv = 1.f / fmaxf(sqrtf(v), 1e-12f);
    if (lane < 16) d_QP[((size_t)b*HDIM + h)*DPH + c] = acc*inv;
}

// ---------------- softmax over Wn ----------------
__global__ void softmax_kernel(const float* __restrict__ w1, const float* __restrict__ w2,
                               const float* __restrict__ w3, int S, int Wn) {
    int bh = blockIdx.x, t = threadIdx.x;   // 256
    __shared__ float red[8];
    __shared__ float sval;
    float c1 = w1[0], c2 = w2[0], c3 = w3[0];
    size_t base = (size_t)bh*S;
    float mx = -1e30f;
    for (int i = t; i < Wn; i += 256) {
        float l = c1*d_tn[base+i] + c2*d_dot2[base+i] + c3*d_dot3[base+i];
        d_attn[base+i] = l;
        mx = fmaxf(mx, l);
    }
    for (int o = 16; o; o >>= 1) mx = fmaxf(mx, __shfl_xor_sync(0xffffffffu, mx, o));
    if ((t & 31) == 0) red[t >> 5] = mx;
    __syncthreads();
    if (t == 0) { float m = red[0]; for (int i = 1; i < 8; i++) m = fmaxf(m, red[i]); sval = m; }
    __syncthreads();
    float MX = sval, sum = 0.f;
    for (int i = t; i < Wn; i += 256) {
        float e = __expf(d_attn[base+i] - MX);
        d_attn[base+i] = e;
        sum += e;
    }
    for (int o = 16; o; o >>= 1) sum += __shfl_xor_sync(0xffffffffu, sum, o);
    __syncthreads();
    if ((t & 31) == 0) red[t >> 5] = sum;
    __syncthreads();
    if (t == 0) { float m = 0.f; for (int i = 0; i < 8; i++) m += red[i]; sval = m; }
    __syncthreads();
    float inv = 1.f / sval;
    for (int i = t; i < Wn; i += 256) {
        float a = d_attn[base+i]*inv;
        d_attn[base+i] = a;
        if (i == Wn-1) d_alast[bh] = a;
    }
}

// ---------------- xbar: attn-weighted row sums of x ----------------
__global__ void xbar_kernel(const float* __restrict__ memory, int S, int Wn) {
    __shared__ float a_s[8][64];
    int t = threadIdx.x;                 // 256
    int w0 = blockIdx.x*64, b = blockIdx.y;
    for (int i = t; i < 512; i += 256) {
        int hh = i >> 6, j = i & 63;
        int w = w0 + j;
        a_s[hh][j] = (w < Wn-1) ? d_attn[((size_t)b*HDIM + hh)*S + w] : 0.f;
    }
    __syncthreads();
    float acc[8][2];
    #pragma unroll
    for (int h = 0; h < 8; h++) { acc[h][0] = 0.f; acc[h][1] = 0.f; }
    int nrow = Wn - 1 - w0; if (nrow > 64) nrow = 64;
    for (int j = 0; j < nrow; j++) {
        size_t sr = (size_t)b*(S-1) + (31 + w0 + j);
        float x0 = memory[sr*DM + t];
        float x1 = memory[sr*DM + 256 + t];
        #pragma unroll
        for (int h = 0; h < 8; h++) {
            float a = a_s[h][j];
            acc[h][0] += a*x0;
            acc[h][1] += a*x1;
        }
    }
    #pragma unroll
    for (int h = 0; h < 8; h++) {
        atomicAdd(&d_xbar[((size_t)b*HDIM + h)*DM + t], acc[h][0]);
        atomicAdd(&d_xbar[((size_t)b*HDIM + h)*DM + 256 + t], acc[h][1]);
    }
}

// ---------------- GRU ----------------
__global__ void gi_kernel(const float* __restrict__ memory, const float* __restrict__ b_ih,
                          int S) {
    int tt = blockIdx.x, b = blockIdx.y;
    __shared__ float xs[DM];
    int s = S - MDIM + tt;
    const float* row = memory + ((size_t)b*(S-1) + s)*DM;
    for (int i = threadIdx.x; i < DM; i += 192) xs[i] = row[i];
    __syncthreads();
    int j = threadIdx.x;
    float acc = b_ih[j];
    #pragma unroll 8
    for (int d = 0; d < DM; d++) acc += xs[d]*d_WihT[d*192 + j];
    d_gi[((size_t)b*31 + tt)*192 + j] = acc;
}

__global__ void gru_kernel(const float* __restrict__ b_hh) {
    int b = blockIdx.x, j = threadIdx.x;  // 192
    __shared__ float hs[DK];
    __shared__ float gh_s[192];
    if (j < DK) hs[j] = 0.f;
    __syncthreads();
    float bh = b_hh[j];
    for (int t = 0; t < 31; t++) {
        float gh = bh;
        #pragma unroll 8
        for (int k2 = 0; k2 < DK; k2++) gh += hs[k2]*d_WhhT[k2*192 + j];
        gh_s[j] = gh;
        __syncthreads();
        float hn = 0.f;
        if (j < DK) {
            const float* gi = d_gi + ((size_t)b*31 + t)*192;
            float r = 1.f/(1.f + __expf(-(gi[j] + gh_s[j])));
            float z = 1.f/(1.f + __expf(-(gi[64 + j] + gh_s[64 + j])));
            float n = tanhf(gi[128 + j] + r*gh_s[128 + j]);
            hn = (1.f - z)*n + z*hs[j];
        }
        __syncthreads();
        if (j < DK) hs[j] = hn;
        __syncthreads();
    }
    if (j < DK) d_res[b*DK + j] = hs[j];
}

// ---------------- deta = xbar @ WvM^T + bv*(1-alast) + alast*res ----------------
__global__ void deta_kernel(const float* __restrict__ bv) {
    int bh = blockIdx.x;
    int b = bh >> 3, h = bh & 7;
    int c = threadIdx.x;                 // 64
    __shared__ float xb[DM];
    for (int i = c; i < DM; i += 64) xb[i] = d_xbar[(size_t)bh*DM + i];
    __syncthreads();
    const float* wt = d_WvMT + (size_t)h*DM*DK;
    float acc = 0.f;
    #pragma unroll 8
    for (int d = 0; d < DM; d++) acc += xb[d]*wt[d*DK + c];
    float al = d_alast[bh];
    d_deta[(size_t)b*DM + h*DK + c] = acc + bv[h*DK + c]*(1.f - al) + al*d_res[b*DK + c];
}

// ---------------- out = x_pre + deta @ WOM^T + bO ----------------
__global__ void out_kernel(const float* __restrict__ x_pre, const float* __restrict__ bO,
                           float* __restrict__ out) {
    int b = blockIdx.x, j = threadIdx.x;  // 512
    __shared__ float dd[DM];
    dd[j] = d_deta[(size_t)b*DM + j];
    __syncthreads();
    float acc = bO[j];
    #pragma unroll 8
    for (int i = 0; i < DM; i++) acc += dd[i]*d_WOMT[(size_t)i*DM + j];
    out[(size_t)b*DM + j] = x_pre[(size_t)b*DM + j] + acc;
}

extern "C" void kernel_launch(void* const* d_in, const int* in_sizes, int n_in,
                              void* d_out, int out_size) {
    const float* memory = (const float*)d_in[0];
    const float* x_pre  = (const float*)d_in[1];
    const float* aux    = (const float*)d_in[2];
    const float* pos    = (const float*)d_in[3];
    const float* Wq  = (const float*)d_in[4];
    const float* bq  = (const float*)d_in[5];
    const float* Wk  = (const float*)d_in[6];
    const float* bk  = (const float*)d_in[7];
    const float* Wv  = (const float*)d_in[8];
    const float* bv  = (const float*)d_in[9];
    const float* Wqa = (const float*)d_in[10];
    const float* bqa = (const float*)d_in[11];
    const float* Wka = (const float*)d_in[12];
    const float* bka = (const float*)d_in[13];
    const float* Wqp = (const float*)d_in[14];
    const float* bqp = (const float*)d_in[15];
    const float* Wkp = (const float*)d_in[16];
    const float* bkp = (const float*)d_in[17];
    const float* W_ih = (const float*)d_in[18];
    const float* W_hh = (const float*)d_in[19];
    const float* b_ih = (const float*)d_in[20];
    const float* b_hh = (const float*)d_in[21];
    const float* WO = (const float*)d_in[22];
    const float* bO = (const float*)d_in[23];
    const float* w   = (const float*)d_in[24];
    const float* w_a = (const float*)d_in[25];
    const float* w_p = (const float*)d_in[26];
    const int* G = (const int*)d_in[27];
    float* out = (float*)d_out;

    int S  = in_sizes[2] / (BDIM*DA);   // 6144
    int Wn = S - MDIM + 1;              // 6113

    __nv_bfloat16 *Xbf_p, *Abf_p, *Pbf_p, *WkMbf_p, *Wkabf_p, *Wkpbf_p;
    cudaGetSymbolAddress((void**)&Xbf_p, d_Xbf);
    cudaGetSymbolAddress((void**)&Abf_p, d_Abf);
    cudaGetSymbolAddress((void**)&Pbf_p, d_Pbf);
    cudaGetSymbolAddress((void**)&WkMbf_p, d_WkMbf);
    cudaGetSymbolAddress((void**)&Wkabf_p, d_Wkabf);
    cudaGetSymbolAddress((void**)&Wkpbf_p, d_Wkpbf);

    convert_kernel<<<4096, 256>>>(memory, x_pre, aux, pos, S);
    mask_kernel<<<1024, 256>>>(Wq, Wk, Wv, WO, W_ih, W_hh, Wka, Wkp, G);
    qv_kernel<<<BDIM*HDIM*MDIM, 64>>>(memory, x_pre, bq, S);
    proj_mma_kernel<DM, DK, 0><<<dim3(S/128, HDIM, BDIM), 256>>>(Xbf_p, WkMbf_p, bk, S, Wn);
    band_mma_kernel<<<dim3((Wn + 63)/64, HDIM, BDIM), 128>>>(S, Wn);
    qa_kernel<<<BDIM*HDIM, 32>>>(aux, Wqa, bqa, S);
    proj_mma_kernel<DA, DAH, 1><<<dim3(S/128, HDIM, BDIM), 256>>>(Abf_p, Wkabf_p, bka, S, Wn);
    qp_kernel<<<BDIM*HDIM, 32>>>(pos, Wqp, bqp, S);
    proj_mma_kernel<DP, DPH, 2><<<dim3(S/128, HDIM, BDIM), 256>>>(Pbf_p, Wkpbf_p, bkp, S, Wn);
    softmax_kernel<<<BDIM*HDIM, 256>>>(w, w_a, w_p, S, Wn);
    xbar_kernel<<<dim3((Wn - 1 + 63)/64, BDIM), 256>>>(memory, S, Wn);
    gi_kernel<<<dim3(31, BDIM), 192>>>(memory, b_ih, S);
    gru_kernel<<<BDIM, 192>>>(b_hh);
    deta_kernel<<<BDIM*HDIM, 64>>>(bv);
    out_kernel<<<BDIM, 512>>>(x_pre, bO, out);
}

// round 11
// speedup vs baseline: 2.2080x; 1.0453x over previous
#include <cuda_runtime.h>
#include <cuda_bf16.h>
#include <math.h>
#include <stdint.h>
#include <stddef.h>

// fixed problem shapes
#define BDIM 8
#define HDIM 8
#define DM 512
#define DA 256
#define DP 128
#define MDIM 32
#define DK 64
#define DAH 32
#define DPH 16
#define SDIM 6144

// ---------------- device scratch ----------------
__device__ __nv_bfloat16 d_Xbf[(size_t)BDIM*SDIM*DM];
__device__ __nv_bfloat16 d_Abf[(size_t)BDIM*SDIM*DA];
__device__ __nv_bfloat16 d_Pbf[(size_t)BDIM*SDIM*DP];
__device__ __nv_bfloat16 d_WkMbf[HDIM*DK*DM];
__device__ __nv_bfloat16 d_Wkabf[HDIM*DAH*DA];
__device__ __nv_bfloat16 d_Wkpbf[HDIM*DPH*DP];
__device__ float d_WqMT[HDIM*DM*DK];   // [h][d][c]
__device__ float d_WvMT[HDIM*DM*DK];   // [h][d][c]
__device__ float d_WOMT[DM*DM];        // [i][j] = WOM[j][i]
__device__ float d_WihT[DM*192];       // [d][j]
__device__ float d_WhhT[DK*192];       // [k][j]
__device__ __nv_bfloat16 d_Knbf[(size_t)BDIM*HDIM*SDIM*DK];  // ~50 MB
__device__ __nv_bfloat16 d_Qvbf[BDIM*HDIM*MDIM*DK];
__device__ float d_QA[BDIM*HDIM*DAH];
__device__ float d_QP[BDIM*HDIM*DPH];
__device__ float d_tn[BDIM*HDIM*SDIM];
__device__ float d_dot2[BDIM*HDIM*SDIM];
__device__ float d_dot3[BDIM*HDIM*SDIM];
__device__ float d_attn[BDIM*HDIM*SDIM];
__device__ float d_alast[BDIM*HDIM];
__device__ float d_xbar[BDIM*HDIM*DM];
__device__ float d_gi[BDIM*31*192];
__device__ float d_res[BDIM*DK];
__device__ float d_deta[BDIM*DM];

__device__ __forceinline__ void mma_bf16(float* c, const uint32_t* a, uint32_t b0, uint32_t b1) {
    asm volatile("mma.sync.aligned.m16n8k16.row.col.f32.bf16.bf16.f32 "
        "{%0,%1,%2,%3}, {%4,%5,%6,%7}, {%8,%9}, {%0,%1,%2,%3};\n"
        : "+f"(c[0]), "+f"(c[1]), "+f"(c[2]), "+f"(c[3])
        : "r"(a[0]), "r"(a[1]), "r"(a[2]), "r"(a[3]), "r"(b0), "r"(b1));
}

__device__ __forceinline__ void ldsm_x4(uint32_t* r, uint32_t addr) {
    asm volatile("ldmatrix.sync.aligned.m8n8.x4.shared.b16 {%0,%1,%2,%3}, [%4];"
        : "=r"(r[0]), "=r"(r[1]), "=r"(r[2]), "=r"(r[3]) : "r"(addr));
}
__device__ __forceinline__ void ldsm_x2(uint32_t* r, uint32_t addr) {
    asm volatile("ldmatrix.sync.aligned.m8n8.x2.shared.b16 {%0,%1}, [%2];"
        : "=r"(r[0]), "=r"(r[1]) : "r"(addr));
}

__device__ __forceinline__ void cpa16(uint32_t saddr, const void* g) {
    asm volatile("cp.async.cg.shared.global [%0], [%1], 16;" :: "r"(saddr), "l"(g));
}
__device__ __forceinline__ void cpa_commit() { asm volatile("cp.async.commit_group;"); }
__device__ __forceinline__ void cpa_wait0() { asm volatile("cp.async.wait_group 0;" ::: "memory"); }

__device__ __forceinline__ uint32_t packbf(float a, float b) {
    __nv_bfloat162 t = __floats2bfloat162_rn(a, b);
    return *(uint32_t*)&t;
}

// ---------------- fp32 -> bf16 conversion of activations ----------------
__global__ void convert_kernel(const float* __restrict__ memory, const float* __restrict__ x_pre,
                               const float* __restrict__ aux, const float* __restrict__ pos,
                               int S) {
    int stride = gridDim.x*256;
    int nX = BDIM*S*(DM/4);
    for (int j = blockIdx.x*256 + threadIdx.x; j < nX; j += stride) {
        int b = j / (S*(DM/4));
        int r = j % (S*(DM/4));
        int s = r / (DM/4);
        int d4 = (r % (DM/4))*4;
        const float* src = (s < S-1) ? memory + ((size_t)b*(S-1) + s)*DM + d4
                                     : x_pre + (size_t)b*DM + d4;
        float4 v = *(const float4*)src;
        uint2 o; o.x = packbf(v.x, v.y); o.y = packbf(v.z, v.w);
        *(uint2*)&d_Xbf[((size_t)b*S + s)*DM + d4] = o;
    }
    int nA = BDIM*S*(DA/4);
    for (int j = blockIdx.x*256 + threadIdx.x; j < nA; j += stride) {
        float4 v = *(const float4*)(aux + (size_t)j*4);
        uint2 o; o.x = packbf(v.x, v.y); o.y = packbf(v.z, v.w);
        *(uint2*)&d_Abf[(size_t)j*4] = o;
    }
    int nP = BDIM*S*(DP/4);
    for (int j = blockIdx.x*256 + threadIdx.x; j < nP; j += stride) {
        float4 v = *(const float4*)(pos + (size_t)j*4);
        uint2 o; o.x = packbf(v.x, v.y); o.y = packbf(v.z, v.w);
        *(uint2*)&d_Pbf[(size_t)j*4] = o;
    }
}

// ---------------- masked weights (+ transposes, bf16 copies) + zero xbar ----------------
__global__ void mask_kernel(const float* __restrict__ Wq, const float* __restrict__ Wk,
                            const float* __restrict__ Wv, const float* __restrict__ WO,
                            const float* __restrict__ W_ih, const float* __restrict__ W_hh,
                            const float* __restrict__ Wka, const float* __restrict__ Wkp,
                            const int* __restrict__ G) {
    int i = blockIdx.x*256 + threadIdx.x;
    const int NW = HDIM*DK*DM;
    if (i < NW) {
        int h = i >> 15;
        int c = (i >> 9) & 63;
        int d = i & 511;
        float g = (float)G[c*64 + (d & 63)];
        d_WkMbf[i] = __float2bfloat16(Wk[i]*g);
        d_WqMT[((size_t)h*DM + d)*DK + c] = Wq[i]*g;
        d_WvMT[((size_t)h*DM + d)*DK + c] = Wv[i]*g;
    }
    if (i < HDIM*DAH*DA) d_Wkabf[i] = __float2bfloat16(Wka[i]);
    if (i < HDIM*DPH*DP) d_Wkpbf[i] = __float2bfloat16(Wkp[i]);
    if (i < DM*DM) {
        int j = i & 511, r = i >> 9;
        d_WOMT[(size_t)j*DM + r] = WO[i]*(float)G[(r & 63)*64 + (j & 63)];
    }
    if (i < 192*DM) {
        int j = i >> 9, d = i & 511;
        d_WihT[d*192 + j] = W_ih[i];
    }
    if (i < 192*DK) {
        int j = i >> 6, k = i & 63;
        d_WhhT[k*192 + j] = W_hh[i];
    }
    if (i < BDIM*HDIM*DM) d_xbar[i] = 0.f;
}

// ---------------- Qv: last M rows, masked proj + l2norm (fp32 math, bf16 out) ----------------
__global__ void qv_kernel(const float* __restrict__ memory, const float* __restrict__ x_pre,
                          const float* __restrict__ bq, int S) {
    int m = blockIdx.x & 31, h = (blockIdx.x >> 5) & 7, b = blockIdx.x >> 8;
    __shared__ float xs[DM];
    __shared__ float wp[2];
    int s = S - MDIM + m;
    const float* row = (s < S-1) ? memory + ((size_t)b*(S-1) + s)*DM : x_pre + (size_t)b*DM;
    for (int i = threadIdx.x; i < DM; i += 64) xs[i] = row[i];
    __syncthreads();
    int c = threadIdx.x;
    const float* wt = d_WqMT + (size_t)h*DM*DK;
    float acc = bq[h*DK + c];
    #pragma unroll 8
    for (int d = 0; d < DM; d++) acc += xs[d]*wt[d*DK + c];
    float v = acc*acc;
    for (int o = 16; o; o >>= 1) v += __shfl_xor_sync(0xffffffffu, v, o);
    if ((c & 31) == 0) wp[c >> 5] = v;
    __syncthreads();
    float inv = 1.f / fmaxf(sqrtf(wp[0] + wp[1]), 1e-12f);
    d_Qvbf[(((size_t)b*HDIM + h)*MDIM + m)*DK + c] = __float2bfloat16(acc*inv);
}

// ---------------- tensor-core projection (bf16 mma + ldmatrix, k-chunk 64, single buffer) ----------------
template<int DIN, int DOUT, int MODE>
__global__ void __launch_bounds__(256)
proj_mma_kernel(const __nv_bfloat16* __restrict__ src, const __nv_bfloat16* __restrict__ W,
                const float* __restrict__ bias, int S, int Wn) {
    constexpr int NW_N = 2;
    constexpr int TM   = 128;            // 4 m-warps * 32
    constexpr int WT_N = DOUT/NW_N;
    constexpr int NFN  = WT_N/8;         // 4 / 2 / 1
    constexpr int NCH  = DIN/64;
    constexpr int RS   = 36;             // 32 pairs + 4 pad (144B = 9*16B)

    __shared__ uint32_t Xs[TM*RS];
    __shared__ uint32_t Wss[DOUT*RS];
    __shared__ float bs_s[DOUT];
    __shared__ float qs_s[DOUT];
    __shared__ float red_s[TM*2];

    int tid = threadIdx.x;
    int lane = tid & 31, wid = tid >> 5;
    int g = lane >> 2, tig = lane & 3;
    int warp_n = wid % NW_N, warp_m = wid / NW_N;
    int rb = warp_m*32, cb = warp_n*WT_N;
    int s0 = blockIdx.x*TM, h = blockIdx.y, b = blockIdx.z;
    int bh = b*HDIM + h;

    uint32_t xB = (uint32_t)__cvta_generic_to_shared(Xs);
    uint32_t wB = (uint32_t)__cvta_generic_to_shared(Wss);

    // ldmatrix lane addresses (bytes), add ps*32 per k16-step
    uint32_t aAddr[2];
    #pragma unroll
    for (int mi = 0; mi < 2; mi++)
        aAddr[mi] = xB + ((rb + mi*16 + (lane & 7) + (lane & 8))*RS + ((lane >> 4) & 1)*4)*4;
    uint32_t bAddr[(NFN + 1)/2];
    #pragma unroll
    for (int pg = 0; pg < (NFN + 1)/2; pg++) {
        if (NFN == 1)
            bAddr[pg] = wB + ((cb + (lane & 7))*RS + ((lane >> 3) & 1)*4)*4;
        else
            bAddr[pg] = wB + ((cb + pg*16 + ((lane >> 4) & 1)*8 + (lane & 7))*RS + ((lane >> 3) & 1)*4)*4;
    }

    for (int i = tid; i < DOUT; i += 256) {
        bs_s[i] = bias[h*DOUT + i];
        if (MODE == 1) qs_s[i] = d_QA[(size_t)bh*DAH + i];
        if (MODE == 2) qs_s[i] = d_QP[(size_t)bh*DPH + i];
    }

    float acc[2][NFN][4];
    #pragma unroll
    for (int mi = 0; mi < 2; mi++)
        #pragma unroll
        for (int ni = 0; ni < NFN; ni++)
            #pragma unroll
            for (int q = 0; q < 4; q++) acc[mi][ni][q] = 0.f;

    for (int ch = 0; ch < NCH; ch++) {
        int d0 = ch*64;
        // stage X tile (TM x 64 bf16): 8 segs of 16B per row
        #pragma unroll
        for (int it = 0; it < TM*8/256; it++) {
            int e = it*256 + tid;
            int row = e >> 3, seg = e & 7;
            cpa16(xB + (row*RS + seg*4)*4, src + ((size_t)b*S + s0 + row)*DIN + d0 + seg*8);
        }
        for (int e = tid; e < DOUT*8; e += 256) {
            int rr = e >> 3, seg = e & 7;
            cpa16(wB + (rr*RS + seg*4)*4, W + ((size_t)(h*DOUT + rr))*DIN + d0 + seg*8);
        }
        cpa_commit();
        cpa_wait0();
        __syncthreads();
        #pragma unroll
        for (int ps = 0; ps < 4; ps++) {
            uint32_t a[2][4];
            ldsm_x4(a[0], aAddr[0] + ps*32);
            ldsm_x4(a[1], aAddr[1] + ps*32);
            uint32_t bb[2*NFN];
            if (NFN == 1) {
                ldsm_x2(bb, bAddr[0] + ps*32);
            } else {
                #pragma unroll
                for (int pg = 0; pg < NFN/2; pg++)
                    ldsm_x4(bb + pg*4, bAddr[pg] + ps*32);
            }
            #pragma unroll
            for (int ni = 0; ni < NFN; ni++) {
                uint32_t b0 = bb[2*ni], b1 = bb[2*ni + 1];
                #pragma unroll
                for (int mi = 0; mi < 2; mi++) mma_bf16(acc[mi][ni], a[mi], b0, b1);
            }
        }
        __syncthreads();
    }

    // ---- epilogue: bias + per-row l2 norm ----
    float sl[2] = {0.f, 0.f}, sh[2] = {0.f, 0.f};
    #pragma unroll
    for (int mi = 0; mi < 2; mi++)
        #pragma unroll
        for (int ni = 0; ni < NFN; ni++) {
            int c0 = cb + ni*8 + 2*tig, c1 = c0 + 1;
            acc[mi][ni][0] += bs_s[c0];
            acc[mi][ni][1] += bs_s[c1];
            acc[mi][ni][2] += bs_s[c0];
            acc[mi][ni][3] += bs_s[c1];
            sl[mi] += acc[mi][ni][0]*acc[mi][ni][0] + acc[mi][ni][1]*acc[mi][ni][1];
            sh[mi] += acc[mi][ni][2]*acc[mi][ni][2] + acc[mi][ni][3]*acc[mi][ni][3];
        }
    #pragma unroll
    for (int mi = 0; mi < 2; mi++) {
        sl[mi] += __shfl_xor_sync(0xffffffffu, sl[mi], 1);
        sl[mi] += __shfl_xor_sync(0xffffffffu, sl[mi], 2);
        sh[mi] += __shfl_xor_sync(0xffffffffu, sh[mi], 1);
        sh[mi] += __shfl_xor_sync(0xffffffffu, sh[mi], 2);
    }
    if (tig == 0) {
        #pragma unroll
        for (int mi = 0; mi < 2; mi++) {
            int rl = rb + mi*16 + g;
            red_s[rl*2 + warp_n] = sl[mi];
            red_s[(rl+8)*2 + warp_n] = sh[mi];
        }
    }
    __syncthreads();
    #pragma unroll
    for (int mi = 0; mi < 2; mi++) {
        int rl = rb + mi*16 + g;
        sl[mi] = red_s[rl*2] + red_s[rl*2+1];
        sh[mi] = red_s[(rl+8)*2] + red_s[(rl+8)*2+1];
    }
    float il[2], ih[2];
    #pragma unroll
    for (int mi = 0; mi < 2; mi++) {
        il[mi] = 1.f / fmaxf(sqrtf(sl[mi]), 1e-12f);
        ih[mi] = 1.f / fmaxf(sqrtf(sh[mi]), 1e-12f);
    }

    if (MODE == 0) {
        #pragma unroll
        for (int mi = 0; mi < 2; mi++) {
            int rl = rb + mi*16 + g;
            size_t base_l = ((size_t)bh*S + s0 + rl)*DK;
            size_t base_h = ((size_t)bh*S + s0 + rl + 8)*DK;
            #pragma unroll
            for (int ni = 0; ni < NFN; ni++) {
                int c0 = cb + ni*8 + 2*tig;
                *(uint32_t*)&d_Knbf[base_l + c0] = packbf(acc[mi][ni][0]*il[mi], acc[mi][ni][1]*il[mi]);
                *(uint32_t*)&d_Knbf[base_h + c0] = packbf(acc[mi][ni][2]*ih[mi], acc[mi][ni][3]*ih[mi]);
            }
        }
    } else {
        float* dst = (MODE == 1) ? d_dot2 : d_dot3;
        float dl[2], dh[2];
        #pragma unroll
        for (int mi = 0; mi < 2; mi++) {
            dl[mi] = 0.f; dh[mi] = 0.f;
            #pragma unroll
            for (int ni = 0; ni < NFN; ni++) {
                int c0 = cb + ni*8 + 2*tig, c1 = c0 + 1;
                dl[mi] += acc[mi][ni][0]*qs_s[c0] + acc[mi][ni][1]*qs_s[c1];
                dh[mi] += acc[mi][ni][2]*qs_s[c0] + acc[mi][ni][3]*qs_s[c1];
            }
            dl[mi] += __shfl_xor_sync(0xffffffffu, dl[mi], 1);
            dl[mi] += __shfl_xor_sync(0xffffffffu, dl[mi], 2);
            dh[mi] += __shfl_xor_sync(0xffffffffu, dh[mi], 1);
            dh[mi] += __shfl_xor_sync(0xffffffffu, dh[mi], 2);
        }
        __syncthreads();
        if (tig == 0) {
            #pragma unroll
            for (int mi = 0; mi < 2; mi++) {
                int rl = rb + mi*16 + g;
                red_s[rl*2 + warp_n] = dl[mi];
                red_s[(rl+8)*2 + warp_n] = dh[mi];
            }
        }
        __syncthreads();
        if (warp_n == 0 && tig == 0) {
            #pragma unroll
            for (int mi = 0; mi < 2; mi++) {
                int rl = rb + mi*16 + g;
                float DL = red_s[rl*2] + red_s[rl*2+1];
                float DH = red_s[(rl+8)*2] + red_s[(rl+8)*2+1];
                int wl = s0 + rl - 31, wh = wl + 8;
                if (wl >= 0 && wl < Wn) dst[(size_t)bh*S + wl] = DL*il[mi];
                if (wh >= 0 && wh < Wn) dst[(size_t)bh*S + wh] = DH*ih[mi];
            }
        }
    }
}

// ---------------- banded Qv . Kn -> tn  (bf16 mma) ----------------
__global__ void __launch_bounds__(128) band_mma_kernel(int S, int Wn) {
    constexpr int RS = 36;
    __shared__ uint32_t Qs[32*RS];
    __shared__ uint32_t Ks[96*RS];
    __shared__ float Ps[32*100];
    int tid = threadIdx.x;
    int lane = tid & 31, wid = tid >> 5;
    int g = lane >> 2, tig = lane & 3;
    int w0 = blockIdx.x*64, h = blockIdx.y, b = blockIdx.z;
    int bh = b*HDIM + h;

    uint32_t qB = (uint32_t)__cvta_generic_to_shared(Qs);
    uint32_t kB = (uint32_t)__cvta_generic_to_shared(Ks);

    for (int e = tid; e < 96*8; e += 128) {
        int r = e >> 3, seg = e & 7;
        int s = w0 + r;
        if (s < S) cpa16(kB + (r*RS + seg*4)*4, d_Knbf + ((size_t)bh*S + s)*DK + seg*8);
        else {
            uint32_t* p = &Ks[r*RS + seg*4];
            p[0] = 0; p[1] = 0; p[2] = 0; p[3] = 0;
        }
    }
    for (int e = tid; e < 32*8; e += 128) {
        int r = e >> 3, seg = e & 7;
        cpa16(qB + (r*RS + seg*4)*4, d_Qvbf + ((size_t)bh*MDIM + r)*DK + seg*8);
    }
    cpa_commit();
    cpa_wait0();
    __syncthreads();

    float acc[2][3][4];
    #pragma unroll
    for (int mi = 0; mi < 2; mi++)
        #pragma unroll
        for (int ni = 0; ni < 3; ni++)
            #pragma unroll
            for (int q = 0; q < 4; q++) acc[mi][ni][q] = 0.f;
    int nb = wid*24;
    #pragma unroll
    for (int ks = 0; ks < 4; ks++) {
        int p0 = ks*8;
        uint32_t a[2][4];
        #pragma unroll
        for (int mi = 0; mi < 2; mi++) {
            int r = mi*16 + g;
            a[mi][0] = Qs[r*RS + p0 + tig];
            a[mi][1] = Qs[(r+8)*RS + p0 + tig];
            a[mi][2] = Qs[r*RS + p0 + tig + 4];
            a[mi][3] = Qs[(r+8)*RS + p0 + tig + 4];
        }
        #pragma unroll
        for (int ni = 0; ni < 3; ni++) {
            int cn = nb + ni*8 + g;
            uint32_t b0 = Ks[cn*RS + p0 + tig];
            uint32_t b1 = Ks[cn*RS + p0 + tig + 4];
            #pragma unroll
            for (int mi = 0; mi < 2; mi++) mma_bf16(acc[mi][ni], a[mi], b0, b1);
        }
    }
    #pragma unroll
    for (int mi = 0; mi < 2; mi++)
        #pragma unroll
        for (int ni = 0; ni < 3; ni++) {
            int c0 = nb + ni*8 + 2*tig;
            int r = mi*16 + g;
            Ps[r*100 + c0]     = acc[mi][ni][0];
            Ps[r*100 + c0 + 1] = acc[mi][ni][1];
            Ps[(r+8)*100 + c0]     = acc[mi][ni][2];
            Ps[(r+8)*100 + c0 + 1] = acc[mi][ni][3];
        }
    __syncthreads();
    if (tid < 64) {
        int w = w0 + tid;
        if (w < Wn) {
            float s = 0.f;
            #pragma unroll
            for (int m = 0; m < 32; m++) s += Ps[m*100 + tid + m];
            d_tn[(size_t)bh*S + w] = s*(1.f/32.f);
        }
    }
}

// ---------------- QA / QP (last-row queries, fp32) ----------------
__global__ void qa_kernel(const float* __restrict__ aux, const float* __restrict__ Wqa,
                          const float* __restrict__ bqa, int S) {
    int h = blockIdx.x & 7, b = blockIdx.x >> 3;
    int c = threadIdx.x;  // 32
    const float* ar = aux + ((size_t)b*S + (S-1))*DA;
    const float* wr = Wqa + ((size_t)h*DAH + c)*DA;
    float acc = bqa[h*DAH + c];
    #pragma unroll 4
    for (int d = 0; d < DA; d++) acc += ar[d]*wr[d];
    float v = acc*acc;
    for (int o = 16; o; o >>= 1) v += __shfl_xor_sync(0xffffffffu, v, o);
    float inv = 1.f / fmaxf(sqrtf(v), 1e-12f);
    d_QA[((size_t)b*HDIM + h)*DAH + c] = acc*inv;
}

__global__ void qp_kernel(const float* __restrict__ pos, const float* __restrict__ Wqp,
                          const float* __restrict__ bqp, int S) {
    int h = blockIdx.x & 7, b = blockIdx.x >> 3;
    int lane = threadIdx.x;   // 32
    int c = lane & 15;
    const float* pr = pos + ((size_t)b*S + (S-1))*DP;
    const float* wr = Wqp + ((size_t)h*DPH + c)*DP;
    float acc = bqp[h*DPH + c];
    #pragma unroll 4
    for (int d = 0; d < DP; d++) acc += pr[d]*wr[d];
    float v = acc*acc;
    for (int o = 8; o; o >>= 1) v += __shfl_xor_sync(0xffffffffu, v, o);
    float inv = 1.f / fmaxf(sqrtf(v), 1e-12f);
    if (lane < 16) d_QP[((size_t)b*HDIM + h)*DPH + c] = acc*inv;
}

// ---------------- softmax over Wn ----------------
__global__ void softmax_kernel(const float* __restrict__ w1, const float* __restrict__ w2,
                               const float* __restrict__ w3, int S, int Wn) {
    int bh = blockIdx.x, t = threadIdx.x;   // 256
    __shared__ float red[8];
    __shared__ float sval;
    float c1 = w1[0], c2 = w2[0], c3 = w3[0];
    size_t base = (size_t)bh*S;
    float mx = -1e30f;
    for (int i = t; i < Wn; i += 256) {
        float l = c1*d_tn[base+i] + c2*d_dot2[base+i] + c3*d_dot3[base+i];
        d_attn[base+i] = l;
        mx = fmaxf(mx, l);
    }
    for (int o = 16; o; o >>= 1) mx = fmaxf(mx, __shfl_xor_sync(0xffffffffu, mx, o));
    if ((t & 31) == 0) red[t >> 5] = mx;
    __syncthreads();
    if (t == 0) { float m = red[0]; for (int i = 1; i < 8; i++) m = fmaxf(m, red[i]); sval = m; }
    __syncthreads();
    float MX = sval, sum = 0.f;
    for (int i = t; i < Wn; i += 256) {
        float e = __expf(d_attn[base+i] - MX);
        d_attn[base+i] = e;
        sum += e;
    }
    for (int o = 16; o; o >>= 1) sum += __shfl_xor_sync(0xffffffffu, sum, o);
    __syncthreads();
    if ((t & 31) == 0) red[t >> 5] = sum;
    __syncthreads();
    if (t == 0) { float m = 0.f; for (int i = 0; i < 8; i++) m += red[i]; sval = m; }
    __syncthreads();
    float inv = 1.f / sval;
    for (int i = t; i < Wn; i += 256) {
        float a = d_attn[base+i]*inv;
        d_attn[base+i] = a;
        if (i == Wn-1) d_alast[bh] = a;
    }
}

// ---------------- xbar: attn-weighted row sums of x (bf16 X) ----------------
__global__ void xbar_kernel(int S, int Wn) {
    __shared__ float a_s[8][64];
    int t = threadIdx.x;                 // 256
    int w0 = blockIdx.x*64, b = blockIdx.y;
    for (int i = t; i < 512; i += 256) {
        int hh = i >> 6, j = i & 63;
        int w = w0 + j;
        a_s[hh][j] = (w < Wn-1) ? d_attn[((size_t)b*HDIM + hh)*S + w] : 0.f;
    }
    __syncthreads();
    float acc[8][2];
    #pragma unroll
    for (int h = 0; h < 8; h++) { acc[h][0] = 0.f; acc[h][1] = 0.f; }
    int nrow = Wn - 1 - w0; if (nrow > 64) nrow = 64;
    for (int j = 0; j < nrow; j++) {
        const __nv_bfloat16* xr = d_Xbf + ((size_t)b*S + (31 + w0 + j))*DM;
        float x0 = __bfloat162float(xr[t]);
        float x1 = __bfloat162float(xr[256 + t]);
        #pragma unroll
        for (int h = 0; h < 8; h++) {
            float a = a_s[h][j];
            acc[h][0] += a*x0;
            acc[h][1] += a*x1;
        }
    }
    #pragma unroll
    for (int h = 0; h < 8; h++) {
        atomicAdd(&d_xbar[((size_t)b*HDIM + h)*DM + t], acc[h][0]);
        atomicAdd(&d_xbar[((size_t)b*HDIM + h)*DM + 256 + t], acc[h][1]);
    }
}

// ---------------- GRU ----------------
__global__ void gi_kernel(const float* __restrict__ memory, const float* __restrict__ b_ih,
                          int S) {
    int tt = blockIdx.x, b = blockIdx.y;
    __shared__ float xs[DM];
    int s = S - MDIM + tt;
    const float* row = memory + ((size_t)b*(S-1) + s)*DM;
    for (int i = threadIdx.x; i < DM; i += 192) xs[i] = row[i];
    __syncthreads();
    int j = threadIdx.x;
    float acc = b_ih[j];
    #pragma unroll 8
    for (int d = 0; d < DM; d++) acc += xs[d]*d_WihT[d*192 + j];
    d_gi[((size_t)b*31 + tt)*192 + j] = acc;
}

__global__ void gru_kernel(const float* __restrict__ b_hh) {
    int b = blockIdx.x, j = threadIdx.x;  // 192
    __shared__ float hs[DK];
    __shared__ float gh_s[192];
    if (j < DK) hs[j] = 0.f;
    __syncthreads();
    float bh = b_hh[j];
    for (int t = 0; t < 31; t++) {
        float gh = bh;
        #pragma unroll 8
        for (int k2 = 0; k2 < DK; k2++) gh += hs[k2]*d_WhhT[k2*192 + j];
        gh_s[j] = gh;
        __syncthreads();
        float hn = 0.f;
        if (j < DK) {
            const float* gi = d_gi + ((size_t)b*31 + t)*192;
            float r = 1.f/(1.f + __expf(-(gi[j] + gh_s[j])));
            float z = 1.f/(1.f + __expf(-(gi[64 + j] + gh_s[64 + j])));
            float n = tanhf(gi[128 + j] + r*gh_s[128 + j]);
            hn = (1.f - z)*n + z*hs[j];
        }
        __syncthreads();
        if (j < DK) hs[j] = hn;
        __syncthreads();
    }
    if (j < DK) d_res[b*DK + j] = hs[j];
}

// ---------------- deta = xbar @ WvM^T + bv*(1-alast) + alast*res ----------------
__global__ void deta_kernel(const float* __restrict__ bv) {
    int bh = blockIdx.x;
    int b = bh >> 3, h = bh & 7;
    int c = threadIdx.x;                 // 64
    __shared__ float xb[DM];
    for (int i = c; i < DM; i += 64) xb[i] = d_xbar[(size_t)bh*DM + i];
    __syncthreads();
    const float* wt = d_WvMT + (size_t)h*DM*DK;
    float acc = 0.f;
    #pragma unroll 8
    for (int d = 0; d < DM; d++) acc += xb[d]*wt[d*DK + c];
    float al = d_alast[bh];
    d_deta[(size_t)b*DM + h*DK + c] = acc + bv[h*DK + c]*(1.f - al) + al*d_res[b*DK + c];
}

// ---------------- out = x_pre + deta @ WOM^T + bO ----------------
__global__ void out_kernel(const float* __restrict__ x_pre, const float* __restrict__ bO,
                           float* __restrict__ out) {
    int b = blockIdx.x, j = threadIdx.x;  // 512
    __shared__ float dd[DM];
    dd[j] = d_deta[(size_t)b*DM + j];
    __syncthreads();
    float acc = bO[j];
    #pragma unroll 8
    for (int i = 0; i < DM; i++) acc += dd[i]*d_WOMT[(size_t)i*DM + j];
    out[(size_t)b*DM + j] = x_pre[(size_t)b*DM + j] + acc;
}

extern "C" void kernel_launch(void* const* d_in, const int* in_sizes, int n_in,
                              void* d_out, int out_size) {
    const float* memory = (const float*)d_in[0];
    const float* x_pre  = (const float*)d_in[1];
    const float* aux    = (const float*)d_in[2];
    const float* pos    = (const float*)d_in[3];
    const float* Wq  = (const float*)d_in[4];
    const float* bq  = (const float*)d_in[5];
    const float* Wk  = (const float*)d_in[6];
    const float* bk  = (const float*)d_in[7];
    const float* Wv  = (const float*)d_in[8];
    const float* bv  = (const float*)d_in[9];
    const float* Wqa = (const float*)d_in[10];
    const float* bqa = (const float*)d_in[11];
    const float* Wka = (const float*)d_in[12];
    const float* bka = (const float*)d_in[13];
    const float* Wqp = (const float*)d_in[14];
    const float* bqp = (const float*)d_in[15];
    const float* Wkp = (const float*)d_in[16];
    const float* bkp = (const float*)d_in[17];
    const float* W_ih = (const float*)d_in[18];
    const float* W_hh = (const float*)d_in[19];
    const float* b_ih = (const float*)d_in[20];
    const float* b_hh = (const float*)d_in[21];
    const float* WO = (const float*)d_in[22];
    const float* bO = (const float*)d_in[23];
    const float* w   = (const float*)d_in[24];
    const float* w_a = (const float*)d_in[25];
    const float* w_p = (const float*)d_in[26];
    const int* G = (const int*)d_in[27];
    float* out = (float*)d_out;

    int S  = in_sizes[2] / (BDIM*DA);   // 6144
    int Wn = S - MDIM + 1;              // 6113

    __nv_bfloat16 *Xbf_p, *Abf_p, *Pbf_p, *WkMbf_p, *Wkabf_p, *Wkpbf_p;
    cudaGetSymbolAddress((void**)&Xbf_p, d_Xbf);
    cudaGetSymbolAddress((void**)&Abf_p, d_Abf);
    cudaGetSymbolAddress((void**)&Pbf_p, d_Pbf);
    cudaGetSymbolAddress((void**)&WkMbf_p, d_WkMbf);
    cudaGetSymbolAddress((void**)&Wkabf_p, d_Wkabf);
    cudaGetSymbolAddress((void**)&Wkpbf_p, d_Wkpbf);

    convert_kernel<<<4096, 256>>>(memory, x_pre, aux, pos, S);
    mask_kernel<<<1024, 256>>>(Wq, Wk, Wv, WO, W_ih, W_hh, Wka, Wkp, G);
    qv_kernel<<<BDIM*HDIM*MDIM, 64>>>(memory, x_pre, bq, S);
    proj_mma_kernel<DM, DK, 0><<<dim3(S/128, HDIM, BDIM), 256>>>(Xbf_p, WkMbf_p, bk, S, Wn);
    band_mma_kernel<<<dim3((Wn + 63)/64, HDIM, BDIM), 128>>>(S, Wn);
    qa_kernel<<<BDIM*HDIM, 32>>>(aux, Wqa, bqa, S);
    proj_mma_kernel<DA, DAH, 1><<<dim3(S/128, HDIM, BDIM), 256>>>(Abf_p, Wkabf_p, bka, S, Wn);
    qp_kernel<<<BDIM*HDIM, 32>>>(pos, Wqp, bqp, S);
    proj_mma_kernel<DP, DPH, 2><<<dim3(S/128, HDIM, BDIM), 256>>>(Pbf_p, Wkpbf_p, bkp, S, Wn);
    softmax_kernel<<<BDIM*HDIM, 256>>>(w, w_a, w_p, S, Wn);
    xbar_kernel<<<dim3((Wn - 1 + 63)/64, BDIM), 256>>>(S, Wn);
    gi_kernel<<<dim3(31, BDIM), 192>>>(memory, b_ih, S);
    gru_kernel<<<BDIM, 192>>>(b_hh);
    deta_kernel<<<BDIM*HDIM, 64>>>(bv);
    out_kernel<<<BDIM, 512>>>(x_pre, bO, out);
}

// round 12
// speedup vs baseline: 2.2479x; 1.0181x over previous
#include <cuda_runtime.h>
#include <cuda_bf16.h>
#include <math.h>
#include <stdint.h>
#include <stddef.h>

// fixed problem shapes
#define BDIM 8
#define HDIM 8
#define DM 512
#define DA 256
#define DP 128
#define MDIM 32
#define DK 64
#define DAH 32
#define DPH 16
#define SDIM 6144

// ---------------- device scratch ----------------
__device__ __nv_bfloat16 d_Xbf[(size_t)BDIM*SDIM*DM];
__device__ __nv_bfloat16 d_Abf[(size_t)BDIM*SDIM*DA];
__device__ __nv_bfloat16 d_Pbf[(size_t)BDIM*SDIM*DP];
__device__ __nv_bfloat16 d_WkMbf[HDIM*DK*DM];
__device__ __nv_bfloat16 d_Wkabf[HDIM*DAH*DA];
__device__ __nv_bfloat16 d_Wkpbf[HDIM*DPH*DP];
__device__ float d_WqMT[HDIM*DM*DK];   // [h][d][c]
__device__ float d_WvMT[HDIM*DM*DK];   // [h][d][c]
__device__ float d_WOMT[DM*DM];        // [i][j] = WOM[j][i]
__device__ float d_WihT[DM*192];       // [d][j]
__device__ float d_WhhT[DK*192];       // [k][j]
__device__ __nv_bfloat16 d_Knbf[(size_t)BDIM*HDIM*SDIM*DK];  // ~50 MB
__device__ __nv_bfloat16 d_Qvbf[BDIM*HDIM*MDIM*DK];
__device__ float d_QA[BDIM*HDIM*DAH];
__device__ float d_QP[BDIM*HDIM*DPH];
__device__ float d_tn[BDIM*HDIM*SDIM];
__device__ float d_dot2[BDIM*HDIM*SDIM];
__device__ float d_dot3[BDIM*HDIM*SDIM];
__device__ float d_attn[BDIM*HDIM*SDIM];
__device__ float d_alast[BDIM*HDIM];
__device__ float d_xbar[BDIM*HDIM*DM];
__device__ float d_gi[BDIM*31*192];
__device__ float d_res[BDIM*DK];
__device__ float d_deta[BDIM*DM];

__device__ __forceinline__ void mma_bf16(float* c, const uint32_t* a, uint32_t b0, uint32_t b1) {
    asm volatile("mma.sync.aligned.m16n8k16.row.col.f32.bf16.bf16.f32 "
        "{%0,%1,%2,%3}, {%4,%5,%6,%7}, {%8,%9}, {%0,%1,%2,%3};\n"
        : "+f"(c[0]), "+f"(c[1]), "+f"(c[2]), "+f"(c[3])
        : "r"(a[0]), "r"(a[1]), "r"(a[2]), "r"(a[3]), "r"(b0), "r"(b1));
}

__device__ __forceinline__ void ldsm_x4(uint32_t* r, uint32_t addr) {
    asm volatile("ldmatrix.sync.aligned.m8n8.x4.shared.b16 {%0,%1,%2,%3}, [%4];"
        : "=r"(r[0]), "=r"(r[1]), "=r"(r[2]), "=r"(r[3]) : "r"(addr));
}
__device__ __forceinline__ void ldsm_x2(uint32_t* r, uint32_t addr) {
    asm volatile("ldmatrix.sync.aligned.m8n8.x2.shared.b16 {%0,%1}, [%2];"
        : "=r"(r[0]), "=r"(r[1]) : "r"(addr));
}

__device__ __forceinline__ void cpa16(uint32_t saddr, const void* g) {
    asm volatile("cp.async.cg.shared.global [%0], [%1], 16;" :: "r"(saddr), "l"(g));
}
__device__ __forceinline__ void cpa_commit() { asm volatile("cp.async.commit_group;"); }
__device__ __forceinline__ void cpa_wait0() { asm volatile("cp.async.wait_group 0;" ::: "memory"); }

__device__ __forceinline__ uint32_t packbf(float a, float b) {
    __nv_bfloat162 t = __floats2bfloat162_rn(a, b);
    return *(uint32_t*)&t;
}

// ---------------- fp32 -> bf16 conversion of activations ----------------
__global__ void convert_kernel(const float* __restrict__ memory, const float* __restrict__ x_pre,
                               const float* __restrict__ aux, const float* __restrict__ pos,
                               int S) {
    int stride = gridDim.x*256;
    int nX = BDIM*S*(DM/4);
    for (int j = blockIdx.x*256 + threadIdx.x; j < nX; j += stride) {
        int b = j / (S*(DM/4));
        int r = j % (S*(DM/4));
        int s = r / (DM/4);
        int d4 = (r % (DM/4))*4;
        const float* src = (s < S-1) ? memory + ((size_t)b*(S-1) + s)*DM + d4
                                     : x_pre + (size_t)b*DM + d4;
        float4 v = *(const float4*)src;
        uint2 o; o.x = packbf(v.x, v.y); o.y = packbf(v.z, v.w);
        *(uint2*)&d_Xbf[((size_t)b*S + s)*DM + d4] = o;
    }
    int nA = BDIM*S*(DA/4);
    for (int j = blockIdx.x*256 + threadIdx.x; j < nA; j += stride) {
        float4 v = *(const float4*)(aux + (size_t)j*4);
        uint2 o; o.x = packbf(v.x, v.y); o.y = packbf(v.z, v.w);
        *(uint2*)&d_Abf[(size_t)j*4] = o;
    }
    int nP = BDIM*S*(DP/4);
    for (int j = blockIdx.x*256 + threadIdx.x; j < nP; j += stride) {
        float4 v = *(const float4*)(pos + (size_t)j*4);
        uint2 o; o.x = packbf(v.x, v.y); o.y = packbf(v.z, v.w);
        *(uint2*)&d_Pbf[(size_t)j*4] = o;
    }
}

// ---------------- masked weights (+ transposes, bf16 copies) + zero xbar ----------------
__global__ void mask_kernel(const float* __restrict__ Wq, const float* __restrict__ Wk,
                            const float* __restrict__ Wv, const float* __restrict__ WO,
                            const float* __restrict__ W_ih, const float* __restrict__ W_hh,
                            const float* __restrict__ Wka, const float* __restrict__ Wkp,
                            const int* __restrict__ G) {
    int i = blockIdx.x*256 + threadIdx.x;
    const int NW = HDIM*DK*DM;
    if (i < NW) {
        int h = i >> 15;
        int c = (i >> 9) & 63;
        int d = i & 511;
        float g = (float)G[c*64 + (d & 63)];
        d_WkMbf[i] = __float2bfloat16(Wk[i]*g);
        d_WqMT[((size_t)h*DM + d)*DK + c] = Wq[i]*g;
        d_WvMT[((size_t)h*DM + d)*DK + c] = Wv[i]*g;
    }
    if (i < HDIM*DAH*DA) d_Wkabf[i] = __float2bfloat16(Wka[i]);
    if (i < HDIM*DPH*DP) d_Wkpbf[i] = __float2bfloat16(Wkp[i]);
    if (i < DM*DM) {
        int j = i & 511, r = i >> 9;
        d_WOMT[(size_t)j*DM + r] = WO[i]*(float)G[(r & 63)*64 + (j & 63)];
    }
    if (i < 192*DM) {
        int j = i >> 9, d = i & 511;
        d_WihT[d*192 + j] = W_ih[i];
    }
    if (i < 192*DK) {
        int j = i >> 6, k = i & 63;
        d_WhhT[k*192 + j] = W_hh[i];
    }
    if (i < BDIM*HDIM*DM) d_xbar[i] = 0.f;
}

// ---------------- Qv: last M rows, masked proj + l2norm (fp32 math, bf16 out) ----------------
__global__ void qv_kernel(const float* __restrict__ memory, const float* __restrict__ x_pre,
                          const float* __restrict__ bq, int S) {
    int m = blockIdx.x & 31, h = (blockIdx.x >> 5) & 7, b = blockIdx.x >> 8;
    __shared__ float xs[DM];
    __shared__ float wp[2];
    int s = S - MDIM + m;
    const float* row = (s < S-1) ? memory + ((size_t)b*(S-1) + s)*DM : x_pre + (size_t)b*DM;
    for (int i = threadIdx.x; i < DM; i += 64) xs[i] = row[i];
    __syncthreads();
    int c = threadIdx.x;
    const float* wt = d_WqMT + (size_t)h*DM*DK;
    float acc = bq[h*DK + c];
    #pragma unroll 8
    for (int d = 0; d < DM; d++) acc += xs[d]*wt[d*DK + c];
    float v = acc*acc;
    for (int o = 16; o; o >>= 1) v += __shfl_xor_sync(0xffffffffu, v, o);
    if ((c & 31) == 0) wp[c >> 5] = v;
    __syncthreads();
    float inv = 1.f / fmaxf(sqrtf(wp[0] + wp[1]), 1e-12f);
    d_Qvbf[(((size_t)b*HDIM + h)*MDIM + m)*DK + c] = __float2bfloat16(acc*inv);
}

// ---------------- tensor-core projection (bf16 mma + ldmatrix, k-chunk 128) ----------------
template<int DIN, int DOUT, int MODE>
__global__ void __launch_bounds__(256)
proj_mma_kernel(const __nv_bfloat16* __restrict__ src, const __nv_bfloat16* __restrict__ W,
                const float* __restrict__ bias, int S, int Wn) {
    constexpr int NW_N = 2;
    constexpr int TM   = 128;            // 4 m-warps * 32
    constexpr int WT_N = DOUT/NW_N;
    constexpr int NFN  = WT_N/8;         // 4 / 2 / 1
    constexpr int KC   = 128;            // k-chunk (bf16 elems)
    constexpr int NCH  = DIN/KC;         // 4 / 2 / 1
    constexpr int RS   = 68;             // 64 pairs + 4 pad (272B = 17*16B); 68%32==4 -> conflict-free

    extern __shared__ uint32_t dynsm[];
    uint32_t* Xs  = dynsm;               // TM*RS
    uint32_t* Wss = dynsm + TM*RS;       // DOUT*RS
    __shared__ float bs_s[DOUT];
    __shared__ float qs_s[DOUT];
    __shared__ float red_s[TM*2];

    int tid = threadIdx.x;
    int lane = tid & 31, wid = tid >> 5;
    int g = lane >> 2, tig = lane & 3;
    int warp_n = wid % NW_N, warp_m = wid / NW_N;
    int rb = warp_m*32, cb = warp_n*WT_N;
    int s0 = blockIdx.x*TM, h = blockIdx.y, b = blockIdx.z;
    int bh = b*HDIM + h;

    uint32_t xB = (uint32_t)__cvta_generic_to_shared(Xs);
    uint32_t wB = (uint32_t)__cvta_generic_to_shared(Wss);

    // ldmatrix lane addresses (bytes), add ps*32 per k16-step (ps = 0..7)
    uint32_t aAddr[2];
    #pragma unroll
    for (int mi = 0; mi < 2; mi++)
        aAddr[mi] = xB + ((rb + mi*16 + (lane & 7) + (lane & 8))*RS + ((lane >> 4) & 1)*4)*4;
    uint32_t bAddr[(NFN + 1)/2];
    #pragma unroll
    for (int pg = 0; pg < (NFN + 1)/2; pg++) {
        if (NFN == 1)
            bAddr[pg] = wB + ((cb + (lane & 7))*RS + ((lane >> 3) & 1)*4)*4;
        else
            bAddr[pg] = wB + ((cb + pg*16 + ((lane >> 4) & 1)*8 + (lane & 7))*RS + ((lane >> 3) & 1)*4)*4;
    }

    for (int i = tid; i < DOUT; i += 256) {
        bs_s[i] = bias[h*DOUT + i];
        if (MODE == 1) qs_s[i] = d_QA[(size_t)bh*DAH + i];
        if (MODE == 2) qs_s[i] = d_QP[(size_t)bh*DPH + i];
    }

    float acc[2][NFN][4];
    #pragma unroll
    for (int mi = 0; mi < 2; mi++)
        #pragma unroll
        for (int ni = 0; ni < NFN; ni++)
            #pragma unroll
            for (int q = 0; q < 4; q++) acc[mi][ni][q] = 0.f;

    for (int ch = 0; ch < NCH; ch++) {
        int d0 = ch*KC;
        // stage X tile (TM x 128 bf16): 16 segs of 16B per row
        #pragma unroll
        for (int it = 0; it < TM*16/256; it++) {
            int e = it*256 + tid;
            int row = e >> 4, seg = e & 15;
            cpa16(xB + (row*RS + seg*4)*4, src + ((size_t)b*S + s0 + row)*DIN + d0 + seg*8);
        }
        for (int e = tid; e < DOUT*16; e += 256) {
            int rr = e >> 4, seg = e & 15;
            cpa16(wB + (rr*RS + seg*4)*4, W + ((size_t)(h*DOUT + rr))*DIN + d0 + seg*8);
        }
        cpa_commit();
        cpa_wait0();
        __syncthreads();
        #pragma unroll
        for (int ps = 0; ps < 8; ps++) {
            uint32_t a[2][4];
            ldsm_x4(a[0], aAddr[0] + ps*32);
            ldsm_x4(a[1], aAddr[1] + ps*32);
            uint32_t bb[2*NFN];
            if (NFN == 1) {
                ldsm_x2(bb, bAddr[0] + ps*32);
            } else {
                #pragma unroll
                for (int pg = 0; pg < NFN/2; pg++)
                    ldsm_x4(bb + pg*4, bAddr[pg] + ps*32);
            }
            #pragma unroll
            for (int ni = 0; ni < NFN; ni++) {
                uint32_t b0 = bb[2*ni], b1 = bb[2*ni + 1];
                #pragma unroll
                for (int mi = 0; mi < 2; mi++) mma_bf16(acc[mi][ni], a[mi], b0, b1);
            }
        }
        if (ch + 1 < NCH) __syncthreads();
    }

    // ---- epilogue: bias + per-row l2 norm ----
    float sl[2] = {0.f, 0.f}, sh[2] = {0.f, 0.f};
    #pragma unroll
    for (int mi = 0; mi < 2; mi++)
        #pragma unroll
        for (int ni = 0; ni < NFN; ni++) {
            int c0 = cb + ni*8 + 2*tig, c1 = c0 + 1;
            acc[mi][ni][0] += bs_s[c0];
            acc[mi][ni][1] += bs_s[c1];
            acc[mi][ni][2] += bs_s[c0];
            acc[mi][ni][3] += bs_s[c1];
            sl[mi] += acc[mi][ni][0]*acc[mi][ni][0] + acc[mi][ni][1]*acc[mi][ni][1];
            sh[mi] += acc[mi][ni][2]*acc[mi][ni][2] + acc[mi][ni][3]*acc[mi][ni][3];
        }
    #pragma unroll
    for (int mi = 0; mi < 2; mi++) {
        sl[mi] += __shfl_xor_sync(0xffffffffu, sl[mi], 1);
        sl[mi] += __shfl_xor_sync(0xffffffffu, sl[mi], 2);
        sh[mi] += __shfl_xor_sync(0xffffffffu, sh[mi], 1);
        sh[mi] += __shfl_xor_sync(0xffffffffu, sh[mi], 2);
    }
    __syncthreads();
    if (tig == 0) {
        #pragma unroll
        for (int mi = 0; mi < 2; mi++) {
            int rl = rb + mi*16 + g;
            red_s[rl*2 + warp_n] = sl[mi];
            red_s[(rl+8)*2 + warp_n] = sh[mi];
        }
    }
    __syncthreads();
    #pragma unroll
    for (int mi = 0; mi < 2; mi++) {
        int rl = rb + mi*16 + g;
        sl[mi] = red_s[rl*2] + red_s[rl*2+1];
        sh[mi] = red_s[(rl+8)*2] + red_s[(rl+8)*2+1];
    }
    float il[2], ih[2];
    #pragma unroll
    for (int mi = 0; mi < 2; mi++) {
        il[mi] = 1.f / fmaxf(sqrtf(sl[mi]), 1e-12f);
        ih[mi] = 1.f / fmaxf(sqrtf(sh[mi]), 1e-12f);
    }

    if (MODE == 0) {
        #pragma unroll
        for (int mi = 0; mi < 2; mi++) {
            int rl = rb + mi*16 + g;
            size_t base_l = ((size_t)bh*S + s0 + rl)*DK;
            size_t base_h = ((size_t)bh*S + s0 + rl + 8)*DK;
            #pragma unroll
            for (int ni = 0; ni < NFN; ni++) {
                int c0 = cb + ni*8 + 2*tig;
                *(uint32_t*)&d_Knbf[base_l + c0] = packbf(acc[mi][ni][0]*il[mi], acc[mi][ni][1]*il[mi]);
                *(uint32_t*)&d_Knbf[base_h + c0] = packbf(acc[mi][ni][2]*ih[mi], acc[mi][ni][3]*ih[mi]);
            }
        }
    } else {
        float* dst = (MODE == 1) ? d_dot2 : d_dot3;
        float dl[2], dh[2];
        #pragma unroll
        for (int mi = 0; mi < 2; mi++) {
            dl[mi] = 0.f; dh[mi] = 0.f;
            #pragma unroll
            for (int ni = 0; ni < NFN; ni++) {
                int c0 = cb + ni*8 + 2*tig, c1 = c0 + 1;
                dl[mi] += acc[mi][ni][0]*qs_s[c0] + acc[mi][ni][1]*qs_s[c1];
                dh[mi] += acc[mi][ni][2]*qs_s[c0] + acc[mi][ni][3]*qs_s[c1];
            }
            dl[mi] += __shfl_xor_sync(0xffffffffu, dl[mi], 1);
            dl[mi] += __shfl_xor_sync(0xffffffffu, dl[mi], 2);
            dh[mi] += __shfl_xor_sync(0xffffffffu, dh[mi], 1);
            dh[mi] += __shfl_xor_sync(0xffffffffu, dh[mi], 2);
        }
        __syncthreads();
        if (tig == 0) {
            #pragma unroll
            for (int mi = 0; mi < 2; mi++) {
                int rl = rb + mi*16 + g;
                red_s[rl*2 + warp_n] = dl[mi];
                red_s[(rl+8)*2 + warp_n] = dh[mi];
            }
        }
        __syncthreads();
        if (warp_n == 0 && tig == 0) {
            #pragma unroll
            for (int mi = 0; mi < 2; mi++) {
                int rl = rb + mi*16 + g;
                float DL = red_s[rl*2] + red_s[rl*2+1];
                float DH = red_s[(rl+8)*2] + red_s[(rl+8)*2+1];
                int wl = s0 + rl - 31, wh = wl + 8;
                if (wl >= 0 && wl < Wn) dst[(size_t)bh*S + wl] = DL*il[mi];
                if (wh >= 0 && wh < Wn) dst[(size_t)bh*S + wh] = DH*ih[mi];
            }
        }
    }
}

// ---------------- banded Qv . Kn -> tn  (bf16 mma) ----------------
__global__ void __launch_bounds__(128) band_mma_kernel(int S, int Wn) {
    constexpr int RS = 36;
    __shared__ uint32_t Qs[32*RS];
    __shared__ uint32_t Ks[96*RS];
    __shared__ float Ps[32*100];
    int tid = threadIdx.x;
    int lane = tid & 31, wid = tid >> 5;
    int g = lane >> 2, tig = lane & 3;
    int w0 = blockIdx.x*64, h = blockIdx.y, b = blockIdx.z;
    int bh = b*HDIM + h;

    uint32_t qB = (uint32_t)__cvta_generic_to_shared(Qs);
    uint32_t kB = (uint32_t)__cvta_generic_to_shared(Ks);

    for (int e = tid; e < 96*8; e += 128) {
        int r = e >> 3, seg = e & 7;
        int s = w0 + r;
        if (s < S) cpa16(kB + (r*RS + seg*4)*4, d_Knbf + ((size_t)bh*S + s)*DK + seg*8);
        else {
            uint32_t* p = &Ks[r*RS + seg*4];
            p[0] = 0; p[1] = 0; p[2] = 0; p[3] = 0;
        }
    }
    for (int e = tid; e < 32*8; e += 128) {
        int r = e >> 3, seg = e & 7;
        cpa16(qB + (r*RS + seg*4)*4, d_Qvbf + ((size_t)bh*MDIM + r)*DK + seg*8);
    }
    cpa_commit();
    cpa_wait0();
    __syncthreads();

    float acc[2][3][4];
    #pragma unroll
    for (int mi = 0; mi < 2; mi++)
        #pragma unroll
        for (int ni = 0; ni < 3; ni++)
            #pragma unroll
            for (int q = 0; q < 4; q++) acc[mi][ni][q] = 0.f;
    int nb = wid*24;
    #pragma unroll
    for (int ks = 0; ks < 4; ks++) {
        int p0 = ks*8;
        uint32_t a[2][4];
        #pragma unroll
        for (int mi = 0; mi < 2; mi++) {
            int r = mi*16 + g;
            a[mi][0] = Qs[r*RS + p0 + tig];
            a[mi][1] = Qs[(r+8)*RS + p0 + tig];
            a[mi][2] = Qs[r*RS + p0 + tig + 4];
            a[mi][3] = Qs[(r+8)*RS + p0 + tig + 4];
        }
        #pragma unroll
        for (int ni = 0; ni < 3; ni++) {
            int cn = nb + ni*8 + g;
            uint32_t b0 = Ks[cn*RS + p0 + tig];
            uint32_t b1 = Ks[cn*RS + p0 + tig + 4];
            #pragma unroll
            for (int mi = 0; mi < 2; mi++) mma_bf16(acc[mi][ni], a[mi], b0, b1);
        }
    }
    #pragma unroll
    for (int mi = 0; mi < 2; mi++)
        #pragma unroll
        for (int ni = 0; ni < 3; ni++) {
            int c0 = nb + ni*8 + 2*tig;
            int r = mi*16 + g;
            Ps[r*100 + c0]     = acc[mi][ni][0];
            Ps[r*100 + c0 + 1] = acc[mi][ni][1];
            Ps[(r+8)*100 + c0]     = acc[mi][ni][2];
            Ps[(r+8)*100 + c0 + 1] = acc[mi][ni][3];
        }
    __syncthreads();
    if (tid < 64) {
        int w = w0 + tid;
        if (w < Wn) {
            float s = 0.f;
            #pragma unroll
            for (int m = 0; m < 32; m++) s += Ps[m*100 + tid + m];
            d_tn[(size_t)bh*S + w] = s*(1.f/32.f);
        }
    }
}

// ---------------- QA / QP (last-row queries, fp32) ----------------
__global__ void qa_kernel(const float* __restrict__ aux, const float* __restrict__ Wqa,
                          const float* __restrict__ bqa, int S) {
    int h = blockIdx.x & 7, b = blockIdx.x >> 3;
    int c = threadIdx.x;  // 32
    const float* ar = aux + ((size_t)b*S + (S-1))*DA;
    const float* wr = Wqa + ((size_t)h*DAH + c)*DA;
    float acc = bqa[h*DAH + c];
    #pragma unroll 4
    for (int d = 0; d < DA; d++) acc += ar[d]*wr[d];
    float v = acc*acc;
    for (int o = 16; o; o >>= 1) v += __shfl_xor_sync(0xffffffffu, v, o);
    float inv = 1.f / fmaxf(sqrtf(v), 1e-12f);
    d_QA[((size_t)b*HDIM + h)*DAH + c] = acc*inv;
}

__global__ void qp_kernel(const float* __restrict__ pos, const float* __restrict__ Wqp,
                          const float* __restrict__ bqp, int S) {
    int h = blockIdx.x & 7, b = blockIdx.x >> 3;
    int lane = threadIdx.x;   // 32
    int c = lane & 15;
    const float* pr = pos + ((size_t)b*S + (S-1))*DP;
    const float* wr = Wqp + ((size_t)h*DPH + c)*DP;
    float acc = bqp[h*DPH + c];
    #pragma unroll 4
    for (int d = 0; d < DP; d++) acc += pr[d]*wr[d];
    float v = acc*acc;
    for (int o = 8; o; o >>= 1) v += __shfl_xor_sync(0xffffffffu, v, o);
    float inv = 1.f / fmaxf(sqrtf(v), 1e-12f);
    if (lane < 16) d_QP[((size_t)b*HDIM + h)*DPH + c] = acc*inv;
}

// ---------------- softmax over Wn ----------------
__global__ void softmax_kernel(const float* __restrict__ w1, const float* __restrict__ w2,
                               const float* __restrict__ w3, int S, int Wn) {
    int bh = blockIdx.x, t = threadIdx.x;   // 256
    __shared__ float red[8];
    __shared__ float sval;
    float c1 = w1[0], c2 = w2[0], c3 = w3[0];
    size_t base = (size_t)bh*S;
    float mx = -1e30f;
    for (int i = t; i < Wn; i += 256) {
        float l = c1*d_tn[base+i] + c2*d_dot2[base+i] + c3*d_dot3[base+i];
        d_attn[base+i] = l;
        mx = fmaxf(mx, l);
    }
    for (int o = 16; o; o >>= 1) mx = fmaxf(mx, __shfl_xor_sync(0xffffffffu, mx, o));
    if ((t & 31) == 0) red[t >> 5] = mx;
    __syncthreads();
    if (t == 0) { float m = red[0]; for (int i = 1; i < 8; i++) m = fmaxf(m, red[i]); sval = m; }
    __syncthreads();
    float MX = sval, sum = 0.f;
    for (int i = t; i < Wn; i += 256) {
        float e = __expf(d_attn[base+i] - MX);
        d_attn[base+i] = e;
        sum += e;
    }
    for (int o = 16; o; o >>= 1) sum += __shfl_xor_sync(0xffffffffu, sum, o);
    __syncthreads();
    if ((t & 31) == 0) red[t >> 5] = sum;
    __syncthreads();
    if (t == 0) { float m = 0.f; for (int i = 0; i < 8; i++) m += red[i]; sval = m; }
    __syncthreads();
    float inv = 1.f / sval;
    for (int i = t; i < Wn; i += 256) {
        float a = d_attn[base+i]*inv;
        d_attn[base+i] = a;
        if (i == Wn-1) d_alast[bh] = a;
    }
}

// ---------------- xbar: attn-weighted row sums of x (bf16 X) ----------------
__global__ void xbar_kernel(int S, int Wn) {
    __shared__ float a_s[8][64];
    int t = threadIdx.x;                 // 256
    int w0 = blockIdx.x*64, b = blockIdx.y;
    for (int i = t; i < 512; i += 256) {
        int hh = i >> 6, j = i & 63;
        int w = w0 + j;
        a_s[hh][j] = (w < Wn-1) ? d_attn[((size_t)b*HDIM + hh)*S + w] : 0.f;
    }
    __syncthreads();
    float acc[8][2];
    #pragma unroll
    for (int h = 0; h < 8; h++) { acc[h][0] = 0.f; acc[h][1] = 0.f; }
    int nrow = Wn - 1 - w0; if (nrow > 64) nrow = 64;
    for (int j = 0; j < nrow; j++) {
        const __nv_bfloat16* xr = d_Xbf + ((size_t)b*S + (31 + w0 + j))*DM;
        float x0 = __bfloat162float(xr[t]);
        float x1 = __bfloat162float(xr[256 + t]);
        #pragma unroll
        for (int h = 0; h < 8; h++) {
            float a = a_s[h][j];
            acc[h][0] += a*x0;
            acc[h][1] += a*x1;
        }
    }
    #pragma unroll
    for (int h = 0; h < 8; h++) {
        atomicAdd(&d_xbar[((size_t)b*HDIM + h)*DM + t], acc[h][0]);
        atomicAdd(&d_xbar[((size_t)b*HDIM + h)*DM + 256 + t], acc[h][1]);
    }
}

// ---------------- GRU ----------------
__global__ void gi_kernel(const float* __restrict__ memory, const float* __restrict__ b_ih,
                          int S) {
    int tt = blockIdx.x, b = blockIdx.y;
    __shared__ float xs[DM];
    int s = S - MDIM + tt;
    const float* row = memory + ((size_t)b*(S-1) + s)*DM;
    for (int i = threadIdx.x; i < DM; i += 192) xs[i] = row[i];
    __syncthreads();
    int j = threadIdx.x;
    float acc = b_ih[j];
    #pragma unroll 8
    for (int d = 0; d < DM; d++) acc += xs[d]*d_WihT[d*192 + j];
    d_gi[((size_t)b*31 + tt)*192 + j] = acc;
}

__global__ void gru_kernel(const float* __restrict__ b_hh) {
    int b = blockIdx.x, j = threadIdx.x;  // 192
    __shared__ float hs[DK];
    __shared__ float gh_s[192];
    if (j < DK) hs[j] = 0.f;
    __syncthreads();
    float bh = b_hh[j];
    for (int t = 0; t < 31; t++) {
        float gh = bh;
        #pragma unroll 8
        for (int k2 = 0; k2 < DK; k2++) gh += hs[k2]*d_WhhT[k2*192 + j];
        gh_s[j] = gh;
        __syncthreads();
        float hn = 0.f;
        if (j < DK) {
            const float* gi = d_gi + ((size_t)b*31 + t)*192;
            float r = 1.f/(1.f + __expf(-(gi[j] + gh_s[j])));
            float z = 1.f/(1.f + __expf(-(gi[64 + j] + gh_s[64 + j])));
            float n = tanhf(gi[128 + j] + r*gh_s[128 + j]);
            hn = (1.f - z)*n + z*hs[j];
        }
        __syncthreads();
        if (j < DK) hs[j] = hn;
        __syncthreads();
    }
    if (j < DK) d_res[b*DK + j] = hs[j];
}

// ---------------- deta = xbar @ WvM^T + bv*(1-alast) + alast*res ----------------
__global__ void deta_kernel(const float* __restrict__ bv) {
    int bh = blockIdx.x;
    int b = bh >> 3, h = bh & 7;
    int c = threadIdx.x;                 // 64
    __shared__ float xb[DM];
    for (int i = c; i < DM; i += 64) xb[i] = d_xbar[(size_t)bh*DM + i];
    __syncthreads();
    const float* wt = d_WvMT + (size_t)h*DM*DK;
    float acc = 0.f;
    #pragma unroll 8
    for (int d = 0; d < DM; d++) acc += xb[d]*wt[d*DK + c];
    float al = d_alast[bh];
    d_deta[(size_t)b*DM + h*DK + c] = acc + bv[h*DK + c]*(1.f - al) + al*d_res[b*DK + c];
}

// ---------------- out = x_pre + deta @ WOM^T + bO ----------------
__global__ void out_kernel(const float* __restrict__ x_pre, const float* __restrict__ bO,
                           float* __restrict__ out) {
    int b = blockIdx.x, j = threadIdx.x;  // 512
    __shared__ float dd[DM];
    dd[j] = d_deta[(size_t)b*DM + j];
    __syncthreads();
    float acc = bO[j];
    #pragma unroll 8
    for (int i = 0; i < DM; i++) acc += dd[i]*d_WOMT[(size_t)i*DM + j];
    out[(size_t)b*DM + j] = x_pre[(size_t)b*DM + j] + acc;
}

extern "C" void kernel_launch(void* const* d_in, const int* in_sizes, int n_in,
                              void* d_out, int out_size) {
    const float* memory = (const float*)d_in[0];
    const float* x_pre  = (const float*)d_in[1];
    const float* aux    = (const float*)d_in[2];
    const float* pos    = (const float*)d_in[3];
    const float* Wq  = (const float*)d_in[4];
    const float* bq  = (const float*)d_in[5];
    const float* Wk  = (const float*)d_in[6];
    const float* bk  = (const float*)d_in[7];
    const float* Wv  = (const float*)d_in[8];
    const float* bv  = (const float*)d_in[9];
    const float* Wqa = (const float*)d_in[10];
    const float* bqa = (const float*)d_in[11];
    const float* Wka = (const float*)d_in[12];
    const float* bka = (const float*)d_in[13];
    const float* Wqp = (const float*)d_in[14];
    const float* bqp = (const float*)d_in[15];
    const float* Wkp = (const float*)d_in[16];
    const float* bkp = (const float*)d_in[17];
    const float* W_ih = (const float*)d_in[18];
    const float* W_hh = (const float*)d_in[19];
    const float* b_ih = (const float*)d_in[20];
    const float* b_hh = (const float*)d_in[21];
    const float* WO = (const float*)d_in[22];
    const float* bO = (const float*)d_in[23];
    const float* w   = (const float*)d_in[24];
    const float* w_a = (const float*)d_in[25];
    const float* w_p = (const float*)d_in[26];
    const int* G = (const int*)d_in[27];
    float* out = (float*)d_out;

    int S  = in_sizes[2] / (BDIM*DA);   // 6144
    int Wn = S - MDIM + 1;              // 6113

    __nv_bfloat16 *Xbf_p, *Abf_p, *Pbf_p, *WkMbf_p, *Wkabf_p, *Wkpbf_p;
    cudaGetSymbolAddress((void**)&Xbf_p, d_Xbf);
    cudaGetSymbolAddress((void**)&Abf_p, d_Abf);
    cudaGetSymbolAddress((void**)&Pbf_p, d_Pbf);
    cudaGetSymbolAddress((void**)&WkMbf_p, d_WkMbf);
    cudaGetSymbolAddress((void**)&Wkabf_p, d_Wkabf);
    cudaGetSymbolAddress((void**)&Wkpbf_p, d_Wkpbf);

    const int smem_k = (128*68 + DK*68)*4;    // 52224
    const int smem_a = (128*68 + DAH*68)*4;   // 43520
    const int smem_p = (128*68 + DPH*68)*4;   // 39168
    cudaFuncSetAttribute(proj_mma_kernel<DM, DK, 0>,
                         cudaFuncAttributeMaxDynamicSharedMemorySize, smem_k);
    cudaFuncSetAttribute(proj_mma_kernel<DA, DAH, 1>,
                         cudaFuncAttributeMaxDynamicSharedMemorySize, smem_a);
    cudaFuncSetAttribute(proj_mma_kernel<DP, DPH, 2>,
                         cudaFuncAttributeMaxDynamicSharedMemorySize, smem_p);

    convert_kernel<<<4096, 256>>>(memory, x_pre, aux, pos, S);
    mask_kernel<<<1024, 256>>>(Wq, Wk, Wv, WO, W_ih, W_hh, Wka, Wkp, G);
    qv_kernel<<<BDIM*HDIM*MDIM, 64>>>(memory, x_pre, bq, S);
    proj_mma_kernel<DM, DK, 0><<<dim3(S/128, HDIM, BDIM), 256, smem_k>>>(Xbf_p, WkMbf_p, bk, S, Wn);
    band_mma_kernel<<<dim3((Wn + 63)/64, HDIM, BDIM), 128>>>(S, Wn);
    qa_kernel<<<BDIM*HDIM, 32>>>(aux, Wqa, bqa, S);
    proj_mma_kernel<DA, DAH, 1><<<dim3(S/128, HDIM, BDIM), 256, smem_a>>>(Abf_p, Wkabf_p, bka, S, Wn);
    qp_kernel<<<BDIM*HDIM, 32>>>(pos, Wqp, bqp, S);
    proj_mma_kernel<DP, DPH, 2><<<dim3(S/128, HDIM, BDIM), 256, smem_p>>>(Pbf_p, Wkpbf_p, bkp, S, Wn);
    softmax_kernel<<<BDIM*HDIM, 256>>>(w, w_a, w_p, S, Wn);
    xbar_kernel<<<dim3((Wn - 1 + 63)/64, BDIM), 256>>>(S, Wn);
    gi_kernel<<<dim3(31, BDIM), 192>>>(memory, b_ih, S);
    gru_kernel<<<BDIM, 192>>>(b_hh);
    deta_kernel<<<BDIM*HDIM, 64>>>(bv);
    out_kernel<<<BDIM, 512>>>(x_pre, bO, out);
}

// round 13
// speedup vs baseline: 2.2976x; 1.0221x over previous
#include <cuda_runtime.h>
#include <cuda_bf16.h>
#include <math.h>
#include <stdint.h>
#include <stddef.h>

// fixed problem shapes
#define BDIM 8
#define HDIM 8
#define DM 512
#define DA 256
#define DP 128
#define MDIM 32
#define DK 64
#define DAH 32
#define DPH 16
#define SDIM 6144

// ---------------- device scratch ----------------
__device__ __nv_bfloat16 d_Xbf[(size_t)BDIM*SDIM*DM];
__device__ __nv_bfloat16 d_Abf[(size_t)BDIM*SDIM*DA];
__device__ __nv_bfloat16 d_Pbf[(size_t)BDIM*SDIM*DP];
__device__ __nv_bfloat16 d_WkMbf[HDIM*DK*DM];
__device__ __nv_bfloat16 d_Wkabf[HDIM*DAH*DA];
__device__ __nv_bfloat16 d_Wkpbf[HDIM*DPH*DP];
__device__ float d_WqMT[HDIM*DM*DK];   // [h][d][c]
__device__ float d_WvMT[HDIM*DM*DK];   // [h][d][c]
__device__ float d_WOMT[DM*DM];        // [i][j] = WOM[j][i]
__device__ float d_WihT[DM*192];       // [d][j]
__device__ float d_WhhT[DK*192];       // [k][j]
__device__ __nv_bfloat16 d_Knbf[(size_t)BDIM*HDIM*SDIM*DK];  // ~50 MB
__device__ __nv_bfloat16 d_Qvbf[BDIM*HDIM*MDIM*DK];
__device__ float d_QA[BDIM*HDIM*DAH];
__device__ float d_QP[BDIM*HDIM*DPH];
__device__ float d_tn[BDIM*HDIM*SDIM];
__device__ float d_dot2[BDIM*HDIM*SDIM];
__device__ float d_dot3[BDIM*HDIM*SDIM];
__device__ float d_attn[BDIM*HDIM*SDIM];
__device__ float d_alast[BDIM*HDIM];
__device__ float d_xbar[BDIM*HDIM*DM];
__device__ float d_gi[BDIM*31*192];
__device__ float d_res[BDIM*DK];

__device__ __forceinline__ void mma_bf16(float* c, const uint32_t* a, uint32_t b0, uint32_t b1) {
    asm volatile("mma.sync.aligned.m16n8k16.row.col.f32.bf16.bf16.f32 "
        "{%0,%1,%2,%3}, {%4,%5,%6,%7}, {%8,%9}, {%0,%1,%2,%3};\n"
        : "+f"(c[0]), "+f"(c[1]), "+f"(c[2]), "+f"(c[3])
        : "r"(a[0]), "r"(a[1]), "r"(a[2]), "r"(a[3]), "r"(b0), "r"(b1));
}

__device__ __forceinline__ void ldsm_x4(uint32_t* r, uint32_t addr) {
    asm volatile("ldmatrix.sync.aligned.m8n8.x4.shared.b16 {%0,%1,%2,%3}, [%4];"
        : "=r"(r[0]), "=r"(r[1]), "=r"(r[2]), "=r"(r[3]) : "r"(addr));
}
__device__ __forceinline__ void ldsm_x2(uint32_t* r, uint32_t addr) {
    asm volatile("ldmatrix.sync.aligned.m8n8.x2.shared.b16 {%0,%1}, [%2];"
        : "=r"(r[0]), "=r"(r[1]) : "r"(addr));
}

__device__ __forceinline__ void cpa16(uint32_t saddr, const void* g) {
    asm volatile("cp.async.cg.shared.global [%0], [%1], 16;" :: "r"(saddr), "l"(g));
}
__device__ __forceinline__ void cpa_commit() { asm volatile("cp.async.commit_group;"); }
__device__ __forceinline__ void cpa_wait0() { asm volatile("cp.async.wait_group 0;" ::: "memory"); }

__device__ __forceinline__ uint32_t packbf(float a, float b) {
    __nv_bfloat162 t = __floats2bfloat162_rn(a, b);
    return *(uint32_t*)&t;
}

// ---------------- fp32 -> bf16 conversion of activations ----------------
__global__ void convert_kernel(const float* __restrict__ memory, const float* __restrict__ x_pre,
                               const float* __restrict__ aux, const float* __restrict__ pos,
                               int S) {
    int stride = gridDim.x*256;
    int nX = BDIM*S*(DM/4);
    for (int j = blockIdx.x*256 + threadIdx.x; j < nX; j += stride) {
        int b = j / (S*(DM/4));
        int r = j % (S*(DM/4));
        int s = r / (DM/4);
        int d4 = (r % (DM/4))*4;
        const float* src = (s < S-1) ? memory + ((size_t)b*(S-1) + s)*DM + d4
                                     : x_pre + (size_t)b*DM + d4;
        float4 v = *(const float4*)src;
        uint2 o; o.x = packbf(v.x, v.y); o.y = packbf(v.z, v.w);
        *(uint2*)&d_Xbf[((size_t)b*S + s)*DM + d4] = o;
    }
    int nA = BDIM*S*(DA/4);
    for (int j = blockIdx.x*256 + threadIdx.x; j < nA; j += stride) {
        float4 v = *(const float4*)(aux + (size_t)j*4);
        uint2 o; o.x = packbf(v.x, v.y); o.y = packbf(v.z, v.w);
        *(uint2*)&d_Abf[(size_t)j*4] = o;
    }
    int nP = BDIM*S*(DP/4);
    for (int j = blockIdx.x*256 + threadIdx.x; j < nP; j += stride) {
        float4 v = *(const float4*)(pos + (size_t)j*4);
        uint2 o; o.x = packbf(v.x, v.y); o.y = packbf(v.z, v.w);
        *(uint2*)&d_Pbf[(size_t)j*4] = o;
    }
}

// ---------------- masked weights (+ transposes, bf16 copies) + zero xbar ----------------
__global__ void mask_kernel(const float* __restrict__ Wq, const float* __restrict__ Wk,
                            const float* __restrict__ Wv, const float* __restrict__ WO,
                            const float* __restrict__ W_ih, const float* __restrict__ W_hh,
                            const float* __restrict__ Wka, const float* __restrict__ Wkp,
                            const int* __restrict__ G) {
    int i = blockIdx.x*256 + threadIdx.x;
    const int NW = HDIM*DK*DM;
    if (i < NW) {
        int h = i >> 15;
        int c = (i >> 9) & 63;
        int d = i & 511;
        float g = (float)G[c*64 + (d & 63)];
        d_WkMbf[i] = __float2bfloat16(Wk[i]*g);
        d_WqMT[((size_t)h*DM + d)*DK + c] = Wq[i]*g;
        d_WvMT[((size_t)h*DM + d)*DK + c] = Wv[i]*g;
    }
    if (i < HDIM*DAH*DA) d_Wkabf[i] = __float2bfloat16(Wka[i]);
    if (i < HDIM*DPH*DP) d_Wkpbf[i] = __float2bfloat16(Wkp[i]);
    if (i < DM*DM) {
        int j = i & 511, r = i >> 9;
        d_WOMT[(size_t)j*DM + r] = WO[i]*(float)G[(r & 63)*64 + (j & 63)];
    }
    if (i < 192*DM) {
        int j = i >> 9, d = i & 511;
        d_WihT[d*192 + j] = W_ih[i];
    }
    if (i < 192*DK) {
        int j = i >> 6, k = i & 63;
        d_WhhT[k*192 + j] = W_hh[i];
    }
    if (i < BDIM*HDIM*DM) d_xbar[i] = 0.f;
}

// ---------------- Qv: last M rows (4 rows per block), masked proj + l2norm ----------------
__global__ void __launch_bounds__(256) qv_kernel(const float* __restrict__ memory,
                          const float* __restrict__ x_pre,
                          const float* __restrict__ bq, int S) {
    int mgrp = blockIdx.x & 7, h = (blockIdx.x >> 3) & 7, b = blockIdx.x >> 6;
    __shared__ float xs[4][DM];
    __shared__ float wp[4][2];
    int tid = threadIdx.x;
    int mg = tid >> 6, c = tid & 63;
    // stage 4 rows
    for (int i = tid; i < 4*DM; i += 256) {
        int r = i >> 9, d = i & 511;
        int s = S - MDIM + mgrp*4 + r;
        const float* row = (s < S-1) ? memory + ((size_t)b*(S-1) + s)*DM : x_pre + (size_t)b*DM;
        xs[r][d] = row[d];
    }
    __syncthreads();
    const float* wt = d_WqMT + (size_t)h*DM*DK;
    float acc = bq[h*DK + c];
    #pragma unroll 8
    for (int d = 0; d < DM; d++) acc += xs[mg][d]*wt[d*DK + c];
    float v = acc*acc;
    for (int o = 16; o; o >>= 1) v += __shfl_xor_sync(0xffffffffu, v, o);
    if ((tid & 31) == 0) wp[mg][(c >> 5)] = v;
    __syncthreads();
    float inv = 1.f / fmaxf(sqrtf(wp[mg][0] + wp[mg][1]), 1e-12f);
    int m = mgrp*4 + mg;
    d_Qvbf[(((size_t)b*HDIM + h)*MDIM + m)*DK + c] = __float2bfloat16(acc*inv);
}

// ---------------- tensor-core projection (bf16 mma + ldmatrix, k-chunk 128) ----------------
// HPB = heads per block. DOUT = total output cols across HPB heads.
// MODE 0 (HPB=2): kproj, warp_n == local head; no cross-warp norm reduce.
// MODE 1/2 (HPB=1): aux/pos with fused query-dot epilogue.
template<int DIN, int DOUT, int MODE, int HPB>
__global__ void __launch_bounds__(256)
proj_mma_kernel(const __nv_bfloat16* __restrict__ src, const __nv_bfloat16* __restrict__ W,
                const float* __restrict__ bias, int S, int Wn) {
    constexpr int NW_N = 2;
    constexpr int TM   = 128;            // 4 m-warps * 32
    constexpr int WT_N = DOUT/NW_N;
    constexpr int NFN  = WT_N/8;
    constexpr int KC   = 128;
    constexpr int NCH  = DIN/KC;
    constexpr int RS   = 68;             // 64 pairs + 4 pad; 68%32==4 -> conflict-free

    extern __shared__ uint32_t dynsm[];
    uint32_t* Xs  = dynsm;               // TM*RS
    uint32_t* Wss = dynsm + TM*RS;       // DOUT*RS
    __shared__ float bs_s[DOUT];
    __shared__ float qs_s[DOUT];
    __shared__ float red_s[TM*2];

    int tid = threadIdx.x;
    int lane = tid & 31, wid = tid >> 5;
    int g = lane >> 2, tig = lane & 3;
    int warp_n = wid % NW_N, warp_m = wid / NW_N;
    int rb = warp_m*32, cb = warp_n*WT_N;
    int s0 = blockIdx.x*TM, hb = blockIdx.y, b = blockIdx.z;

    uint32_t xB = (uint32_t)__cvta_generic_to_shared(Xs);
    uint32_t wB = (uint32_t)__cvta_generic_to_shared(Wss);

    uint32_t aAddr[2];
    #pragma unroll
    for (int mi = 0; mi < 2; mi++)
        aAddr[mi] = xB + ((rb + mi*16 + (lane & 7) + (lane & 8))*RS + ((lane >> 4) & 1)*4)*4;
    uint32_t bAddr[(NFN + 1)/2];
    #pragma unroll
    for (int pg = 0; pg < (NFN + 1)/2; pg++) {
        if (NFN == 1)
            bAddr[pg] = wB + ((cb + (lane & 7))*RS + ((lane >> 3) & 1)*4)*4;
        else
            bAddr[pg] = wB + ((cb + pg*16 + ((lane >> 4) & 1)*8 + (lane & 7))*RS + ((lane >> 3) & 1)*4)*4;
    }

    for (int i = tid; i < DOUT; i += 256) {
        bs_s[i] = bias[hb*DOUT + i];
        if (MODE == 1) qs_s[i] = d_QA[(size_t)(b*HDIM + hb)*DAH + i];
        if (MODE == 2) qs_s[i] = d_QP[(size_t)(b*HDIM + hb)*DPH + i];
    }

    float acc[2][NFN][4];
    #pragma unroll
    for (int mi = 0; mi < 2; mi++)
        #pragma unroll
        for (int ni = 0; ni < NFN; ni++)
            #pragma unroll
            for (int q = 0; q < 4; q++) acc[mi][ni][q] = 0.f;

    for (int ch = 0; ch < NCH; ch++) {
        int d0 = ch*KC;
        #pragma unroll
        for (int it = 0; it < TM*16/256; it++) {
            int e = it*256 + tid;
            int row = e >> 4, seg = e & 15;
            cpa16(xB + (row*RS + seg*4)*4, src + ((size_t)b*S + s0 + row)*DIN + d0 + seg*8);
        }
        for (int e = tid; e < DOUT*16; e += 256) {
            int rr = e >> 4, seg = e & 15;
            cpa16(wB + (rr*RS + seg*4)*4, W + ((size_t)(hb*DOUT + rr))*DIN + d0 + seg*8);
        }
        cpa_commit();
        cpa_wait0();
        __syncthreads();
        #pragma unroll
        for (int ps = 0; ps < 8; ps++) {
            uint32_t a[2][4];
            ldsm_x4(a[0], aAddr[0] + ps*32);
            ldsm_x4(a[1], aAddr[1] + ps*32);
            uint32_t bb[2*NFN];
            if (NFN == 1) {
                ldsm_x2(bb, bAddr[0] + ps*32);
            } else {
                #pragma unroll
                for (int pg = 0; pg < NFN/2; pg++)
                    ldsm_x4(bb + pg*4, bAddr[pg] + ps*32);
            }
            #pragma unroll
            for (int ni = 0; ni < NFN; ni++) {
                uint32_t b0 = bb[2*ni], b1 = bb[2*ni + 1];
                #pragma unroll
                for (int mi = 0; mi < 2; mi++) mma_bf16(acc[mi][ni], a[mi], b0, b1);
            }
        }
        if (ch + 1 < NCH) __syncthreads();
    }

    // ---- epilogue: bias + per-row per-head l2 norm ----
    float sl[2] = {0.f, 0.f}, sh[2] = {0.f, 0.f};
    #pragma unroll
    for (int mi = 0; mi < 2; mi++)
        #pragma unroll
        for (int ni = 0; ni < NFN; ni++) {
            int c0 = cb + ni*8 + 2*tig, c1 = c0 + 1;
            acc[mi][ni][0] += bs_s[c0];
            acc[mi][ni][1] += bs_s[c1];
            acc[mi][ni][2] += bs_s[c0];
            acc[mi][ni][3] += bs_s[c1];
            sl[mi] += acc[mi][ni][0]*acc[mi][ni][0] + acc[mi][ni][1]*acc[mi][ni][1];
            sh[mi] += acc[mi][ni][2]*acc[mi][ni][2] + acc[mi][ni][3]*acc[mi][ni][3];
        }
    #pragma unroll
    for (int mi = 0; mi < 2; mi++) {
        sl[mi] += __shfl_xor_sync(0xffffffffu, sl[mi], 1);
        sl[mi] += __shfl_xor_sync(0xffffffffu, sl[mi], 2);
        sh[mi] += __shfl_xor_sync(0xffffffffu, sh[mi], 1);
        sh[mi] += __shfl_xor_sync(0xffffffffu, sh[mi], 2);
    }
    if (HPB == 1) {
        // cross-warp (warp_n pair) reduce: warp covers half the head
        __syncthreads();
        if (tig == 0) {
            #pragma unroll
            for (int mi = 0; mi < 2; mi++) {
                int rl = rb + mi*16 + g;
                red_s[rl*2 + warp_n] = sl[mi];
                red_s[(rl+8)*2 + warp_n] = sh[mi];
            }
        }
        __syncthreads();
        #pragma unroll
        for (int mi = 0; mi < 2; mi++) {
            int rl = rb + mi*16 + g;
            sl[mi] = red_s[rl*2] + red_s[rl*2+1];
            sh[mi] = red_s[(rl+8)*2] + red_s[(rl+8)*2+1];
        }
    }
    float il[2], ih[2];
    #pragma unroll
    for (int mi = 0; mi < 2; mi++) {
        il[mi] = 1.f / fmaxf(sqrtf(sl[mi]), 1e-12f);
        ih[mi] = 1.f / fmaxf(sqrtf(sh[mi]), 1e-12f);
    }

    if (MODE == 0) {
        // HPB == 2: warp_n is the local head; cols within head = ni*8 + 2*tig
        int bh_out = b*HDIM + hb*HPB + warp_n;
        #pragma unroll
        for (int mi = 0; mi < 2; mi++) {
            int rl = rb + mi*16 + g;
            size_t base_l = ((size_t)bh_out*S + s0 + rl)*DK;
            size_t base_h = ((size_t)bh_out*S + s0 + rl + 8)*DK;
            #pragma unroll
            for (int ni = 0; ni < NFN; ni++) {
                int c0 = ni*8 + 2*tig;
                *(uint32_t*)&d_Knbf[base_l + c0] = packbf(acc[mi][ni][0]*il[mi], acc[mi][ni][1]*il[mi]);
                *(uint32_t*)&d_Knbf[base_h + c0] = packbf(acc[mi][ni][2]*ih[mi], acc[mi][ni][3]*ih[mi]);
            }
        }
    } else {
        float* dst = (MODE == 1) ? d_dot2 : d_dot3;
        int bh = b*HDIM + hb;
        float dl[2], dh[2];
        #pragma unroll
        for (int mi = 0; mi < 2; mi++) {
            dl[mi] = 0.f; dh[mi] = 0.f;
            #pragma unroll
            for (int ni = 0; ni < NFN; ni++) {
                int c0 = cb + ni*8 + 2*tig, c1 = c0 + 1;
                dl[mi] += acc[mi][ni][0]*qs_s[c0] + acc[mi][ni][1]*qs_s[c1];
                dh[mi] += acc[mi][ni][2]*qs_s[c0] + acc[mi][ni][3]*qs_s[c1];
            }
            dl[mi] += __shfl_xor_sync(0xffffffffu, dl[mi], 1);
            dl[mi] += __shfl_xor_sync(0xffffffffu, dl[mi], 2);
            dh[mi] += __shfl_xor_sync(0xffffffffu, dh[mi], 1);
            dh[mi] += __shfl_xor_sync(0xffffffffu, dh[mi], 2);
        }
        __syncthreads();
        if (tig == 0) {
            #pragma unroll
            for (int mi = 0; mi < 2; mi++) {
                int rl = rb + mi*16 + g;
                red_s[rl*2 + warp_n] = dl[mi];
                red_s[(rl+8)*2 + warp_n] = dh[mi];
            }
        }
        __syncthreads();
        if (warp_n == 0 && tig == 0) {
            #pragma unroll
            for (int mi = 0; mi < 2; mi++) {
                int rl = rb + mi*16 + g;
                float DL = red_s[rl*2] + red_s[rl*2+1];
                float DH = red_s[(rl+8)*2] + red_s[(rl+8)*2+1];
                int wl = s0 + rl - 31, wh = wl + 8;
                if (wl >= 0 && wl < Wn) dst[(size_t)bh*S + wl] = DL*il[mi];
                if (wh >= 0 && wh < Wn) dst[(size_t)bh*S + wh] = DH*ih[mi];
            }
        }
    }
}

// ---------------- banded Qv . Kn -> tn  (bf16 mma) ----------------
__global__ void __launch_bounds__(128) band_mma_kernel(int S, int Wn) {
    constexpr int RS = 36;
    __shared__ uint32_t Qs[32*RS];
    __shared__ uint32_t Ks[96*RS];
    __shared__ float Ps[32*100];
    int tid = threadIdx.x;
    int lane = tid & 31, wid = tid >> 5;
    int g = lane >> 2, tig = lane & 3;
    int w0 = blockIdx.x*64, h = blockIdx.y, b = blockIdx.z;
    int bh = b*HDIM + h;

    uint32_t qB = (uint32_t)__cvta_generic_to_shared(Qs);
    uint32_t kB = (uint32_t)__cvta_generic_to_shared(Ks);

    for (int e = tid; e < 96*8; e += 128) {
        int r = e >> 3, seg = e & 7;
        int s = w0 + r;
        if (s < S) cpa16(kB + (r*RS + seg*4)*4, d_Knbf + ((size_t)bh*S + s)*DK + seg*8);
        else {
            uint32_t* p = &Ks[r*RS + seg*4];
            p[0] = 0; p[1] = 0; p[2] = 0; p[3] = 0;
        }
    }
    for (int e = tid; e < 32*8; e += 128) {
        int r = e >> 3, seg = e & 7;
        cpa16(qB + (r*RS + seg*4)*4, d_Qvbf + ((size_t)bh*MDIM + r)*DK + seg*8);
    }
    cpa_commit();
    cpa_wait0();
    __syncthreads();

    float acc[2][3][4];
    #pragma unroll
    for (int mi = 0; mi < 2; mi++)
        #pragma unroll
        for (int ni = 0; ni < 3; ni++)
            #pragma unroll
            for (int q = 0; q < 4; q++) acc[mi][ni][q] = 0.f;
    int nb = wid*24;
    #pragma unroll
    for (int ks = 0; ks < 4; ks++) {
        int p0 = ks*8;
        uint32_t a[2][4];
        #pragma unroll
        for (int mi = 0; mi < 2; mi++) {
            int r = mi*16 + g;
            a[mi][0] = Qs[r*RS + p0 + tig];
            a[mi][1] = Qs[(r+8)*RS + p0 + tig];
            a[mi][2] = Qs[r*RS + p0 + tig + 4];
            a[mi][3] = Qs[(r+8)*RS + p0 + tig + 4];
        }
        #pragma unroll
        for (int ni = 0; ni < 3; ni++) {
            int cn = nb + ni*8 + g;
            uint32_t b0 = Ks[cn*RS + p0 + tig];
            uint32_t b1 = Ks[cn*RS + p0 + tig + 4];
            #pragma unroll
            for (int mi = 0; mi < 2; mi++) mma_bf16(acc[mi][ni], a[mi], b0, b1);
        }
    }
    #pragma unroll
    for (int mi = 0; mi < 2; mi++)
        #pragma unroll
        for (int ni = 0; ni < 3; ni++) {
            int c0 = nb + ni*8 + 2*tig;
            int r = mi*16 + g;
            Ps[r*100 + c0]     = acc[mi][ni][0];
            Ps[r*100 + c0 + 1] = acc[mi][ni][1];
            Ps[(r+8)*100 + c0]     = acc[mi][ni][2];
            Ps[(r+8)*100 + c0 + 1] = acc[mi][ni][3];
        }
    __syncthreads();
    if (tid < 64) {
        int w = w0 + tid;
        if (w < Wn) {
            float s = 0.f;
            #pragma unroll
            for (int m = 0; m < 32; m++) s += Ps[m*100 + tid + m];
            d_tn[(size_t)bh*S + w] = s*(1.f/32.f);
        }
    }
}

// ---------------- QA / QP (last-row queries, fp32) ----------------
__global__ void qa_kernel(const float* __restrict__ aux, const float* __restrict__ Wqa,
                          const float* __restrict__ bqa, int S) {
    int h = blockIdx.x & 7, b = blockIdx.x >> 3;
    int c = threadIdx.x;  // 32
    const float* ar = aux + ((size_t)b*S + (S-1))*DA;
    const float* wr = Wqa + ((size_t)h*DAH + c)*DA;
    float acc = bqa[h*DAH + c];
    #pragma unroll 4
    for (int d = 0; d < DA; d++) acc += ar[d]*wr[d];
    float v = acc*acc;
    for (int o = 16; o; o >>= 1) v += __shfl_xor_sync(0xffffffffu, v, o);
    float inv = 1.f / fmaxf(sqrtf(v), 1e-12f);
    d_QA[((size_t)b*HDIM + h)*DAH + c] = acc*inv;
}

__global__ void qp_kernel(const float* __restrict__ pos, const float* __restrict__ Wqp,
                          const float* __restrict__ bqp, int S) {
    int h = blockIdx.x & 7, b = blockIdx.x >> 3;
    int lane = threadIdx.x;   // 32
    int c = lane & 15;
    const float* pr = pos + ((size_t)b*S + (S-1))*DP;
    const float* wr = Wqp + ((size_t)h*DPH + c)*DP;
    float acc = bqp[h*DPH + c];
    #pragma unroll 4
    for (int d = 0; d < DP; d++) acc += pr[d]*wr[d];
    float v = acc*acc;
    for (int o = 8; o; o >>= 1) v += __shfl_xor_sync(0xffffffffu, v, o);
    float inv = 1.f / fmaxf(sqrtf(v), 1e-12f);
    if (lane < 16) d_QP[((size_t)b*HDIM + h)*DPH + c] = acc*inv;
}

// ---------------- softmax over Wn ----------------
__global__ void softmax_kernel(const float* __restrict__ w1, const float* __restrict__ w2,
                               const float* __restrict__ w3, int S, int Wn) {
    int bh = blockIdx.x, t = threadIdx.x;   // 256
    __shared__ float red[8];
    __shared__ float sval;
    float c1 = w1[0], c2 = w2[0], c3 = w3[0];
    size_t base = (size_t)bh*S;
    float mx = -1e30f;
    for (int i = t; i < Wn; i += 256) {
        float l = c1*d_tn[base+i] + c2*d_dot2[base+i] + c3*d_dot3[base+i];
        d_attn[base+i] = l;
        mx = fmaxf(mx, l);
    }
    for (int o = 16; o; o >>= 1) mx = fmaxf(mx, __shfl_xor_sync(0xffffffffu, mx, o));
    if ((t & 31) == 0) red[t >> 5] = mx;
    __syncthreads();
    if (t == 0) { float m = red[0]; for (int i = 1; i < 8; i++) m = fmaxf(m, red[i]); sval = m; }
    __syncthreads();
    float MX = sval, sum = 0.f;
    for (int i = t; i < Wn; i += 256) {
        float e = __expf(d_attn[base+i] - MX);
        d_attn[base+i] = e;
        sum += e;
    }
    for (int o = 16; o; o >>= 1) sum += __shfl_xor_sync(0xffffffffu, sum, o);
    __syncthreads();
    if ((t & 31) == 0) red[t >> 5] = sum;
    __syncthreads();
    if (t == 0) { float m = 0.f; for (int i = 0; i < 8; i++) m += red[i]; sval = m; }
    __syncthreads();
    float inv = 1.f / sval;
    for (int i = t; i < Wn; i += 256) {
        float a = d_attn[base+i]*inv;
        d_attn[base+i] = a;
        if (i == Wn-1) d_alast[bh] = a;
    }
}

// ---------------- xbar: attn-weighted row sums of x (bf16 X) ----------------
__global__ void xbar_kernel(int S, int Wn) {
    __shared__ float a_s[8][64];
    int t = threadIdx.x;                 // 256
    int w0 = blockIdx.x*64, b = blockIdx.y;
    for (int i = t; i < 512; i += 256) {
        int hh = i >> 6, j = i & 63;
        int w = w0 + j;
        a_s[hh][j] = (w < Wn-1) ? d_attn[((size_t)b*HDIM + hh)*S + w] : 0.f;
    }
    __syncthreads();
    float acc[8][2];
    #pragma unroll
    for (int h = 0; h < 8; h++) { acc[h][0] = 0.f; acc[h][1] = 0.f; }
    int nrow = Wn - 1 - w0; if (nrow > 64) nrow = 64;
    for (int j = 0; j < nrow; j++) {
        const __nv_bfloat16* xr = d_Xbf + ((size_t)b*S + (31 + w0 + j))*DM;
        float x0 = __bfloat162float(xr[t]);
        float x1 = __bfloat162float(xr[256 + t]);
        #pragma unroll
        for (int h = 0; h < 8; h++) {
            float a = a_s[h][j];
            acc[h][0] += a*x0;
            acc[h][1] += a*x1;
        }
    }
    #pragma unroll
    for (int h = 0; h < 8; h++) {
        atomicAdd(&d_xbar[((size_t)b*HDIM + h)*DM + t], acc[h][0]);
        atomicAdd(&d_xbar[((size_t)b*HDIM + h)*DM + 256 + t], acc[h][1]);
    }
}

// ---------------- GRU ----------------
__global__ void gi_kernel(const float* __restrict__ memory, const float* __restrict__ b_ih,
                          int S) {
    int tt = blockIdx.x, b = blockIdx.y;
    __shared__ float xs[DM];
    int s = S - MDIM + tt;
    const float* row = memory + ((size_t)b*(S-1) + s)*DM;
    for (int i = threadIdx.x; i < DM; i += 192) xs[i] = row[i];
    __syncthreads();
    int j = threadIdx.x;
    float acc = b_ih[j];
    #pragma unroll 8
    for (int d = 0; d < DM; d++) acc += xs[d]*d_WihT[d*192 + j];
    d_gi[((size_t)b*31 + tt)*192 + j] = acc;
}

__global__ void gru_kernel(const float* __restrict__ b_hh) {
    int b = blockIdx.x, j = threadIdx.x;  // 192
    __shared__ float hs[DK];
    __shared__ float gh_s[192];
    if (j < DK) hs[j] = 0.f;
    __syncthreads();
    float bh = b_hh[j];
    for (int t = 0; t < 31; t++) {
        float gh = bh;
        #pragma unroll 8
        for (int k2 = 0; k2 < DK; k2++) gh += hs[k2]*d_WhhT[k2*192 + j];
        gh_s[j] = gh;
        __syncthreads();
        float hn = 0.f;
        if (j < DK) {
            const float* gi = d_gi + ((size_t)b*31 + t)*192;
            float r = 1.f/(1.f + __expf(-(gi[j] + gh_s[j])));
            float z = 1.f/(1.f + __expf(-(gi[64 + j] + gh_s[64 + j])));
            float n = tanhf(gi[128 + j] + r*gh_s[128 + j]);
            hn = (1.f - z)*n + z*hs[j];
        }
        __syncthreads();
        if (j < DK) hs[j] = hn;
        __syncthreads();
    }
    if (j < DK) d_res[b*DK + j] = hs[j];
}

// ---------------- fused: deta = xbar@WvM^T + bv*(1-alast) + alast*res;  out = x_pre + deta@WOM^T + bO
__global__ void __launch_bounds__(512) detaout_kernel(const float* __restrict__ bv,
                               const float* __restrict__ x_pre, const float* __restrict__ bO,
                               float* __restrict__ out) {
    int b = blockIdx.x, t = threadIdx.x;  // 512
    __shared__ float xb[8][DM];
    __shared__ float dd[DM];
    for (int i = t; i < 8*DM; i += 512)
        xb[i >> 9][i & 511] = d_xbar[(size_t)(b*HDIM + (i >> 9))*DM + (i & 511)];
    __syncthreads();
    int h = t >> 6, c = t & 63;
    const float* wt = d_WvMT + (size_t)h*DM*DK;
    float acc = 0.f;
    #pragma unroll 8
    for (int d = 0; d < DM; d++) acc += xb[h][d]*wt[d*DK + c];
    float al = d_alast[b*HDIM + h];
    dd[t] = acc + bv[h*DK + c]*(1.f - al) + al*d_res[b*DK + c];
    __syncthreads();
    float o = bO[t];
    #pragma unroll 8
    for (int i = 0; i < DM; i++) o += dd[i]*d_WOMT[(size_t)i*DM + t];
    out[(size_t)b*DM + t] = x_pre[(size_t)b*DM + t] + o;
}

extern "C" void kernel_launch(void* const* d_in, const int* in_sizes, int n_in,
                              void* d_out, int out_size) {
    const float* memory = (const float*)d_in[0];
    const float* x_pre  = (const float*)d_in[1];
    const float* aux    = (const float*)d_in[2];
    const float* pos    = (const float*)d_in[3];
    const float* Wq  = (const float*)d_in[4];
    const float* bq  = (const float*)d_in[5];
    const float* Wk  = (const float*)d_in[6];
    const float* bk  = (const float*)d_in[7];
    const float* Wv  = (const float*)d_in[8];
    const float* bv  = (const float*)d_in[9];
    const float* Wqa = (const float*)d_in[10];
    const float* bqa = (const float*)d_in[11];
    const float* Wka = (const float*)d_in[12];
    const float* bka = (const float*)d_in[13];
    const float* Wqp = (const float*)d_in[14];
    const float* bqp = (const float*)d_in[15];
    const float* Wkp = (const float*)d_in[16];
    const float* bkp = (const float*)d_in[17];
    const float* W_ih = (const float*)d_in[18];
    const float* W_hh = (const float*)d_in[19];
    const float* b_ih = (const float*)d_in[20];
    const float* b_hh = (const float*)d_in[21];
    const float* WO = (const float*)d_in[22];
    const float* bO = (const float*)d_in[23];
    const float* w   = (const float*)d_in[24];
    const float* w_a = (const float*)d_in[25];
    const float* w_p = (const float*)d_in[26];
    const int* G = (const int*)d_in[27];
    float* out = (float*)d_out;

    int S  = in_sizes[2] / (BDIM*DA);   // 6144
    int Wn = S - MDIM + 1;              // 6113

    __nv_bfloat16 *Xbf_p, *Abf_p, *Pbf_p, *WkMbf_p, *Wkabf_p, *Wkpbf_p;
    cudaGetSymbolAddress((void**)&Xbf_p, d_Xbf);
    cudaGetSymbolAddress((void**)&Abf_p, d_Abf);
    cudaGetSymbolAddress((void**)&Pbf_p, d_Pbf);
    cudaGetSymbolAddress((void**)&WkMbf_p, d_WkMbf);
    cudaGetSymbolAddress((void**)&Wkabf_p, d_Wkabf);
    cudaGetSymbolAddress((void**)&Wkpbf_p, d_Wkpbf);

    const int smem_k = (128*68 + 128*68)*4;   // 69632
    const int smem_a = (128*68 + DAH*68)*4;   // 43520
    const int smem_p = (128*68 + DPH*68)*4;   // 39168
    cudaFuncSetAttribute(proj_mma_kernel<DM, 128, 0, 2>,
                         cudaFuncAttributeMaxDynamicSharedMemorySize, smem_k);
    cudaFuncSetAttribute(proj_mma_kernel<DA, DAH, 1, 1>,
                         cudaFuncAttributeMaxDynamicSharedMemorySize, smem_a);
    cudaFuncSetAttribute(proj_mma_kernel<DP, DPH, 2, 1>,
                         cudaFuncAttributeMaxDynamicSharedMemorySize, smem_p);

    convert_kernel<<<4096, 256>>>(memory, x_pre, aux, pos, S);
    mask_kernel<<<1024, 256>>>(Wq, Wk, Wv, WO, W_ih, W_hh, Wka, Wkp, G);
    qv_kernel<<<BDIM*HDIM*8, 256>>>(memory, x_pre, bq, S);
    proj_mma_kernel<DM, 128, 0, 2><<<dim3(S/128, HDIM/2, BDIM), 256, smem_k>>>(Xbf_p, WkMbf_p, bk, S, Wn);
    band_mma_kernel<<<dim3((Wn + 63)/64, HDIM, BDIM), 128>>>(S, Wn);
    qa_kernel<<<BDIM*HDIM, 32>>>(aux, Wqa, bqa, S);
    proj_mma_kernel<DA, DAH, 1, 1><<<dim3(S/128, HDIM, BDIM), 256, smem_a>>>(Abf_p, Wkabf_p, bka, S, Wn);
    qp_kernel<<<BDIM*HDIM, 32>>>(pos, Wqp, bqp, S);
    proj_mma_kernel<DP, DPH, 2, 1><<<dim3(S/128, HDIM, BDIM), 256, smem_p>>>(Pbf_p, Wkpbf_p, bkp, S, Wn);
    softmax_kernel<<<BDIM*HDIM, 256>>>(w, w_a, w_p, S, Wn);
    xbar_kernel<<<dim3((Wn - 1 + 63)/64, BDIM), 256>>>(S, Wn);
    gi_kernel<<<dim3(31, BDIM), 192>>>(memory, b_ih, S);
    gru_kernel<<<BDIM, 192>>>(b_hh);
    detaout_kernel<<<BDIM, 512>>>(bv, x_pre, bO, out);
}

// round 14
// speedup vs baseline: 2.4529x; 1.0676x over previous
#include <cuda_runtime.h>
#include <cuda_bf16.h>
#include <math.h>
#include <stdint.h>
#include <stddef.h>

// fixed problem shapes
#define BDIM 8
#define HDIM 8
#define DM 512
#define DA 256
#define DP 128
#define MDIM 32
#define DK 64
#define DAH 32
#define DPH 16
#define SDIM 6144

// ---------------- device scratch ----------------
__device__ __nv_bfloat16 d_Xbf[(size_t)BDIM*SDIM*DM];
__device__ __nv_bfloat16 d_Abf[(size_t)BDIM*SDIM*DA];
__device__ __nv_bfloat16 d_Pbf[(size_t)BDIM*SDIM*DP];
__device__ __nv_bfloat16 d_WkMbf[HDIM*DK*DM];
__device__ __nv_bfloat16 d_Wkabf[HDIM*DAH*DA];
__device__ __nv_bfloat16 d_Wkpbf[HDIM*DPH*DP];
__device__ float d_WqMT[HDIM*DM*DK];   // [h][d][c]
__device__ float d_WvMT[HDIM*DM*DK];   // [h][d][c]
__device__ float d_WOMT[DM*DM];        // [i][j] = WOM[j][i]
__device__ float d_WihT[DM*192];       // [d][j]
__device__ float d_WhhT[DK*192];       // [k][j]
__device__ __nv_bfloat16 d_Knbf[(size_t)BDIM*HDIM*SDIM*DK];  // ~50 MB
__device__ __nv_bfloat16 d_Qvbf[BDIM*HDIM*MDIM*DK];
__device__ float d_QA[BDIM*HDIM*DAH];
__device__ float d_QP[BDIM*HDIM*DPH];
__device__ float d_tn[BDIM*HDIM*SDIM];
__device__ float d_dot2[BDIM*HDIM*SDIM];
__device__ float d_dot3[BDIM*HDIM*SDIM];
__device__ float d_attn[BDIM*HDIM*SDIM];
__device__ float d_alast[BDIM*HDIM];
__device__ float d_xbar[BDIM*HDIM*DM];
__device__ float d_gi[BDIM*31*192];
__device__ float d_res[BDIM*DK];

__device__ __forceinline__ void mma_bf16(float* c, const uint32_t* a, uint32_t b0, uint32_t b1) {
    asm volatile("mma.sync.aligned.m16n8k16.row.col.f32.bf16.bf16.f32 "
        "{%0,%1,%2,%3}, {%4,%5,%6,%7}, {%8,%9}, {%0,%1,%2,%3};\n"
        : "+f"(c[0]), "+f"(c[1]), "+f"(c[2]), "+f"(c[3])
        : "r"(a[0]), "r"(a[1]), "r"(a[2]), "r"(a[3]), "r"(b0), "r"(b1));
}

__device__ __forceinline__ void ldsm_x4(uint32_t* r, uint32_t addr) {
    asm volatile("ldmatrix.sync.aligned.m8n8.x4.shared.b16 {%0,%1,%2,%3}, [%4];"
        : "=r"(r[0]), "=r"(r[1]), "=r"(r[2]), "=r"(r[3]) : "r"(addr));
}
__device__ __forceinline__ void ldsm_x2(uint32_t* r, uint32_t addr) {
    asm volatile("ldmatrix.sync.aligned.m8n8.x2.shared.b16 {%0,%1}, [%2];"
        : "=r"(r[0]), "=r"(r[1]) : "r"(addr));
}

__device__ __forceinline__ void cpa16(uint32_t saddr, const void* g) {
    asm volatile("cp.async.cg.shared.global [%0], [%1], 16;" :: "r"(saddr), "l"(g));
}
__device__ __forceinline__ void cpa_commit() { asm volatile("cp.async.commit_group;"); }
__device__ __forceinline__ void cpa_wait0() { asm volatile("cp.async.wait_group 0;" ::: "memory"); }

__device__ __forceinline__ uint32_t packbf(float a, float b) {
    __nv_bfloat162 t = __floats2bfloat162_rn(a, b);
    return *(uint32_t*)&t;
}

// ---------------- fp32 -> bf16 conversion (2D grid, shift indexing) ----------------
__global__ void __launch_bounds__(256) convert_kernel(
        const float* __restrict__ memory, const float* __restrict__ x_pre,
        const float* __restrict__ aux, const float* __restrict__ pos, int S) {
    int b = blockIdx.y;
    int stride = gridDim.x*256;
    int t0 = blockIdx.x*256 + threadIdx.x;
    // X: S*128 float4 groups per b; s = j>>7, d4 = (j&127)*4
    int nX = S << 7;
    const float* memB = memory + (size_t)b*(S-1)*DM;
    __nv_bfloat16* XB = d_Xbf + (size_t)b*S*DM;
    for (int j = t0; j < nX; j += stride) {
        int s = j >> 7, d4 = (j & 127) << 2;
        const float* src = (s < S-1) ? memB + ((size_t)s << 9) + d4 : x_pre + ((size_t)b << 9) + d4;
        float4 v = *(const float4*)src;
        uint2 o; o.x = packbf(v.x, v.y); o.y = packbf(v.z, v.w);
        *(uint2*)&XB[((size_t)s << 9) + d4] = o;
    }
    // aux: S*64 groups
    int nA = S << 6;
    const float* auxB = aux + (size_t)b*S*DA;
    __nv_bfloat16* AB = d_Abf + (size_t)b*S*DA;
    for (int j = t0; j < nA; j += stride) {
        float4 v = *(const float4*)(auxB + ((size_t)j << 2));
        uint2 o; o.x = packbf(v.x, v.y); o.y = packbf(v.z, v.w);
        *(uint2*)&AB[(size_t)j << 2] = o;
    }
    // pos: S*32 groups
    int nP = S << 5;
    const float* posB = pos + (size_t)b*S*DP;
    __nv_bfloat16* PB = d_Pbf + (size_t)b*S*DP;
    for (int j = t0; j < nP; j += stride) {
        float4 v = *(const float4*)(posB + ((size_t)j << 2));
        uint2 o; o.x = packbf(v.x, v.y); o.y = packbf(v.z, v.w);
        *(uint2*)&PB[(size_t)j << 2] = o;
    }
}

// ---------------- masked weights (+ transposes, bf16 copies) + zero xbar ----------------
__global__ void mask_kernel(const float* __restrict__ Wq, const float* __restrict__ Wk,
                            const float* __restrict__ Wv, const float* __restrict__ WO,
                            const float* __restrict__ W_ih, const float* __restrict__ W_hh,
                            const float* __restrict__ Wka, const float* __restrict__ Wkp,
                            const int* __restrict__ G) {
    int i = blockIdx.x*256 + threadIdx.x;
    const int NW = HDIM*DK*DM;
    if (i < NW) {
        int h = i >> 15;
        int c = (i >> 9) & 63;
        int d = i & 511;
        float g = (float)G[c*64 + (d & 63)];
        d_WkMbf[i] = __float2bfloat16(Wk[i]*g);
        d_WqMT[((size_t)h*DM + d)*DK + c] = Wq[i]*g;
        d_WvMT[((size_t)h*DM + d)*DK + c] = Wv[i]*g;
    }
    if (i < HDIM*DAH*DA) d_Wkabf[i] = __float2bfloat16(Wka[i]);
    if (i < HDIM*DPH*DP) d_Wkpbf[i] = __float2bfloat16(Wkp[i]);
    if (i < DM*DM) {
        int j = i & 511, r = i >> 9;
        d_WOMT[(size_t)j*DM + r] = WO[i]*(float)G[(r & 63)*64 + (j & 63)];
    }
    if (i < 192*DM) {
        int j = i >> 9, d = i & 511;
        d_WihT[d*192 + j] = W_ih[i];
    }
    if (i < 192*DK) {
        int j = i >> 6, k = i & 63;
        d_WhhT[k*192 + j] = W_hh[i];
    }
    if (i < BDIM*HDIM*DM) d_xbar[i] = 0.f;
}

// ---------------- Qv: last M rows (4 rows per block), masked proj + l2norm ----------------
__global__ void __launch_bounds__(256) qv_kernel(const float* __restrict__ memory,
                          const float* __restrict__ x_pre,
                          const float* __restrict__ bq, int S) {
    int mgrp = blockIdx.x & 7, h = (blockIdx.x >> 3) & 7, b = blockIdx.x >> 6;
    __shared__ float xs[4][DM];
    __shared__ float wp[4][2];
    int tid = threadIdx.x;
    int mg = tid >> 6, c = tid & 63;
    for (int i = tid; i < 4*DM; i += 256) {
        int r = i >> 9, d = i & 511;
        int s = S - MDIM + mgrp*4 + r;
        const float* row = (s < S-1) ? memory + ((size_t)b*(S-1) + s)*DM : x_pre + (size_t)b*DM;
        xs[r][d] = row[d];
    }
    __syncthreads();
    const float* wt = d_WqMT + (size_t)h*DM*DK;
    float acc = bq[h*DK + c];
    #pragma unroll 8
    for (int d = 0; d < DM; d++) acc += xs[mg][d]*wt[d*DK + c];
    float v = acc*acc;
    for (int o = 16; o; o >>= 1) v += __shfl_xor_sync(0xffffffffu, v, o);
    if ((tid & 31) == 0) wp[mg][(c >> 5)] = v;
    __syncthreads();
    float inv = 1.f / fmaxf(sqrtf(wp[mg][0] + wp[mg][1]), 1e-12f);
    int m = mgrp*4 + mg;
    d_Qvbf[(((size_t)b*HDIM + h)*MDIM + m)*DK + c] = __float2bfloat16(acc*inv);
}

// ---------------- tensor-core projection: 2 heads per block, warp_n = local head ----------------
// MODE 0: kproj (DOUT=128, 2x64) -> d_Knbf
// MODE 1: aux   (DOUT=64,  2x32) -> dot with QA -> d_dot2
// MODE 2: pos   (DOUT=32,  2x16) -> dot with QP -> d_dot3
template<int DIN, int DOUT, int MODE>
__global__ void __launch_bounds__(256)
proj_mma_kernel(const __nv_bfloat16* __restrict__ src, const __nv_bfloat16* __restrict__ W,
                const float* __restrict__ bias, int S, int Wn) {
    constexpr int NW_N = 2;
    constexpr int TM   = 128;
    constexpr int WT_N = DOUT/NW_N;      // cols per head: 64/32/16
    constexpr int NFN  = WT_N/8;         // 8/4/2
    constexpr int KC   = 128;
    constexpr int NCH  = DIN/KC;
    constexpr int RS   = 68;             // 272B row, 16B-aligned; 68%32==4 conflict-free

    extern __shared__ uint32_t dynsm[];
    uint32_t* Xs  = dynsm;               // TM*RS
    uint32_t* Wss = dynsm + TM*RS;       // DOUT*RS
    __shared__ float bs_s[DOUT];
    __shared__ float qs_s[DOUT];

    int tid = threadIdx.x;
    int lane = tid & 31, wid = tid >> 5;
    int g = lane >> 2, tig = lane & 3;
    int warp_n = wid % NW_N, warp_m = wid / NW_N;
    int rb = warp_m*32, cb = warp_n*WT_N;
    int s0 = blockIdx.x*TM, hb = blockIdx.y, b = blockIdx.z;

    uint32_t xB = (uint32_t)__cvta_generic_to_shared(Xs);
    uint32_t wB = (uint32_t)__cvta_generic_to_shared(Wss);

    uint32_t aAddr[2];
    #pragma unroll
    for (int mi = 0; mi < 2; mi++)
        aAddr[mi] = xB + ((rb + mi*16 + (lane & 7) + (lane & 8))*RS + ((lane >> 4) & 1)*4)*4;
    uint32_t bAddr[(NFN + 1)/2];
    #pragma unroll
    for (int pg = 0; pg < (NFN + 1)/2; pg++) {
        if (NFN == 1)
            bAddr[pg] = wB + ((cb + (lane & 7))*RS + ((lane >> 3) & 1)*4)*4;
        else
            bAddr[pg] = wB + ((cb + pg*16 + ((lane >> 4) & 1)*8 + (lane & 7))*RS + ((lane >> 3) & 1)*4)*4;
    }

    for (int i = tid; i < DOUT; i += 256) {
        bs_s[i] = bias[hb*DOUT + i];
        if (MODE == 1) qs_s[i] = d_QA[(size_t)(b*HDIM + hb*2 + (i >> 5))*DAH + (i & 31)];
        if (MODE == 2) qs_s[i] = d_QP[(size_t)(b*HDIM + hb*2 + (i >> 4))*DPH + (i & 15)];
    }

    float acc[2][NFN][4];
    #pragma unroll
    for (int mi = 0; mi < 2; mi++)
        #pragma unroll
        for (int ni = 0; ni < NFN; ni++)
            #pragma unroll
            for (int q = 0; q < 4; q++) acc[mi][ni][q] = 0.f;

    for (int ch = 0; ch < NCH; ch++) {
        int d0 = ch*KC;
        #pragma unroll
        for (int it = 0; it < TM*16/256; it++) {
            int e = it*256 + tid;
            int row = e >> 4, seg = e & 15;
            cpa16(xB + (row*RS + seg*4)*4, src + ((size_t)b*S + s0 + row)*DIN + d0 + seg*8);
        }
        for (int e = tid; e < DOUT*16; e += 256) {
            int rr = e >> 4, seg = e & 15;
            cpa16(wB + (rr*RS + seg*4)*4, W + ((size_t)(hb*DOUT + rr))*DIN + d0 + seg*8);
        }
        cpa_commit();
        cpa_wait0();
        __syncthreads();
        #pragma unroll
        for (int ps = 0; ps < 8; ps++) {
            uint32_t a[2][4];
            ldsm_x4(a[0], aAddr[0] + ps*32);
            ldsm_x4(a[1], aAddr[1] + ps*32);
            uint32_t bb[2*NFN];
            if (NFN == 1) {
                ldsm_x2(bb, bAddr[0] + ps*32);
            } else {
                #pragma unroll
                for (int pg = 0; pg < NFN/2; pg++)
                    ldsm_x4(bb + pg*4, bAddr[pg] + ps*32);
            }
            #pragma unroll
            for (int ni = 0; ni < NFN; ni++) {
                uint32_t b0 = bb[2*ni], b1 = bb[2*ni + 1];
                #pragma unroll
                for (int mi = 0; mi < 2; mi++) mma_bf16(acc[mi][ni], a[mi], b0, b1);
            }
        }
        if (ch + 1 < NCH) __syncthreads();
    }

    // ---- epilogue: bias + per-row per-head (per-warp) l2 norm ----
    float sl[2] = {0.f, 0.f}, sh[2] = {0.f, 0.f};
    #pragma unroll
    for (int mi = 0; mi < 2; mi++)
        #pragma unroll
        for (int ni = 0; ni < NFN; ni++) {
            int c0 = cb + ni*8 + 2*tig, c1 = c0 + 1;
            acc[mi][ni][0] += bs_s[c0];
            acc[mi][ni][1] += bs_s[c1];
            acc[mi][ni][2] += bs_s[c0];
            acc[mi][ni][3] += bs_s[c1];
            sl[mi] += acc[mi][ni][0]*acc[mi][ni][0] + acc[mi][ni][1]*acc[mi][ni][1];
            sh[mi] += acc[mi][ni][2]*acc[mi][ni][2] + acc[mi][ni][3]*acc[mi][ni][3];
        }
    #pragma unroll
    for (int mi = 0; mi < 2; mi++) {
        sl[mi] += __shfl_xor_sync(0xffffffffu, sl[mi], 1);
        sl[mi] += __shfl_xor_sync(0xffffffffu, sl[mi], 2);
        sh[mi] += __shfl_xor_sync(0xffffffffu, sh[mi], 1);
        sh[mi] += __shfl_xor_sync(0xffffffffu, sh[mi], 2);
    }
    float il[2], ih[2];
    #pragma unroll
    for (int mi = 0; mi < 2; mi++) {
        il[mi] = 1.f / fmaxf(sqrtf(sl[mi]), 1e-12f);
        ih[mi] = 1.f / fmaxf(sqrtf(sh[mi]), 1e-12f);
    }

    int bh_out = b*HDIM + hb*2 + warp_n;
    if (MODE == 0) {
        #pragma unroll
        for (int mi = 0; mi < 2; mi++) {
            int rl = rb + mi*16 + g;
            size_t base_l = ((size_t)bh_out*S + s0 + rl)*DK;
            size_t base_h = ((size_t)bh_out*S + s0 + rl + 8)*DK;
            #pragma unroll
            for (int ni = 0; ni < NFN; ni++) {
                int c0 = ni*8 + 2*tig;
                *(uint32_t*)&d_Knbf[base_l + c0] = packbf(acc[mi][ni][0]*il[mi], acc[mi][ni][1]*il[mi]);
                *(uint32_t*)&d_Knbf[base_h + c0] = packbf(acc[mi][ni][2]*ih[mi], acc[mi][ni][3]*ih[mi]);
            }
        }
    } else {
        float* dst = (MODE == 1) ? d_dot2 : d_dot3;
        float dl[2], dh[2];
        #pragma unroll
        for (int mi = 0; mi < 2; mi++) {
            dl[mi] = 0.f; dh[mi] = 0.f;
            #pragma unroll
            for (int ni = 0; ni < NFN; ni++) {
                int c0 = cb + ni*8 + 2*tig, c1 = c0 + 1;
                dl[mi] += acc[mi][ni][0]*qs_s[c0] + acc[mi][ni][1]*qs_s[c1];
                dh[mi] += acc[mi][ni][2]*qs_s[c0] + acc[mi][ni][3]*qs_s[c1];
            }
            dl[mi] += __shfl_xor_sync(0xffffffffu, dl[mi], 1);
            dl[mi] += __shfl_xor_sync(0xffffffffu, dl[mi], 2);
            dh[mi] += __shfl_xor_sync(0xffffffffu, dh[mi], 1);
            dh[mi] += __shfl_xor_sync(0xffffffffu, dh[mi], 2);
        }
        if (tig == 0) {
            #pragma unroll
            for (int mi = 0; mi < 2; mi++) {
                int rl = rb + mi*16 + g;
                int wl = s0 + rl - 31, wh = wl + 8;
                if (wl >= 0 && wl < Wn) dst[(size_t)bh_out*S + wl] = dl[mi]*il[mi];
                if (wh >= 0 && wh < Wn) dst[(size_t)bh_out*S + wh] = dh[mi]*ih[mi];
            }
        }
    }
}

// ---------------- banded Qv . Kn -> tn  (bf16 mma) ----------------
__global__ void __launch_bounds__(128) band_mma_kernel(int S, int Wn) {
    constexpr int RS = 36;
    __shared__ uint32_t Qs[32*RS];
    __shared__ uint32_t Ks[96*RS];
    __shared__ float Ps[32*100];
    int tid = threadIdx.x;
    int lane = tid & 31, wid = tid >> 5;
    int g = lane >> 2, tig = lane & 3;
    int w0 = blockIdx.x*64, h = blockIdx.y, b = blockIdx.z;
    int bh = b*HDIM + h;

    uint32_t qB = (uint32_t)__cvta_generic_to_shared(Qs);
    uint32_t kB = (uint32_t)__cvta_generic_to_shared(Ks);

    for (int e = tid; e < 96*8; e += 128) {
        int r = e >> 3, seg = e & 7;
        int s = w0 + r;
        if (s < S) cpa16(kB + (r*RS + seg*4)*4, d_Knbf + ((size_t)bh*S + s)*DK + seg*8);
        else {
            uint32_t* p = &Ks[r*RS + seg*4];
            p[0] = 0; p[1] = 0; p[2] = 0; p[3] = 0;
        }
    }
    for (int e = tid; e < 32*8; e += 128) {
        int r = e >> 3, seg = e & 7;
        cpa16(qB + (r*RS + seg*4)*4, d_Qvbf + ((size_t)bh*MDIM + r)*DK + seg*8);
    }
    cpa_commit();
    cpa_wait0();
    __syncthreads();

    float acc[2][3][4];
    #pragma unroll
    for (int mi = 0; mi < 2; mi++)
        #pragma unroll
        for (int ni = 0; ni < 3; ni++)
            #pragma unroll
            for (int q = 0; q < 4; q++) acc[mi][ni][q] = 0.f;
    int nb = wid*24;
    #pragma unroll
    for (int ks = 0; ks < 4; ks++) {
        int p0 = ks*8;
        uint32_t a[2][4];
        #pragma unroll
        for (int mi = 0; mi < 2; mi++) {
            int r = mi*16 + g;
            a[mi][0] = Qs[r*RS + p0 + tig];
            a[mi][1] = Qs[(r+8)*RS + p0 + tig];
            a[mi][2] = Qs[r*RS + p0 + tig + 4];
            a[mi][3] = Qs[(r+8)*RS + p0 + tig + 4];
        }
        #pragma unroll
        for (int ni = 0; ni < 3; ni++) {
            int cn = nb + ni*8 + g;
            uint32_t b0 = Ks[cn*RS + p0 + tig];
            uint32_t b1 = Ks[cn*RS + p0 + tig + 4];
            #pragma unroll
            for (int mi = 0; mi < 2; mi++) mma_bf16(acc[mi][ni], a[mi], b0, b1);
        }
    }
    #pragma unroll
    for (int mi = 0; mi < 2; mi++)
        #pragma unroll
        for (int ni = 0; ni < 3; ni++) {
            int c0 = nb + ni*8 + 2*tig;
            int r = mi*16 + g;
            Ps[r*100 + c0]     = acc[mi][ni][0];
            Ps[r*100 + c0 + 1] = acc[mi][ni][1];
            Ps[(r+8)*100 + c0]     = acc[mi][ni][2];
            Ps[(r+8)*100 + c0 + 1] = acc[mi][ni][3];
        }
    __syncthreads();
    if (tid < 64) {
        int w = w0 + tid;
        if (w < Wn) {
            float s = 0.f;
            #pragma unroll
            for (int m = 0; m < 32; m++) s += Ps[m*100 + tid + m];
            d_tn[(size_t)bh*S + w] = s*(1.f/32.f);
        }
    }
}

// ---------------- QA + QP fused (last-row queries, fp32) ----------------
__global__ void qaqp_kernel(const float* __restrict__ aux, const float* __restrict__ Wqa,
                            const float* __restrict__ bqa,
                            const float* __restrict__ pos, const float* __restrict__ Wqp,
                            const float* __restrict__ bqp, int S) {
    int h = blockIdx.x & 7, b = blockIdx.x >> 3;
    int t = threadIdx.x;  // 64
    if (t < 32) {
        int c = t;
        const float* ar = aux + ((size_t)b*S + (S-1))*DA;
        const float* wr = Wqa + ((size_t)h*DAH + c)*DA;
        float acc = bqa[h*DAH + c];
        #pragma unroll 4
        for (int d = 0; d < DA; d++) acc += ar[d]*wr[d];
        float v = acc*acc;
        for (int o = 16; o; o >>= 1) v += __shfl_xor_sync(0xffffffffu, v, o);
        float inv = 1.f / fmaxf(sqrtf(v), 1e-12f);
        d_QA[((size_t)b*HDIM + h)*DAH + c] = acc*inv;
    } else {
        int lane = t - 32;
        int c = lane & 15;
        const float* pr = pos + ((size_t)b*S + (S-1))*DP;
        const float* wr = Wqp + ((size_t)h*DPH + c)*DP;
        float acc = bqp[h*DPH + c];
        #pragma unroll 4
        for (int d = 0; d < DP; d++) acc += pr[d]*wr[d];
        float v = acc*acc;
        for (int o = 8; o; o >>= 1) v += __shfl_xor_sync(0xffffffffu, v, o);
        float inv = 1.f / fmaxf(sqrtf(v), 1e-12f);
        if (lane < 16) d_QP[((size_t)b*HDIM + h)*DPH + c] = acc*inv;
    }
}

// ---------------- online 2-pass softmax over Wn ----------------
__global__ void softmax_kernel(const float* __restrict__ w1, const float* __restrict__ w2,
                               const float* __restrict__ w3, int S, int Wn) {
    int bh = blockIdx.x, t = threadIdx.x;   // 256
    __shared__ float red_m[8], red_l[8];
    __shared__ float fm, fl;
    float c1 = w1[0], c2 = w2[0], c3 = w3[0];
    size_t base = (size_t)bh*S;
    // pass 1: online (max, sum)
    float m = -1e30f, l = 0.f;
    for (int i = t; i < Wn; i += 256) {
        float x = c1*d_tn[base+i] + c2*d_dot2[base+i] + c3*d_dot3[base+i];
        float mn = fmaxf(m, x);
        l = l*__expf(m - mn) + __expf(x - mn);
        m = mn;
    }
    for (int o = 16; o; o >>= 1) {
        float m2 = __shfl_xor_sync(0xffffffffu, m, o);
        float l2 = __shfl_xor_sync(0xffffffffu, l, o);
        float mn = fmaxf(m, m2);
        l = l*__expf(m - mn) + l2*__expf(m2 - mn);
        m = mn;
    }
    if ((t & 31) == 0) { red_m[t >> 5] = m; red_l[t >> 5] = l; }
    __syncthreads();
    if (t == 0) {
        float M = red_m[0], L = red_l[0];
        for (int i = 1; i < 8; i++) {
            float mn = fmaxf(M, red_m[i]);
            L = L*__expf(M - mn) + red_l[i]*__expf(red_m[i] - mn);
            M = mn;
        }
        fm = M; fl = L;
    }
    __syncthreads();
    float MX = fm, inv = 1.f/fl;
    for (int i = t; i < Wn; i += 256) {
        float x = c1*d_tn[base+i] + c2*d_dot2[base+i] + c3*d_dot3[base+i];
        float a = __expf(x - MX)*inv;
        d_attn[base+i] = a;
        if (i == Wn-1) d_alast[bh] = a;
    }
}

// ---------------- xbar: attn-weighted row sums of x (bf16 X) ----------------
__global__ void xbar_kernel(int S, int Wn) {
    __shared__ float a_s[8][64];
    int t = threadIdx.x;                 // 256
    int w0 = blockIdx.x*64, b = blockIdx.y;
    for (int i = t; i < 512; i += 256) {
        int hh = i >> 6, j = i & 63;
        int w = w0 + j;
        a_s[hh][j] = (w < Wn-1) ? d_attn[((size_t)b*HDIM + hh)*S + w] : 0.f;
    }
    __syncthreads();
    float acc[8][2];
    #pragma unroll
    for (int h = 0; h < 8; h++) { acc[h][0] = 0.f; acc[h][1] = 0.f; }
    int nrow = Wn - 1 - w0; if (nrow > 64) nrow = 64;
    for (int j = 0; j < nrow; j++) {
        const __nv_bfloat16* xr = d_Xbf + ((size_t)b*S + (31 + w0 + j))*DM;
        float x0 = __bfloat162float(xr[t]);
        float x1 = __bfloat162float(xr[256 + t]);
        #pragma unroll
        for (int h = 0; h < 8; h++) {
            float a = a_s[h][j];
            acc[h][0] += a*x0;
            acc[h][1] += a*x1;
        }
    }
    #pragma unroll
    for (int h = 0; h < 8; h++) {
        atomicAdd(&d_xbar[((size_t)b*HDIM + h)*DM + t], acc[h][0]);
        atomicAdd(&d_xbar[((size_t)b*HDIM + h)*DM + 256 + t], acc[h][1]);
    }
}

// ---------------- GRU ----------------
__global__ void gi_kernel(const float* __restrict__ memory, const float* __restrict__ b_ih,
                          int S) {
    int tt = blockIdx.x, b = blockIdx.y;
    __shared__ float xs[DM];
    int s = S - MDIM + tt;
    const float* row = memory + ((size_t)b*(S-1) + s)*DM;
    for (int i = threadIdx.x; i < DM; i += 192) xs[i] = row[i];
    __syncthreads();
    int j = threadIdx.x;
    float acc = b_ih[j];
    #pragma unroll 8
    for (int d = 0; d < DM; d++) acc += xs[d]*d_WihT[d*192 + j];
    d_gi[((size_t)b*31 + tt)*192 + j] = acc;
}

__global__ void gru_kernel(const float* __restrict__ b_hh) {
    int b = blockIdx.x, j = threadIdx.x;  // 192
    __shared__ float hs[DK];
    __shared__ float gh_s[192];
    if (j < DK) hs[j] = 0.f;
    __syncthreads();
    float bh = b_hh[j];
    for (int t = 0; t < 31; t++) {
        float gh = bh;
        #pragma unroll 8
        for (int k2 = 0; k2 < DK; k2++) gh += hs[k2]*d_WhhT[k2*192 + j];
        gh_s[j] = gh;
        __syncthreads();
        float hn = 0.f;
        if (j < DK) {
            const float* gi = d_gi + ((size_t)b*31 + t)*192;
            float r = 1.f/(1.f + __expf(-(gi[j] + gh_s[j])));
            float z = 1.f/(1.f + __expf(-(gi[64 + j] + gh_s[64 + j])));
            float n = tanhf(gi[128 + j] + r*gh_s[128 + j]);
            hn = (1.f - z)*n + z*hs[j];
        }
        __syncthreads();
        if (j < DK) hs[j] = hn;
        __syncthreads();
    }
    if (j < DK) d_res[b*DK + j] = hs[j];
}

// ---------------- fused deta + out ----------------
__global__ void __launch_bounds__(512) detaout_kernel(const float* __restrict__ bv,
                               const float* __restrict__ x_pre, const float* __restrict__ bO,
                               float* __restrict__ out) {
    int b = blockIdx.x, t = threadIdx.x;  // 512
    __shared__ float xb[8][DM];
    __shared__ float dd[DM];
    for (int i = t; i < 8*DM; i += 512)
        xb[i >> 9][i & 511] = d_xbar[(size_t)(b*HDIM + (i >> 9))*DM + (i & 511)];
    __syncthreads();
    int h = t >> 6, c = t & 63;
    const float* wt = d_WvMT + (size_t)h*DM*DK;
    float acc = 0.f;
    #pragma unroll 8
    for (int d = 0; d < DM; d++) acc += xb[h][d]*wt[d*DK + c];
    float al = d_alast[b*HDIM + h];
    dd[t] = acc + bv[h*DK + c]*(1.f - al) + al*d_res[b*DK + c];
    __syncthreads();
    float o = bO[t];
    #pragma unroll 8
    for (int i = 0; i < DM; i++) o += dd[i]*d_WOMT[(size_t)i*DM + t];
    out[(size_t)b*DM + t] = x_pre[(size_t)b*DM + t] + o;
}

extern "C" void kernel_launch(void* const* d_in, const int* in_sizes, int n_in,
                              void* d_out, int out_size) {
    const float* memory = (const float*)d_in[0];
    const float* x_pre  = (const float*)d_in[1];
    const float* aux    = (const float*)d_in[2];
    const float* pos    = (const float*)d_in[3];
    const float* Wq  = (const float*)d_in[4];
    const float* bq  = (const float*)d_in[5];
    const float* Wk  = (const float*)d_in[6];
    const float* bk  = (const float*)d_in[7];
    const float* Wv  = (const float*)d_in[8];
    const float* bv  = (const float*)d_in[9];
    const float* Wqa = (const float*)d_in[10];
    const float* bqa = (const float*)d_in[11];
    const float* Wka = (const float*)d_in[12];
    const float* bka = (const float*)d_in[13];
    const float* Wqp = (const float*)d_in[14];
    const float* bqp = (const float*)d_in[15];
    const float* Wkp = (const float*)d_in[16];
    const float* bkp = (const float*)d_in[17];
    const float* W_ih = (const float*)d_in[18];
    const float* W_hh = (const float*)d_in[19];
    const float* b_ih = (const float*)d_in[20];
    const float* b_hh = (const float*)d_in[21];
    const float* WO = (const float*)d_in[22];
    const float* bO = (const float*)d_in[23];
    const float* w   = (const float*)d_in[24];
    const float* w_a = (const float*)d_in[25];
    const float* w_p = (const float*)d_in[26];
    const int* G = (const int*)d_in[27];
    float* out = (float*)d_out;

    int S  = in_sizes[2] / (BDIM*DA);   // 6144
    int Wn = S - MDIM + 1;              // 6113

    __nv_bfloat16 *Xbf_p, *Abf_p, *Pbf_p, *WkMbf_p, *Wkabf_p, *Wkpbf_p;
    cudaGetSymbolAddress((void**)&Xbf_p, d_Xbf);
    cudaGetSymbolAddress((void**)&Abf_p, d_Abf);
    cudaGetSymbolAddress((void**)&Pbf_p, d_Pbf);
    cudaGetSymbolAddress((void**)&WkMbf_p, d_WkMbf);
    cudaGetSymbolAddress((void**)&Wkabf_p, d_Wkabf);
    cudaGetSymbolAddress((void**)&Wkpbf_p, d_Wkpbf);

    const int smem_k = (128 + 128)*68*4;   // 69632
    const int smem_a = (128 + 64)*68*4;    // 52224
    const int smem_p = (128 + 32)*68*4;    // 43520
    cudaFuncSetAttribute(proj_mma_kernel<DM, 128, 0>,
                         cudaFuncAttributeMaxDynamicSharedMemorySize, smem_k);
    cudaFuncSetAttribute(proj_mma_kernel<DA, 64, 1>,
                         cudaFuncAttributeMaxDynamicSharedMemorySize, smem_a);
    cudaFuncSetAttribute(proj_mma_kernel<DP, 32, 2>,
                         cudaFuncAttributeMaxDynamicSharedMemorySize, smem_p);

    convert_kernel<<<dim3(512, BDIM), 256>>>(memory, x_pre, aux, pos, S);
    mask_kernel<<<1024, 256>>>(Wq, Wk, Wv, WO, W_ih, W_hh, Wka, Wkp, G);
    qv_kernel<<<BDIM*HDIM*8, 256>>>(memory, x_pre, bq, S);
    proj_mma_kernel<DM, 128, 0><<<dim3(S/128, HDIM/2, BDIM), 256, smem_k>>>(Xbf_p, WkMbf_p, bk, S, Wn);
    band_mma_kernel<<<dim3((Wn + 63)/64, HDIM, BDIM), 128>>>(S, Wn);
    qaqp_kernel<<<BDIM*HDIM, 64>>>(aux, Wqa, bqa, pos, Wqp, bqp, S);
    proj_mma_kernel<DA, 64, 1><<<dim3(S/128, HDIM/2, BDIM), 256, smem_a>>>(Abf_p, Wkabf_p, bka, S, Wn);
    proj_mma_kernel<DP, 32, 2><<<dim3(S/128, HDIM/2, BDIM), 256, smem_p>>>(Pbf_p, Wkpbf_p, bkp, S, Wn);
    softmax_kernel<<<BDIM*HDIM, 256>>>(w, w_a, w_p, S, Wn);
    xbar_kernel<<<dim3((Wn - 1 + 63)/64, BDIM), 256>>>(S, Wn);
    gi_kernel<<<dim3(31, BDIM), 192>>>(memory, b_ih, S);
    gru_kernel<<<BDIM, 192>>>(b_hh);
    detaout_kernel<<<BDIM, 512>>>(bv, x_pre, bO, out);
}